// round 1
// baseline (speedup 1.0000x reference)
#include <cuda_runtime.h>
#include <math.h>
#include <stdint.h>

// ---------------- problem constants ----------------
constexpr int SEQ  = 4096;
constexpr int DM   = 1024;     // d_model
constexpr int ODIM = 1024;     // out_dim
constexpr int KW   = 256;      // window length
constexpr int STR  = 16;       // stride
constexpr int NH   = 16;       // heads
constexpr int DH   = 64;       // head dim
constexpr int NWIN = (SEQ - KW) / STR;   // 240
constexpr int ROWS = NWIN * KW;          // 61440

// ---------------- scratch (device globals; no allocation allowed) ----------------
__device__ float g_qkv1[SEQ * 3 * DM];      // 50 MB   qkv of every path row
__device__ float g_attn1[ROWS * DM];        // 252 MB  window attention output
__device__ float g_x[ROWS * ODIM];          // 252 MB  relu(linear(outproj(...)))
__device__ float g_q2[ROWS * ODIM];         // 252 MB  Q projections for recurrence
__device__ float g_kv[KW * 2 * ODIM];       // per-step K,V of cum
__device__ float g_att2[KW * ODIM];         // per-step attention out
__device__ float g_cum[KW * ODIM];          // running accumulator
__device__ float g_wt[DM * DM];             // w_out1^T
__device__ float g_wcomb[DM * DM];          // w_lin @ w_out1
__device__ float g_bcomb[DM];
__device__ float g_zerobias[DM];

// ---------------- generic SGEMM: C[M,N] = A[M,K] @ W[N,K]^T + bias (+relu) ----------------
// All M,N multiples of BM/BN; K multiple of BK. A,W row-major.
template<int BM, int BN, int BK, int TM, int TN, bool RELU>
__global__ __launch_bounds__((BM/TM)*(BN/TN))
void gemm_bias(const float* __restrict__ A, const float* __restrict__ W,
               const float* __restrict__ bias, float* __restrict__ C,
               int M, int N, int K)
{
    constexpr int THREADS = (BM/TM)*(BN/TN);
    __shared__ float As[BK][BM];
    __shared__ float Bs[BK][BN];
    const int tid  = threadIdx.x;
    const int bm   = blockIdx.y * BM;
    const int bn   = blockIdx.x * BN;
    const int tcol = tid % (BN/TN);
    const int trow = tid / (BN/TN);

    float acc[TM][TN];
    #pragma unroll
    for (int i = 0; i < TM; i++)
        #pragma unroll
        for (int j = 0; j < TN; j++) acc[i][j] = 0.f;

    constexpr int AF4 = BM * (BK/4);
    constexpr int BF4 = BN * (BK/4);

    for (int k0 = 0; k0 < K; k0 += BK) {
        #pragma unroll
        for (int i = tid; i < AF4; i += THREADS) {
            int r  = i / (BK/4);
            int c4 = i % (BK/4);
            float4 v = *(const float4*)&A[(size_t)(bm + r) * K + k0 + c4*4];
            As[c4*4+0][r] = v.x; As[c4*4+1][r] = v.y;
            As[c4*4+2][r] = v.z; As[c4*4+3][r] = v.w;
        }
        #pragma unroll
        for (int i = tid; i < BF4; i += THREADS) {
            int r  = i / (BK/4);
            int c4 = i % (BK/4);
            float4 v = *(const float4*)&W[(size_t)(bn + r) * K + k0 + c4*4];
            Bs[c4*4+0][r] = v.x; Bs[c4*4+1][r] = v.y;
            Bs[c4*4+2][r] = v.z; Bs[c4*4+3][r] = v.w;
        }
        __syncthreads();

        #pragma unroll
        for (int k = 0; k < BK; k++) {
            float ra[TM], rb[TN];
            #pragma unroll
            for (int i = 0; i < TM; i += 4) {
                float4 v = *(const float4*)&As[k][trow*TM + i];
                ra[i] = v.x; ra[i+1] = v.y; ra[i+2] = v.z; ra[i+3] = v.w;
            }
            #pragma unroll
            for (int j = 0; j < TN; j += 4) {
                float4 v = *(const float4*)&Bs[k][tcol*TN + j];
                rb[j] = v.x; rb[j+1] = v.y; rb[j+2] = v.z; rb[j+3] = v.w;
            }
            #pragma unroll
            for (int i = 0; i < TM; i++)
                #pragma unroll
                for (int j = 0; j < TN; j++)
                    acc[i][j] = fmaf(ra[i], rb[j], acc[i][j]);
        }
        __syncthreads();
    }

    #pragma unroll
    for (int i = 0; i < TM; i++) {
        size_t row = (size_t)(bm + trow*TM + i);
        #pragma unroll
        for (int j = 0; j < TN; j += 4) {
            int col = bn + tcol*TN + j;
            float4 b4 = *(const float4*)&bias[col];
            float4 o;
            o.x = acc[i][j+0] + b4.x;
            o.y = acc[i][j+1] + b4.y;
            o.z = acc[i][j+2] + b4.z;
            o.w = acc[i][j+3] + b4.w;
            if (RELU) {
                o.x = fmaxf(o.x, 0.f); o.y = fmaxf(o.y, 0.f);
                o.z = fmaxf(o.z, 0.f); o.w = fmaxf(o.w, 0.f);
            }
            *(float4*)&C[row * N + col] = o;
        }
    }
}

// ---------------- misc small kernels ----------------
__global__ void transpose1024(const float* __restrict__ in, float* __restrict__ out)
{
    __shared__ float tile[32][33];
    int x = blockIdx.x * 32 + threadIdx.x;
    int y = blockIdx.y * 32 + threadIdx.y;
    #pragma unroll
    for (int j = 0; j < 32; j += 8)
        tile[threadIdx.y + j][threadIdx.x] = in[(size_t)(y + j) * DM + x];
    __syncthreads();
    x = blockIdx.y * 32 + threadIdx.x;
    y = blockIdx.x * 32 + threadIdx.y;
    #pragma unroll
    for (int j = 0; j < 32; j += 8)
        out[(size_t)(y + j) * DM + x] = tile[threadIdx.x][threadIdx.y + j];
}

__global__ void bcomb_kernel(const float* __restrict__ w_lin,
                             const float* __restrict__ b_out1,
                             const float* __restrict__ b_lin,
                             float* __restrict__ out)
{
    int n = blockIdx.x * blockDim.x + threadIdx.x;
    float s = 0.f;
    for (int j = 0; j < DM; j++) s = fmaf(w_lin[(size_t)n * DM + j], b_out1[j], s);
    out[n] = s + b_lin[n];
}

__global__ void zero_kernel(float* p, int n)
{
    int i = blockIdx.x * blockDim.x + threadIdx.x;
    if (i < n) p[i] = 0.f;
}

// ---------------- flash-style attention ----------------
// Block: 256 threads = (4 key-chunks of 64) x (64 queries). One block handles
// 64 queries of one (window, head). grid = (heads, 4 q-tiles, n_windows).
// K/V tiles for the full 256-key context live in dynamic smem (128 KB).
constexpr int ATTN_SMEM = (2 * KW * DH + 2 * 256) * (int)sizeof(float); // 133120 B

__global__ __launch_bounds__(256)
void attn_kernel(const float* __restrict__ qbase, long long q_ws, int q_rs,
                 const float* __restrict__ kbase, long long k_ws, int k_rs,
                 const float* __restrict__ vbase, long long v_ws, int v_rs,
                 float* __restrict__ obase,       long long o_ws, int o_rs,
                 float scale)
{
    extern __shared__ float sm[];
    float* Ks   = sm;                     // 256*64
    float* Vs   = sm + KW * DH;           // 256*64
    float* mbuf = sm + 2 * KW * DH;       // 256
    float* lbuf = mbuf + 256;             // 256

    const int h  = blockIdx.x;
    const int qt = blockIdx.y;
    const int w  = blockIdx.z;
    const int tid = threadIdx.x;

    const float* Kp = kbase + (size_t)w * k_ws + h * DH;
    const float* Vp = vbase + (size_t)w * v_ws + h * DH;

    // cooperative, coalesced K/V load (rows of 64 floats)
    for (int idx = tid; idx < KW * (DH/4); idx += 256) {
        int r  = idx >> 4;
        int c4 = idx & 15;
        *(float4*)(Ks + r * DH + c4*4) = *(const float4*)(Kp + (size_t)r * k_rs + c4*4);
        *(float4*)(Vs + r * DH + c4*4) = *(const float4*)(Vp + (size_t)r * v_rs + c4*4);
    }
    __syncthreads();

    const int q = tid & 63;         // query within tile
    const int c = tid >> 6;         // key chunk 0..3
    const int qrow = qt * 64 + q;

    const float* Qr = qbase + (size_t)w * q_ws + (size_t)qrow * q_rs + h * DH;
    float qreg[DH];
    #pragma unroll
    for (int d4 = 0; d4 < 16; d4++) {
        float4 v = *(const float4*)(Qr + d4*4);
        qreg[d4*4+0] = v.x; qreg[d4*4+1] = v.y; qreg[d4*4+2] = v.z; qreg[d4*4+3] = v.w;
    }

    float m = -1e30f, l = 0.f;
    float acc[DH];
    #pragma unroll
    for (int d = 0; d < DH; d++) acc[d] = 0.f;

    const int k0 = c * 64;
    for (int kk = 0; kk < 64; kk++) {
        const float* Krow = Ks + (k0 + kk) * DH;
        float s = 0.f;
        #pragma unroll
        for (int d4 = 0; d4 < 16; d4++) {
            float4 kv = *(const float4*)(Krow + d4*4);
            s = fmaf(qreg[d4*4+0], kv.x, s);
            s = fmaf(qreg[d4*4+1], kv.y, s);
            s = fmaf(qreg[d4*4+2], kv.z, s);
            s = fmaf(qreg[d4*4+3], kv.w, s);
        }
        s *= scale;
        if (s > m) {                      // rare after warm-up
            float corr = __expf(m - s);
            l *= corr;
            #pragma unroll
            for (int d = 0; d < DH; d++) acc[d] *= corr;
            m = s;
        }
        float p = __expf(s - m);
        l += p;
        const float* Vrow = Vs + (k0 + kk) * DH;
        #pragma unroll
        for (int d4 = 0; d4 < 16; d4++) {
            float4 vv = *(const float4*)(Vrow + d4*4);
            acc[d4*4+0] = fmaf(p, vv.x, acc[d4*4+0]);
            acc[d4*4+1] = fmaf(p, vv.y, acc[d4*4+1]);
            acc[d4*4+2] = fmaf(p, vv.z, acc[d4*4+2]);
            acc[d4*4+3] = fmaf(p, vv.w, acc[d4*4+3]);
        }
    }
    __syncthreads();           // everyone done reading Ks/Vs

    // merge the 4 key-chunk partials per query (accbuf reuses Ks region)
    float* accbuf = Ks;
    mbuf[tid] = m;
    lbuf[tid] = l;
    #pragma unroll
    for (int d4 = 0; d4 < 16; d4++)
        *(float4*)(accbuf + (size_t)tid * DH + d4*4) =
            make_float4(acc[d4*4+0], acc[d4*4+1], acc[d4*4+2], acc[d4*4+3]);
    __syncthreads();

    float m0 = mbuf[q], m1 = mbuf[64+q], m2 = mbuf[128+q], m3 = mbuf[192+q];
    float mg = fmaxf(fmaxf(m0, m1), fmaxf(m2, m3));
    float e0 = __expf(m0 - mg), e1 = __expf(m1 - mg);
    float e2 = __expf(m2 - mg), e3 = __expf(m3 - mg);
    float lg = lbuf[q]*e0 + lbuf[64+q]*e1 + lbuf[128+q]*e2 + lbuf[192+q]*e3;
    float inv = 1.f / lg;

    float* Or = obase + (size_t)w * o_ws + (size_t)qrow * o_rs + h * DH;
    #pragma unroll
    for (int d = c*16; d < c*16 + 16; d++) {
        float o = accbuf[(size_t)(0*64+q)*DH + d] * e0
                + accbuf[(size_t)(1*64+q)*DH + d] * e1
                + accbuf[(size_t)(2*64+q)*DH + d] * e2
                + accbuf[(size_t)(3*64+q)*DH + d] * e3;
        Or[d] = o * inv;
    }
}

// ---------------- host ----------------
using Gemm128  = void(*)(const float*, const float*, const float*, float*, int, int, int);

extern "C" void kernel_launch(void* const* d_in, const int* in_sizes, int n_in,
                              void* d_out, int out_size)
{
    const float* path   = (const float*)d_in[0];
    const float* w_in1  = (const float*)d_in[1];
    const float* b_in1  = (const float*)d_in[2];
    const float* w_out1 = (const float*)d_in[3];
    const float* b_out1 = (const float*)d_in[4];
    const float* w_lin  = (const float*)d_in[5];
    const float* b_lin  = (const float*)d_in[6];
    const float* w_in2  = (const float*)d_in[7];
    const float* b_in2  = (const float*)d_in[8];
    const float* w_out2 = (const float*)d_in[9];
    const float* b_out2 = (const float*)d_in[10];

    float *qkv1, *attn1, *x, *q2, *kv, *att2, *cum, *wt, *wcomb, *bcomb, *zb;
    cudaGetSymbolAddress((void**)&qkv1,  g_qkv1);
    cudaGetSymbolAddress((void**)&attn1, g_attn1);
    cudaGetSymbolAddress((void**)&x,     g_x);
    cudaGetSymbolAddress((void**)&q2,    g_q2);
    cudaGetSymbolAddress((void**)&kv,    g_kv);
    cudaGetSymbolAddress((void**)&att2,  g_att2);
    cudaGetSymbolAddress((void**)&cum,   g_cum);
    cudaGetSymbolAddress((void**)&wt,    g_wt);
    cudaGetSymbolAddress((void**)&wcomb, g_wcomb);
    cudaGetSymbolAddress((void**)&bcomb, g_bcomb);
    cudaGetSymbolAddress((void**)&zb,    g_zerobias);

    cudaFuncSetAttribute(attn_kernel, cudaFuncAttributeMaxDynamicSharedMemorySize, ATTN_SMEM);

    // big-tile and small-tile GEMM instantiations
    auto g128   = gemm_bias<128,128,8,8,8,false>;
    auto g128r  = gemm_bias<128,128,8,8,8,true>;
    auto g64    = gemm_bias<64,64,16,4,4,false>;

    // ---- prologue: fold w_out1 into w_lin ----
    zero_kernel<<<(DM+255)/256, 256>>>(zb, DM);
    transpose1024<<<dim3(32,32), dim3(32,8)>>>(w_out1, wt);
    g128<<<dim3(DM/128, DM/128), 256>>>(w_lin, wt, zb, wcomb, DM, DM, DM);
    bcomb_kernel<<<DM/256, 256>>>(w_lin, b_out1, b_lin, bcomb);

    // ---- stage 1: QKV of every path row (windows share rows!) ----
    g128<<<dim3(3*DM/128, SEQ/128), 256>>>(path, w_in1, b_in1, qkv1, SEQ, 3*DM, DM);

    // ---- stage 2: batched window self-attention ----
    attn_kernel<<<dim3(NH, KW/64, NWIN), 256, ATTN_SMEM>>>(
        qkv1,          (long long)STR * 3*DM, 3*DM,
        qkv1 + DM,     (long long)STR * 3*DM, 3*DM,
        qkv1 + 2*DM,   (long long)STR * 3*DM, 3*DM,
        attn1,         (long long)KW * DM,    DM,
        0.125f);

    // ---- stage 3: fused outproj1 + linear + relu ----
    g128r<<<dim3(ODIM/128, ROWS/128), 256>>>(attn1, wcomb, bcomb, x, ROWS, ODIM, DM);

    // ---- stage 4a: bulk Q2 projections for the recurrence ----
    g128<<<dim3(ODIM/128, ROWS/128), 256>>>(x, w_in2, b_in2, q2, ROWS, ODIM, ODIM);

    // ---- stage 4b: sequential recurrence ----
    cudaMemcpyAsync(cum, x, (size_t)KW * ODIM * sizeof(float), cudaMemcpyDeviceToDevice);
    for (int i = 1; i < NWIN; i++) {
        // K,V projections of cum
        g64<<<dim3(2*ODIM/64, KW/64), 256>>>(cum, w_in2 + (size_t)ODIM*ODIM,
                                             b_in2 + ODIM, kv, KW, 2*ODIM, ODIM);
        // attention: Q = precomputed q2[i], K/V = kv
        attn_kernel<<<dim3(NH, KW/64, 1), 256, ATTN_SMEM>>>(
            q2 + (size_t)i * KW * ODIM, 0, ODIM,
            kv,                          0, 2*ODIM,
            kv + ODIM,                   0, 2*ODIM,
            att2,                        0, ODIM,
            0.125f);
        // output projection -> new cum
        g64<<<dim3(ODIM/64, KW/64), 256>>>(att2, w_out2, b_out2, cum, KW, ODIM, ODIM);
    }

    cudaMemcpyAsync(d_out, cum, (size_t)KW * ODIM * sizeof(float), cudaMemcpyDeviceToDevice);
}

// round 2
// speedup vs baseline: 1.4273x; 1.4273x over previous
#include <cuda_runtime.h>
#include <math.h>
#include <stdint.h>

// ---------------- problem constants ----------------
constexpr int SEQ  = 4096;
constexpr int DM   = 1024;
constexpr int ODIM = 1024;
constexpr int KW   = 256;
constexpr int STR  = 16;
constexpr int NH   = 16;
constexpr int DH   = 64;
constexpr int NWIN = (SEQ - KW) / STR;   // 240
constexpr int ROWS = NWIN * KW;          // 61440

typedef unsigned long long ull;

// packed fp32x2 helpers (Blackwell; ptxas never auto-emits FFMA2 from C++)
#define PACK2(o, lo, hi)   asm("mov.b64 %0, {%1,%2};" : "=l"(o) : "f"(lo), "f"(hi))
#define UNPACK2(lo, hi, i) asm("mov.b64 {%0,%1}, %2;" : "=f"(lo), "=f"(hi) : "l"(i))
#define FMA2(d, a, b, c)   asm("fma.rn.f32x2 %0, %1, %2, %3;" : "=l"(d) : "l"(a), "l"(b), "l"(c))
#define MUL2(d, a, b)      asm("mul.rn.f32x2 %0, %1, %2;" : "=l"(d) : "l"(a), "l"(b))

// ---------------- scratch ----------------
__device__ float g_qkv1[SEQ * 3 * DM];
__device__ float g_attn1[ROWS * DM];
__device__ float g_x[ROWS * ODIM];
__device__ float g_q2[ROWS * ODIM];
__device__ float g_kv[KW * 2 * ODIM];
__device__ float g_st[KW * ODIM];          // recurrence state (pre-outproj)
__device__ float g_wt[DM * DM];
__device__ float g_wcomb[DM * DM];
__device__ float g_bcomb[DM];
__device__ float g_wkv[2 * ODIM * DM];     // wkv2 @ w_out2
__device__ float g_bkv[2 * ODIM];
__device__ float g_zb[DM];

// ---------------- SGEMM: C[M,N] = A[M,K] @ W[N,K]^T + bias (+relu), packed f32x2 ----------------
template<int BM, int BN, int BK, int TM, int TN, bool RELU>
__global__ __launch_bounds__((BM/TM)*(BN/TN))
void gemm_bias(const float* __restrict__ A, const float* __restrict__ W,
               const float* __restrict__ bias, float* __restrict__ C,
               int M, int N, int K)
{
    constexpr int THREADS = (BM/TM)*(BN/TN);
    __shared__ __align__(16) float As[BK][BM];
    __shared__ __align__(16) float Bs[BK][BN];
    const int tid  = threadIdx.x;
    const int bm   = blockIdx.y * BM;
    const int bn   = blockIdx.x * BN;
    const int tcol = tid % (BN/TN);
    const int trow = tid / (BN/TN);

    ull acc2[TM][TN/2];
    #pragma unroll
    for (int i = 0; i < TM; i++)
        #pragma unroll
        for (int j = 0; j < TN/2; j++) acc2[i][j] = 0ull;

    constexpr int AF4 = BM * (BK/4);
    constexpr int BF4 = BN * (BK/4);

    for (int k0 = 0; k0 < K; k0 += BK) {
        #pragma unroll
        for (int i = tid; i < AF4; i += THREADS) {
            int r  = i / (BK/4);
            int c4 = i % (BK/4);
            float4 v = *(const float4*)&A[(size_t)(bm + r) * K + k0 + c4*4];
            As[c4*4+0][r] = v.x; As[c4*4+1][r] = v.y;
            As[c4*4+2][r] = v.z; As[c4*4+3][r] = v.w;
        }
        #pragma unroll
        for (int i = tid; i < BF4; i += THREADS) {
            int r  = i / (BK/4);
            int c4 = i % (BK/4);
            float4 v = *(const float4*)&W[(size_t)(bn + r) * K + k0 + c4*4];
            Bs[c4*4+0][r] = v.x; Bs[c4*4+1][r] = v.y;
            Bs[c4*4+2][r] = v.z; Bs[c4*4+3][r] = v.w;
        }
        __syncthreads();

        #pragma unroll
        for (int k = 0; k < BK; k++) {
            float ra[TM];
            #pragma unroll
            for (int i = 0; i < TM; i += 4) {
                float4 v = *(const float4*)&As[k][trow*TM + i];
                ra[i] = v.x; ra[i+1] = v.y; ra[i+2] = v.z; ra[i+3] = v.w;
            }
            ull ras[TM];
            #pragma unroll
            for (int i = 0; i < TM; i++) PACK2(ras[i], ra[i], ra[i]);

            ull rb2[TN/2];
            #pragma unroll
            for (int j4 = 0; j4 < TN/4; j4++) {
                ulonglong2 v = *(const ulonglong2*)&Bs[k][tcol*TN + j4*4];
                rb2[2*j4]   = v.x;
                rb2[2*j4+1] = v.y;
            }
            #pragma unroll
            for (int i = 0; i < TM; i++)
                #pragma unroll
                for (int j = 0; j < TN/2; j++)
                    FMA2(acc2[i][j], ras[i], rb2[j], acc2[i][j]);
        }
        __syncthreads();
    }

    #pragma unroll
    for (int i = 0; i < TM; i++) {
        size_t row = (size_t)(bm + trow*TM + i);
        float oc[TN];
        #pragma unroll
        for (int j = 0; j < TN/2; j++) UNPACK2(oc[2*j], oc[2*j+1], acc2[i][j]);
        #pragma unroll
        for (int j = 0; j < TN; j += 4) {
            int col = bn + tcol*TN + j;
            float4 b4 = *(const float4*)&bias[col];
            float4 o;
            o.x = oc[j+0] + b4.x;
            o.y = oc[j+1] + b4.y;
            o.z = oc[j+2] + b4.z;
            o.w = oc[j+3] + b4.w;
            if (RELU) {
                o.x = fmaxf(o.x, 0.f); o.y = fmaxf(o.y, 0.f);
                o.z = fmaxf(o.z, 0.f); o.w = fmaxf(o.w, 0.f);
            }
            *(float4*)&C[row * N + col] = o;
        }
    }
}

// ---------------- misc small kernels ----------------
__global__ void transpose1024(const float* __restrict__ in, float* __restrict__ out)
{
    __shared__ float tile[32][33];
    int x = blockIdx.x * 32 + threadIdx.x;
    int y = blockIdx.y * 32 + threadIdx.y;
    #pragma unroll
    for (int j = 0; j < 32; j += 8)
        tile[threadIdx.y + j][threadIdx.x] = in[(size_t)(y + j) * DM + x];
    __syncthreads();
    x = blockIdx.y * 32 + threadIdx.x;
    y = blockIdx.x * 32 + threadIdx.y;
    #pragma unroll
    for (int j = 0; j < 32; j += 8)
        out[(size_t)(y + j) * DM + x] = tile[threadIdx.x][threadIdx.y + j];
}

// out[n] = dot(W[n, 0:K], b1) + b2[n]; one warp per n; grid*8 warps = N
__global__ void bias_dot(const float* __restrict__ W, const float* __restrict__ b1,
                         const float* __restrict__ b2, float* __restrict__ out, int K)
{
    int n    = blockIdx.x * (blockDim.x / 32) + (threadIdx.x >> 5);
    int lane = threadIdx.x & 31;
    float s = 0.f;
    for (int j = lane; j < K; j += 32) s = fmaf(W[(size_t)n * K + j], b1[j], s);
    #pragma unroll
    for (int o = 16; o; o >>= 1) s += __shfl_xor_sync(0xffffffffu, s, o);
    if (lane == 0) out[n] = s + b2[n];
}

__global__ void zero_kernel(float* p, int n)
{
    int i = blockIdx.x * blockDim.x + threadIdx.x;
    if (i < n) p[i] = 0.f;
}

// ---------------- flash-style attention (packed f32x2 math) ----------------
constexpr int ATTN_SMEM = (2 * KW * DH + 2 * 256) * (int)sizeof(float); // 133120 B

__global__ __launch_bounds__(256)
void attn_kernel(const float* __restrict__ qbase, long long q_ws, int q_rs,
                 const float* __restrict__ kbase, long long k_ws, int k_rs,
                 const float* __restrict__ vbase, long long v_ws, int v_rs,
                 float* __restrict__ obase,       long long o_ws, int o_rs,
                 float scale)
{
    extern __shared__ float sm[];
    float* Ks   = sm;
    float* Vs   = sm + KW * DH;
    float* mbuf = sm + 2 * KW * DH;
    float* lbuf = mbuf + 256;

    const int h  = blockIdx.x;
    const int qt = blockIdx.y;
    const int w  = blockIdx.z;
    const int tid = threadIdx.x;

    const float* Kp = kbase + (size_t)w * k_ws + h * DH;
    const float* Vp = vbase + (size_t)w * v_ws + h * DH;

    for (int idx = tid; idx < KW * (DH/4); idx += 256) {
        int r  = idx >> 4;
        int c4 = idx & 15;
        *(float4*)(Ks + r * DH + c4*4) = *(const float4*)(Kp + (size_t)r * k_rs + c4*4);
        *(float4*)(Vs + r * DH + c4*4) = *(const float4*)(Vp + (size_t)r * v_rs + c4*4);
    }
    __syncthreads();

    const int q = tid & 63;
    const int c = tid >> 6;
    const int qrow = qt * 64 + q;

    const float* Qr = qbase + (size_t)w * q_ws + (size_t)qrow * q_rs + h * DH;
    ull qp[DH/2];
    #pragma unroll
    for (int d4 = 0; d4 < 16; d4++) {
        ulonglong2 v = *(const ulonglong2*)(Qr + d4*4);
        qp[2*d4]   = v.x;
        qp[2*d4+1] = v.y;
    }

    float m = -1e30f, l = 0.f;
    ull accp[DH/2];
    #pragma unroll
    for (int t = 0; t < DH/2; t++) accp[t] = 0ull;

    const int k0 = c * 64;
    for (int kk = 0; kk < 64; kk++) {
        const float* Krow = Ks + (k0 + kk) * DH;
        ull s0 = 0ull, s1 = 0ull, s2 = 0ull, s3 = 0ull;
        #pragma unroll
        for (int d4 = 0; d4 < 16; d4 += 2) {
            ulonglong2 a = *(const ulonglong2*)(Krow + d4*4);
            ulonglong2 b = *(const ulonglong2*)(Krow + d4*4 + 4);
            FMA2(s0, qp[2*d4+0], a.x, s0);
            FMA2(s1, qp[2*d4+1], a.y, s1);
            FMA2(s2, qp[2*d4+2], b.x, s2);
            FMA2(s3, qp[2*d4+3], b.y, s3);
        }
        float a0,a1,b0,b1,c0,c1,d0,d1;
        UNPACK2(a0,a1,s0); UNPACK2(b0,b1,s1); UNPACK2(c0,c1,s2); UNPACK2(d0,d1,s3);
        float s = ((a0+a1)+(b0+b1)) + ((c0+c1)+(d0+d1));
        s *= scale;

        if (s > m) {
            float corr = __expf(m - s);
            l *= corr;
            ull cp; PACK2(cp, corr, corr);
            #pragma unroll
            for (int t = 0; t < DH/2; t++) MUL2(accp[t], accp[t], cp);
            m = s;
        }
        float p = __expf(s - m);
        l += p;
        ull pp; PACK2(pp, p, p);
        const float* Vrow = Vs + (k0 + kk) * DH;
        #pragma unroll
        for (int d4 = 0; d4 < 16; d4 += 2) {
            ulonglong2 a = *(const ulonglong2*)(Vrow + d4*4);
            ulonglong2 b = *(const ulonglong2*)(Vrow + d4*4 + 4);
            FMA2(accp[2*d4+0], pp, a.x, accp[2*d4+0]);
            FMA2(accp[2*d4+1], pp, a.y, accp[2*d4+1]);
            FMA2(accp[2*d4+2], pp, b.x, accp[2*d4+2]);
            FMA2(accp[2*d4+3], pp, b.y, accp[2*d4+3]);
        }
    }
    __syncthreads();

    // merge 4 key-chunk partials per query (accbuf reuses Ks region: 64KB)
    float* accbuf = Ks;
    mbuf[tid] = m;
    lbuf[tid] = l;
    #pragma unroll
    for (int d4 = 0; d4 < 16; d4++)
        *(ulonglong2*)(accbuf + (size_t)tid * DH + d4*4) =
            make_ulonglong2(accp[2*d4], accp[2*d4+1]);
    __syncthreads();

    float m0 = mbuf[q], m1 = mbuf[64+q], m2 = mbuf[128+q], m3 = mbuf[192+q];
    float mg = fmaxf(fmaxf(m0, m1), fmaxf(m2, m3));
    float e0 = __expf(m0 - mg), e1 = __expf(m1 - mg);
    float e2 = __expf(m2 - mg), e3 = __expf(m3 - mg);
    float lg = lbuf[q]*e0 + lbuf[64+q]*e1 + lbuf[128+q]*e2 + lbuf[192+q]*e3;
    float inv = 1.f / lg;

    float* Or = obase + (size_t)w * o_ws + (size_t)qrow * o_rs + h * DH;
    #pragma unroll
    for (int d = c*16; d < c*16 + 16; d++) {
        float o = accbuf[(size_t)(0*64+q)*DH + d] * e0
                + accbuf[(size_t)(1*64+q)*DH + d] * e1
                + accbuf[(size_t)(2*64+q)*DH + d] * e2
                + accbuf[(size_t)(3*64+q)*DH + d] * e3;
        Or[d] = o * inv;
    }
}

// ---------------- host ----------------
extern "C" void kernel_launch(void* const* d_in, const int* in_sizes, int n_in,
                              void* d_out, int out_size)
{
    const float* path   = (const float*)d_in[0];
    const float* w_in1  = (const float*)d_in[1];
    const float* b_in1  = (const float*)d_in[2];
    const float* w_out1 = (const float*)d_in[3];
    const float* b_out1 = (const float*)d_in[4];
    const float* w_lin  = (const float*)d_in[5];
    const float* b_lin  = (const float*)d_in[6];
    const float* w_in2  = (const float*)d_in[7];
    const float* b_in2  = (const float*)d_in[8];
    const float* w_out2 = (const float*)d_in[9];
    const float* b_out2 = (const float*)d_in[10];

    float *qkv1, *attn1, *x, *q2, *kv, *st, *wt, *wcomb, *bcomb, *wkv, *bkv, *zb;
    cudaGetSymbolAddress((void**)&qkv1,  g_qkv1);
    cudaGetSymbolAddress((void**)&attn1, g_attn1);
    cudaGetSymbolAddress((void**)&x,     g_x);
    cudaGetSymbolAddress((void**)&q2,    g_q2);
    cudaGetSymbolAddress((void**)&kv,    g_kv);
    cudaGetSymbolAddress((void**)&st,    g_st);
    cudaGetSymbolAddress((void**)&wt,    g_wt);
    cudaGetSymbolAddress((void**)&wcomb, g_wcomb);
    cudaGetSymbolAddress((void**)&bcomb, g_bcomb);
    cudaGetSymbolAddress((void**)&wkv,   g_wkv);
    cudaGetSymbolAddress((void**)&bkv,   g_bkv);
    cudaGetSymbolAddress((void**)&zb,    g_zb);

    cudaFuncSetAttribute(attn_kernel, cudaFuncAttributeMaxDynamicSharedMemorySize, ATTN_SMEM);

    auto g128  = gemm_bias<128,128,8,8,8,false>;
    auto g128r = gemm_bias<128,128,8,8,8,true>;
    auto g64   = gemm_bias<64,64,16,4,4,false>;

    const float* wkv2 = w_in2 + (size_t)ODIM * ODIM;   // K,V rows of w_in2
    const float* bkv2 = b_in2 + ODIM;

    // ---- prologue ----
    zero_kernel<<<(DM+255)/256, 256>>>(zb, DM);                               // 1
    transpose1024<<<dim3(32,32), dim3(32,8)>>>(w_out1, wt);                   // 2
    g128<<<dim3(DM/128, DM/128), 256>>>(w_lin, wt, zb, wcomb, DM, DM, DM);    // 3: w_lin @ w_out1
    bias_dot<<<DM/8, 256>>>(w_lin, b_out1, b_lin, bcomb, DM);                 // 4
    transpose1024<<<dim3(32,32), dim3(32,8)>>>(w_out2, wt);                   // 5
    g128<<<dim3(DM/128, 2*ODIM/128), 256>>>(wkv2, wt, zb, wkv, 2*ODIM, DM, DM); // 6: wkv2 @ w_out2 (ncu target)
    bias_dot<<<2*ODIM/8, 256>>>(wkv2, b_out2, bkv2, bkv, DM);                 // 7

    // ---- stage 1: QKV of every path row ----
    g128<<<dim3(3*DM/128, SEQ/128), 256>>>(path, w_in1, b_in1, qkv1, SEQ, 3*DM, DM);

    // ---- stage 2: batched window self-attention ----
    attn_kernel<<<dim3(NH, KW/64, NWIN), 256, ATTN_SMEM>>>(
        qkv1,        (long long)STR * 3*DM, 3*DM,
        qkv1 + DM,   (long long)STR * 3*DM, 3*DM,
        qkv1 + 2*DM, (long long)STR * 3*DM, 3*DM,
        attn1,       (long long)KW * DM,    DM,
        0.125f);

    // ---- stage 3: fused outproj1 + linear + relu ----
    g128r<<<dim3(ODIM/128, ROWS/128), 256>>>(attn1, wcomb, bcomb, x, ROWS, ODIM, DM);

    // ---- stage 4a: bulk Q2 projections ----
    g128<<<dim3(ODIM/128, ROWS/128), 256>>>(x, w_in2, b_in2, q2, ROWS, ODIM, ODIM);

    // ---- stage 4b: recurrence with w_out2 folded into KV projection ----
    // step 1: KV from cum0 = x[0] with original weights
    g64<<<dim3(2*ODIM/64, KW/64), 256>>>(x, wkv2, bkv2, kv, KW, 2*ODIM, ODIM);
    attn_kernel<<<dim3(NH, KW/64, 1), 256, ATTN_SMEM>>>(
        q2 + (size_t)1 * KW * ODIM, 0, ODIM,
        kv,        0, 2*ODIM,
        kv + ODIM, 0, 2*ODIM,
        st,        0, ODIM,
        0.125f);
    // steps 2..239: KV directly from state (pre-outproj) via folded weights
    for (int i = 2; i < NWIN; i++) {
        g64<<<dim3(2*ODIM/64, KW/64), 256>>>(st, wkv, bkv, kv, KW, 2*ODIM, ODIM);
        attn_kernel<<<dim3(NH, KW/64, 1), 256, ATTN_SMEM>>>(
            q2 + (size_t)i * KW * ODIM, 0, ODIM,
            kv,        0, 2*ODIM,
            kv + ODIM, 0, 2*ODIM,
            st,        0, ODIM,
            0.125f);
    }
    // final out-projection -> d_out
    g64<<<dim3(ODIM/64, KW/64), 256>>>(st, w_out2, b_out2, (float*)d_out, KW, ODIM, ODIM);
}

// round 3
// speedup vs baseline: 1.6397x; 1.1488x over previous
#include <cuda_runtime.h>
#include <math.h>
#include <stdint.h>

// ---------------- problem constants ----------------
constexpr int SEQ  = 4096;
constexpr int DM   = 1024;
constexpr int ODIM = 1024;
constexpr int KW   = 256;
constexpr int STR  = 16;
constexpr int NH   = 16;
constexpr int DH   = 64;
constexpr int NWIN = (SEQ - KW) / STR;   // 240
constexpr int ROWS = NWIN * KW;          // 61440

typedef unsigned long long ull;

// packed fp32x2 helpers
#define PACK2(o, lo, hi)   asm("mov.b64 %0, {%1,%2};" : "=l"(o) : "f"(lo), "f"(hi))
#define UNPACK2(lo, hi, i) asm("mov.b64 {%0,%1}, %2;" : "=f"(lo), "=f"(hi) : "l"(i))
#define FMA2(d, a, b, c)   asm("fma.rn.f32x2 %0, %1, %2, %3;" : "=l"(d) : "l"(a), "l"(b), "l"(c))
#define MUL2(d, a, b)      asm("mul.rn.f32x2 %0, %1, %2;" : "=l"(d) : "l"(a), "l"(b))

__device__ __forceinline__ uint32_t f2tf32(float f) {
    uint32_t u; asm("cvt.rna.tf32.f32 %0, %1;" : "=r"(u) : "f"(f)); return u;
}

#define MMA_TF32(c, a, b) \
    asm volatile("mma.sync.aligned.m16n8k8.row.col.f32.tf32.tf32.f32 " \
        "{%0,%1,%2,%3},{%4,%5,%6,%7},{%8,%9},{%0,%1,%2,%3};" \
        : "+f"((c)[0]), "+f"((c)[1]), "+f"((c)[2]), "+f"((c)[3]) \
        : "r"((a)[0]), "r"((a)[1]), "r"((a)[2]), "r"((a)[3]), "r"((b)[0]), "r"((b)[1]))

// ---------------- scratch ----------------
__device__ float g_qkv1[SEQ * 3 * DM];
__device__ float g_attn1[ROWS * DM];
__device__ float g_x[ROWS * ODIM];
__device__ float g_q2[ROWS * ODIM];
__device__ float g_kv[KW * 2 * ODIM];
__device__ float g_st[KW * ODIM];
__device__ float g_wt[DM * DM];
__device__ float g_wt2[DM * DM];
__device__ float g_wcomb[DM * DM];
__device__ float g_bcomb[DM];
__device__ float g_wkv[2 * ODIM * DM];
__device__ float g_bkv[2 * ODIM];
__device__ float g_zb[DM];

// ================= TF32 tensor-core GEMM =================
// C[M,N] = A[M,K] @ W[N,K]^T + bias (+relu).  BM=BN=128, BK=32,
// 256 threads = 8 warps tiled 2(m) x 4(n); warp tile 64x32 = 4x4 mma m16n8k8.
// Double-buffered smem, +4 float padding -> conflict-free fragment LDS.
constexpr int TF_BM = 128, TF_BN = 128, TF_BK = 32;
constexpr int TF_LD = TF_BK + 4;                       // 36 floats
constexpr int TF_BUF = (TF_BM + TF_BN) * TF_LD;        // floats per buffer
constexpr int TF_SMEM = 2 * TF_BUF * (int)sizeof(float);  // 73728 B

template<bool RELU>
__global__ __launch_bounds__(256)
void gemm_tf32(const float* __restrict__ A, const float* __restrict__ W,
               const float* __restrict__ bias, float* __restrict__ C,
               int M, int N, int K)
{
    extern __shared__ float smem[];
    const int tid    = threadIdx.x;
    const int lane   = tid & 31;
    const int warp   = tid >> 5;
    const int g      = lane >> 2;       // group id 0..7
    const int tg     = lane & 3;        // thread in group 0..3
    const int warp_m = (warp & 1) * 64;
    const int warp_n = (warp >> 1) * 32;
    const int bm     = blockIdx.y * TF_BM;
    const int bn     = blockIdx.x * TF_BN;

    float c[4][4][4];
    #pragma unroll
    for (int i = 0; i < 4; i++)
        #pragma unroll
        for (int j = 0; j < 4; j++)
            #pragma unroll
            for (int r = 0; r < 4; r++) c[i][j][r] = 0.f;

    // global-load slots: 1024 float4 per operand tile, 4 per thread
    const int lr = tid >> 3;        // row within tile (0..31 step: 4 rows/thread via +32)
    const int lc = tid & 7;         // float4 col (0..7)

    float4 ra[4], rw[4];
    auto loadG = [&](int t) {
        const size_t ko = (size_t)t * TF_BK + lc * 4;
        #pragma unroll
        for (int i = 0; i < 4; i++) {
            int r = lr + i * 32;
            ra[i] = *(const float4*)&A[(size_t)(bm + r) * K + ko];
            rw[i] = *(const float4*)&W[(size_t)(bn + r) * K + ko];
        }
    };
    auto storeS = [&](int buf) {
        float* As = smem + buf * TF_BUF;
        float* Bs = As + TF_BM * TF_LD;
        #pragma unroll
        for (int i = 0; i < 4; i++) {
            int r = lr + i * 32;
            uint4 ua = make_uint4(f2tf32(ra[i].x), f2tf32(ra[i].y), f2tf32(ra[i].z), f2tf32(ra[i].w));
            uint4 uw = make_uint4(f2tf32(rw[i].x), f2tf32(rw[i].y), f2tf32(rw[i].z), f2tf32(rw[i].w));
            *(uint4*)&As[r * TF_LD + lc * 4] = ua;
            *(uint4*)&Bs[r * TF_LD + lc * 4] = uw;
        }
    };

    const int nk = K / TF_BK;
    loadG(0);
    storeS(0);
    __syncthreads();

    for (int t = 0; t < nk; t++) {
        if (t + 1 < nk) loadG(t + 1);

        const int buf = t & 1;
        const uint32_t* Asu = (const uint32_t*)(smem + buf * TF_BUF);
        const uint32_t* Bsu = Asu + TF_BM * TF_LD;

        #pragma unroll
        for (int ks = 0; ks < 4; ks++) {
            uint32_t a[4][4], b[4][2];
            #pragma unroll
            for (int mt = 0; mt < 4; mt++) {
                int base = (warp_m + mt * 16 + g) * TF_LD + ks * 8 + tg;
                a[mt][0] = Asu[base];
                a[mt][1] = Asu[base + 8 * TF_LD];
                a[mt][2] = Asu[base + 4];
                a[mt][3] = Asu[base + 8 * TF_LD + 4];
            }
            #pragma unroll
            for (int nt = 0; nt < 4; nt++) {
                int base = (warp_n + nt * 8 + g) * TF_LD + ks * 8 + tg;
                b[nt][0] = Bsu[base];
                b[nt][1] = Bsu[base + 4];
            }
            #pragma unroll
            for (int mt = 0; mt < 4; mt++)
                #pragma unroll
                for (int nt = 0; nt < 4; nt++)
                    MMA_TF32(c[mt][nt], a[mt], b[nt]);
        }

        if (t + 1 < nk) storeS((t + 1) & 1);
        __syncthreads();
    }

    // epilogue
    #pragma unroll
    for (int mt = 0; mt < 4; mt++) {
        int row0 = bm + warp_m + mt * 16 + g;
        #pragma unroll
        for (int nt = 0; nt < 4; nt++) {
            int col = bn + warp_n + nt * 8 + tg * 2;
            float2 bb = *(const float2*)&bias[col];
            float2 o0, o1;
            o0.x = c[mt][nt][0] + bb.x;  o0.y = c[mt][nt][1] + bb.y;
            o1.x = c[mt][nt][2] + bb.x;  o1.y = c[mt][nt][3] + bb.y;
            if (RELU) {
                o0.x = fmaxf(o0.x, 0.f); o0.y = fmaxf(o0.y, 0.f);
                o1.x = fmaxf(o1.x, 0.f); o1.y = fmaxf(o1.y, 0.f);
            }
            *(float2*)&C[(size_t)row0 * N + col]       = o0;
            *(float2*)&C[(size_t)(row0 + 8) * N + col] = o1;
        }
    }
}

// ================= exact FFMA2 SGEMM (weights folds + recurrence) =================
template<int BM, int BN, int BK, int TM, int TN, bool RELU>
__global__ __launch_bounds__((BM/TM)*(BN/TN))
void gemm_bias(const float* __restrict__ A, const float* __restrict__ W,
               const float* __restrict__ bias, float* __restrict__ C,
               int M, int N, int K)
{
    constexpr int THREADS = (BM/TM)*(BN/TN);
    __shared__ __align__(16) float As[BK][BM];
    __shared__ __align__(16) float Bs[BK][BN];
    const int tid  = threadIdx.x;
    const int bm   = blockIdx.y * BM;
    const int bn   = blockIdx.x * BN;
    const int tcol = tid % (BN/TN);
    const int trow = tid / (BN/TN);

    ull acc2[TM][TN/2];
    #pragma unroll
    for (int i = 0; i < TM; i++)
        #pragma unroll
        for (int j = 0; j < TN/2; j++) acc2[i][j] = 0ull;

    constexpr int AF4 = BM * (BK/4);
    constexpr int BF4 = BN * (BK/4);

    for (int k0 = 0; k0 < K; k0 += BK) {
        #pragma unroll
        for (int i = tid; i < AF4; i += THREADS) {
            int r  = i / (BK/4);
            int c4 = i % (BK/4);
            float4 v = *(const float4*)&A[(size_t)(bm + r) * K + k0 + c4*4];
            As[c4*4+0][r] = v.x; As[c4*4+1][r] = v.y;
            As[c4*4+2][r] = v.z; As[c4*4+3][r] = v.w;
        }
        #pragma unroll
        for (int i = tid; i < BF4; i += THREADS) {
            int r  = i / (BK/4);
            int c4 = i % (BK/4);
            float4 v = *(const float4*)&W[(size_t)(bn + r) * K + k0 + c4*4];
            Bs[c4*4+0][r] = v.x; Bs[c4*4+1][r] = v.y;
            Bs[c4*4+2][r] = v.z; Bs[c4*4+3][r] = v.w;
        }
        __syncthreads();

        #pragma unroll
        for (int k = 0; k < BK; k++) {
            float ra[TM];
            #pragma unroll
            for (int i = 0; i < TM; i += 4) {
                float4 v = *(const float4*)&As[k][trow*TM + i];
                ra[i] = v.x; ra[i+1] = v.y; ra[i+2] = v.z; ra[i+3] = v.w;
            }
            ull ras[TM];
            #pragma unroll
            for (int i = 0; i < TM; i++) PACK2(ras[i], ra[i], ra[i]);

            ull rb2[TN/2];
            #pragma unroll
            for (int j4 = 0; j4 < TN/4; j4++) {
                ulonglong2 v = *(const ulonglong2*)&Bs[k][tcol*TN + j4*4];
                rb2[2*j4]   = v.x;
                rb2[2*j4+1] = v.y;
            }
            #pragma unroll
            for (int i = 0; i < TM; i++)
                #pragma unroll
                for (int j = 0; j < TN/2; j++)
                    FMA2(acc2[i][j], ras[i], rb2[j], acc2[i][j]);
        }
        __syncthreads();
    }

    #pragma unroll
    for (int i = 0; i < TM; i++) {
        size_t row = (size_t)(bm + trow*TM + i);
        float oc[TN];
        #pragma unroll
        for (int j = 0; j < TN/2; j++) UNPACK2(oc[2*j], oc[2*j+1], acc2[i][j]);
        #pragma unroll
        for (int j = 0; j < TN; j += 4) {
            int col = bn + tcol*TN + j;
            float4 b4 = *(const float4*)&bias[col];
            float4 o;
            o.x = oc[j+0] + b4.x;
            o.y = oc[j+1] + b4.y;
            o.z = oc[j+2] + b4.z;
            o.w = oc[j+3] + b4.w;
            if (RELU) {
                o.x = fmaxf(o.x, 0.f); o.y = fmaxf(o.y, 0.f);
                o.z = fmaxf(o.z, 0.f); o.w = fmaxf(o.w, 0.f);
            }
            *(float4*)&C[row * N + col] = o;
        }
    }
}

// ---------------- misc small kernels ----------------
__global__ void transpose1024(const float* __restrict__ in, float* __restrict__ out)
{
    __shared__ float tile[32][33];
    int x = blockIdx.x * 32 + threadIdx.x;
    int y = blockIdx.y * 32 + threadIdx.y;
    #pragma unroll
    for (int j = 0; j < 32; j += 8)
        tile[threadIdx.y + j][threadIdx.x] = in[(size_t)(y + j) * DM + x];
    __syncthreads();
    x = blockIdx.y * 32 + threadIdx.x;
    y = blockIdx.x * 32 + threadIdx.y;
    #pragma unroll
    for (int j = 0; j < 32; j += 8)
        out[(size_t)(y + j) * DM + x] = tile[threadIdx.x][threadIdx.y + j];
}

__global__ void bias_dot(const float* __restrict__ W, const float* __restrict__ b1,
                         const float* __restrict__ b2, float* __restrict__ out, int K)
{
    int n    = blockIdx.x * (blockDim.x / 32) + (threadIdx.x >> 5);
    int lane = threadIdx.x & 31;
    float s = 0.f;
    for (int j = lane; j < K; j += 32) s = fmaf(W[(size_t)n * K + j], b1[j], s);
    #pragma unroll
    for (int o = 16; o; o >>= 1) s += __shfl_xor_sync(0xffffffffu, s, o);
    if (lane == 0) out[n] = s + b2[n];
}

__global__ void zero_kernel(float* p, int n)
{
    int i = blockIdx.x * blockDim.x + threadIdx.x;
    if (i < n) p[i] = 0.f;
}

// ---------------- flash-style attention (packed f32x2 math) ----------------
constexpr int ATTN_SMEM = (2 * KW * DH + 2 * 256) * (int)sizeof(float); // 133120 B

__global__ __launch_bounds__(256)
void attn_kernel(const float* __restrict__ qbase, long long q_ws, int q_rs,
                 const float* __restrict__ kbase, long long k_ws, int k_rs,
                 const float* __restrict__ vbase, long long v_ws, int v_rs,
                 float* __restrict__ obase,       long long o_ws, int o_rs,
                 float scale)
{
    extern __shared__ float sm[];
    float* Ks   = sm;
    float* Vs   = sm + KW * DH;
    float* mbuf = sm + 2 * KW * DH;
    float* lbuf = mbuf + 256;

    const int h  = blockIdx.x;
    const int qt = blockIdx.y;
    const int w  = blockIdx.z;
    const int tid = threadIdx.x;

    const float* Kp = kbase + (size_t)w * k_ws + h * DH;
    const float* Vp = vbase + (size_t)w * v_ws + h * DH;

    for (int idx = tid; idx < KW * (DH/4); idx += 256) {
        int r  = idx >> 4;
        int c4 = idx & 15;
        *(float4*)(Ks + r * DH + c4*4) = *(const float4*)(Kp + (size_t)r * k_rs + c4*4);
        *(float4*)(Vs + r * DH + c4*4) = *(const float4*)(Vp + (size_t)r * v_rs + c4*4);
    }
    __syncthreads();

    const int q = tid & 63;
    const int c = tid >> 6;
    const int qrow = qt * 64 + q;

    const float* Qr = qbase + (size_t)w * q_ws + (size_t)qrow * q_rs + h * DH;
    ull qp[DH/2];
    #pragma unroll
    for (int d4 = 0; d4 < 16; d4++) {
        ulonglong2 v = *(const ulonglong2*)(Qr + d4*4);
        qp[2*d4]   = v.x;
        qp[2*d4+1] = v.y;
    }

    float m = -1e30f, l = 0.f;
    ull accp[DH/2];
    #pragma unroll
    for (int t = 0; t < DH/2; t++) accp[t] = 0ull;

    const int k0 = c * 64;
    for (int kk = 0; kk < 64; kk++) {
        const float* Krow = Ks + (k0 + kk) * DH;
        ull s0 = 0ull, s1 = 0ull, s2 = 0ull, s3 = 0ull;
        #pragma unroll
        for (int d4 = 0; d4 < 16; d4 += 2) {
            ulonglong2 a = *(const ulonglong2*)(Krow + d4*4);
            ulonglong2 b = *(const ulonglong2*)(Krow + d4*4 + 4);
            FMA2(s0, qp[2*d4+0], a.x, s0);
            FMA2(s1, qp[2*d4+1], a.y, s1);
            FMA2(s2, qp[2*d4+2], b.x, s2);
            FMA2(s3, qp[2*d4+3], b.y, s3);
        }
        float a0,a1,b0,b1,c0,c1,d0,d1;
        UNPACK2(a0,a1,s0); UNPACK2(b0,b1,s1); UNPACK2(c0,c1,s2); UNPACK2(d0,d1,s3);
        float s = ((a0+a1)+(b0+b1)) + ((c0+c1)+(d0+d1));
        s *= scale;

        if (s > m) {
            float corr = __expf(m - s);
            l *= corr;
            ull cp; PACK2(cp, corr, corr);
            #pragma unroll
            for (int t = 0; t < DH/2; t++) MUL2(accp[t], accp[t], cp);
            m = s;
        }
        float p = __expf(s - m);
        l += p;
        ull pp; PACK2(pp, p, p);
        const float* Vrow = Vs + (k0 + kk) * DH;
        #pragma unroll
        for (int d4 = 0; d4 < 16; d4 += 2) {
            ulonglong2 a = *(const ulonglong2*)(Vrow + d4*4);
            ulonglong2 b = *(const ulonglong2*)(Vrow + d4*4 + 4);
            FMA2(accp[2*d4+0], pp, a.x, accp[2*d4+0]);
            FMA2(accp[2*d4+1], pp, a.y, accp[2*d4+1]);
            FMA2(accp[2*d4+2], pp, b.x, accp[2*d4+2]);
            FMA2(accp[2*d4+3], pp, b.y, accp[2*d4+3]);
        }
    }
    __syncthreads();

    float* accbuf = Ks;
    mbuf[tid] = m;
    lbuf[tid] = l;
    #pragma unroll
    for (int d4 = 0; d4 < 16; d4++)
        *(ulonglong2*)(accbuf + (size_t)tid * DH + d4*4) =
            make_ulonglong2(accp[2*d4], accp[2*d4+1]);
    __syncthreads();

    float m0 = mbuf[q], m1 = mbuf[64+q], m2 = mbuf[128+q], m3 = mbuf[192+q];
    float mg = fmaxf(fmaxf(m0, m1), fmaxf(m2, m3));
    float e0 = __expf(m0 - mg), e1 = __expf(m1 - mg);
    float e2 = __expf(m2 - mg), e3 = __expf(m3 - mg);
    float lg = lbuf[q]*e0 + lbuf[64+q]*e1 + lbuf[128+q]*e2 + lbuf[192+q]*e3;
    float inv = 1.f / lg;

    float* Or = obase + (size_t)w * o_ws + (size_t)qrow * o_rs + h * DH;
    #pragma unroll
    for (int d = c*16; d < c*16 + 16; d++) {
        float o = accbuf[(size_t)(0*64+q)*DH + d] * e0
                + accbuf[(size_t)(1*64+q)*DH + d] * e1
                + accbuf[(size_t)(2*64+q)*DH + d] * e2
                + accbuf[(size_t)(3*64+q)*DH + d] * e3;
        Or[d] = o * inv;
    }
}

// ---------------- host ----------------
extern "C" void kernel_launch(void* const* d_in, const int* in_sizes, int n_in,
                              void* d_out, int out_size)
{
    const float* path   = (const float*)d_in[0];
    const float* w_in1  = (const float*)d_in[1];
    const float* b_in1  = (const float*)d_in[2];
    const float* w_out1 = (const float*)d_in[3];
    const float* b_out1 = (const float*)d_in[4];
    const float* w_lin  = (const float*)d_in[5];
    const float* b_lin  = (const float*)d_in[6];
    const float* w_in2  = (const float*)d_in[7];
    const float* b_in2  = (const float*)d_in[8];
    const float* w_out2 = (const float*)d_in[9];
    const float* b_out2 = (const float*)d_in[10];

    float *qkv1, *attn1, *x, *q2, *kv, *st, *wt, *wt2, *wcomb, *bcomb, *wkv, *bkv, *zb;
    cudaGetSymbolAddress((void**)&qkv1,  g_qkv1);
    cudaGetSymbolAddress((void**)&attn1, g_attn1);
    cudaGetSymbolAddress((void**)&x,     g_x);
    cudaGetSymbolAddress((void**)&q2,    g_q2);
    cudaGetSymbolAddress((void**)&kv,    g_kv);
    cudaGetSymbolAddress((void**)&st,    g_st);
    cudaGetSymbolAddress((void**)&wt,    g_wt);
    cudaGetSymbolAddress((void**)&wt2,   g_wt2);
    cudaGetSymbolAddress((void**)&wcomb, g_wcomb);
    cudaGetSymbolAddress((void**)&bcomb, g_bcomb);
    cudaGetSymbolAddress((void**)&wkv,   g_wkv);
    cudaGetSymbolAddress((void**)&bkv,   g_bkv);
    cudaGetSymbolAddress((void**)&zb,    g_zb);

    cudaFuncSetAttribute(attn_kernel, cudaFuncAttributeMaxDynamicSharedMemorySize, ATTN_SMEM);
    cudaFuncSetAttribute(gemm_tf32<false>, cudaFuncAttributeMaxDynamicSharedMemorySize, TF_SMEM);
    cudaFuncSetAttribute(gemm_tf32<true>,  cudaFuncAttributeMaxDynamicSharedMemorySize, TF_SMEM);

    auto g128  = gemm_bias<128,128,8,8,8,false>;
    auto g64   = gemm_bias<64,64,16,4,4,false>;
    auto t32   = gemm_tf32<false>;
    auto t32r  = gemm_tf32<true>;

    const float* wkv2 = w_in2 + (size_t)ODIM * ODIM;
    const float* bkv2 = b_in2 + ODIM;

    // ---- prologue (exact fp32 weight folds) ----
    zero_kernel<<<(DM+255)/256, 256>>>(zb, DM);                                 // 0
    transpose1024<<<dim3(32,32), dim3(32,8)>>>(w_out1, wt);                     // 1
    transpose1024<<<dim3(32,32), dim3(32,8)>>>(w_out2, wt2);                    // 2
    g128<<<dim3(DM/128, DM/128), 256>>>(w_lin, wt, zb, wcomb, DM, DM, DM);      // 3
    g128<<<dim3(DM/128, 2*ODIM/128), 256>>>(wkv2, wt2, zb, wkv, 2*ODIM, DM, DM);// 4

    // ---- stage 1: QKV of every path row (tf32, ncu target @ launch 5) ----
    t32<<<dim3(3*DM/128, SEQ/128), 256, TF_SMEM>>>(path, w_in1, b_in1, qkv1, SEQ, 3*DM, DM); // 5

    bias_dot<<<DM/8, 256>>>(w_lin, b_out1, b_lin, bcomb, DM);                   // 6
    bias_dot<<<2*ODIM/8, 256>>>(wkv2, b_out2, bkv2, bkv, DM);                   // 7

    // ---- stage 2: batched window self-attention (exact fp32) ----
    attn_kernel<<<dim3(NH, KW/64, NWIN), 256, ATTN_SMEM>>>(
        qkv1,        (long long)STR * 3*DM, 3*DM,
        qkv1 + DM,   (long long)STR * 3*DM, 3*DM,
        qkv1 + 2*DM, (long long)STR * 3*DM, 3*DM,
        attn1,       (long long)KW * DM,    DM,
        0.125f);

    // ---- stage 3: fused outproj1 + linear + relu (tf32) ----
    t32r<<<dim3(ODIM/128, ROWS/128), 256, TF_SMEM>>>(attn1, wcomb, bcomb, x, ROWS, ODIM, DM);

    // ---- stage 4a: bulk Q2 projections (tf32) ----
    t32<<<dim3(ODIM/128, ROWS/128), 256, TF_SMEM>>>(x, w_in2, b_in2, q2, ROWS, ODIM, ODIM);

    // ---- stage 4b: recurrence (exact fp32 serial chain) ----
    g64<<<dim3(2*ODIM/64, KW/64), 256>>>(x, wkv2, bkv2, kv, KW, 2*ODIM, ODIM);
    attn_kernel<<<dim3(NH, KW/64, 1), 256, ATTN_SMEM>>>(
        q2 + (size_t)1 * KW * ODIM, 0, ODIM,
        kv,        0, 2*ODIM,
        kv + ODIM, 0, 2*ODIM,
        st,        0, ODIM,
        0.125f);
    for (int i = 2; i < NWIN; i++) {
        g64<<<dim3(2*ODIM/64, KW/64), 256>>>(st, wkv, bkv, kv, KW, 2*ODIM, ODIM);
        attn_kernel<<<dim3(NH, KW/64, 1), 256, ATTN_SMEM>>>(
            q2 + (size_t)i * KW * ODIM, 0, ODIM,
            kv,        0, 2*ODIM,
            kv + ODIM, 0, 2*ODIM,
            st,        0, ODIM,
            0.125f);
    }
    g64<<<dim3(ODIM/64, KW/64), 256>>>(st, w_out2, b_out2, (float*)d_out, KW, ODIM, ODIM);
}

// round 4
// speedup vs baseline: 2.4063x; 1.4675x over previous
#include <cuda_runtime.h>
#include <math.h>
#include <stdint.h>

// ---------------- problem constants ----------------
constexpr int SEQ  = 4096;
constexpr int DM   = 1024;
constexpr int ODIM = 1024;
constexpr int KW   = 256;
constexpr int STR  = 16;
constexpr int NH   = 16;
constexpr int DH   = 64;
constexpr int NWIN = (SEQ - KW) / STR;   // 240
constexpr int ROWS = NWIN * KW;          // 61440

typedef unsigned long long ull;

// packed fp32x2 helpers
#define PACK2(o, lo, hi)   asm("mov.b64 %0, {%1,%2};" : "=l"(o) : "f"(lo), "f"(hi))
#define UNPACK2(lo, hi, i) asm("mov.b64 {%0,%1}, %2;" : "=f"(lo), "=f"(hi) : "l"(i))
#define FMA2(d, a, b, c)   asm("fma.rn.f32x2 %0, %1, %2, %3;" : "=l"(d) : "l"(a), "l"(b), "l"(c))
#define MUL2(d, a, b)      asm("mul.rn.f32x2 %0, %1, %2;" : "=l"(d) : "l"(a), "l"(b))

__device__ __forceinline__ uint32_t f2tf32(float f) {
    uint32_t u; asm("cvt.rna.tf32.f32 %0, %1;" : "=r"(u) : "f"(f)); return u;
}

#define MMA_TF32(c, a, b) \
    asm volatile("mma.sync.aligned.m16n8k8.row.col.f32.tf32.tf32.f32 " \
        "{%0,%1,%2,%3},{%4,%5,%6,%7},{%8,%9},{%0,%1,%2,%3};" \
        : "+f"((c)[0]), "+f"((c)[1]), "+f"((c)[2]), "+f"((c)[3]) \
        : "r"((a)[0]), "r"((a)[1]), "r"((a)[2]), "r"((a)[3]), "r"((b)[0]), "r"((b)[1]))

// ---------------- scratch ----------------
__device__ float g_qkv1[SEQ * 3 * DM];
__device__ float g_attn1[ROWS * DM];
__device__ float g_x[ROWS * ODIM];
__device__ float g_q2[ROWS * ODIM];
__device__ float g_kv[KW * 2 * ODIM];
__device__ float g_st[KW * ODIM];
__device__ float g_wt[DM * DM];
__device__ float g_wt2[DM * DM];
__device__ float g_wcomb[DM * DM];
__device__ float g_bcomb[DM];
__device__ float g_wkv[2 * ODIM * DM];
__device__ float g_bkv[2 * ODIM];
__device__ float g_zb[DM];

// ================= TF32 tensor-core GEMM, 128x128 tiles =================
constexpr int TF_BK = 32;
constexpr int TF_LD = TF_BK + 4;                       // 36 floats
constexpr int TF_BUF = (128 + 128) * TF_LD;
constexpr int TF_SMEM = 2 * TF_BUF * (int)sizeof(float);  // 73728 B

template<bool RELU>
__global__ __launch_bounds__(256)
void gemm_tf32(const float* __restrict__ A, const float* __restrict__ W,
               const float* __restrict__ bias, float* __restrict__ C,
               int M, int N, int K)
{
    extern __shared__ float smem[];
    const int tid    = threadIdx.x;
    const int lane   = tid & 31;
    const int warp   = tid >> 5;
    const int g      = lane >> 2;
    const int tg     = lane & 3;
    const int warp_m = (warp & 1) * 64;
    const int warp_n = (warp >> 1) * 32;
    const int bm     = blockIdx.y * 128;
    const int bn     = blockIdx.x * 128;

    float c[4][4][4];
    #pragma unroll
    for (int i = 0; i < 4; i++)
        #pragma unroll
        for (int j = 0; j < 4; j++)
            #pragma unroll
            for (int r = 0; r < 4; r++) c[i][j][r] = 0.f;

    const int lr = tid >> 3;
    const int lc = tid & 7;

    float4 ra[4], rw[4];
    auto loadG = [&](int t) {
        const size_t ko = (size_t)t * TF_BK + lc * 4;
        #pragma unroll
        for (int i = 0; i < 4; i++) {
            int r = lr + i * 32;
            ra[i] = *(const float4*)&A[(size_t)(bm + r) * K + ko];
            rw[i] = *(const float4*)&W[(size_t)(bn + r) * K + ko];
        }
    };
    auto storeS = [&](int buf) {
        float* As = smem + buf * TF_BUF;
        float* Bs = As + 128 * TF_LD;
        #pragma unroll
        for (int i = 0; i < 4; i++) {
            int r = lr + i * 32;
            uint4 ua = make_uint4(f2tf32(ra[i].x), f2tf32(ra[i].y), f2tf32(ra[i].z), f2tf32(ra[i].w));
            uint4 uw = make_uint4(f2tf32(rw[i].x), f2tf32(rw[i].y), f2tf32(rw[i].z), f2tf32(rw[i].w));
            *(uint4*)&As[r * TF_LD + lc * 4] = ua;
            *(uint4*)&Bs[r * TF_LD + lc * 4] = uw;
        }
    };

    const int nk = K / TF_BK;
    loadG(0);
    storeS(0);
    __syncthreads();

    for (int t = 0; t < nk; t++) {
        if (t + 1 < nk) loadG(t + 1);

        const int buf = t & 1;
        const uint32_t* Asu = (const uint32_t*)(smem + buf * TF_BUF);
        const uint32_t* Bsu = Asu + 128 * TF_LD;

        #pragma unroll
        for (int ks = 0; ks < 4; ks++) {
            uint32_t a[4][4], b[4][2];
            #pragma unroll
            for (int mt = 0; mt < 4; mt++) {
                int base = (warp_m + mt * 16 + g) * TF_LD + ks * 8 + tg;
                a[mt][0] = Asu[base];
                a[mt][1] = Asu[base + 8 * TF_LD];
                a[mt][2] = Asu[base + 4];
                a[mt][3] = Asu[base + 8 * TF_LD + 4];
            }
            #pragma unroll
            for (int nt = 0; nt < 4; nt++) {
                int base = (warp_n + nt * 8 + g) * TF_LD + ks * 8 + tg;
                b[nt][0] = Bsu[base];
                b[nt][1] = Bsu[base + 4];
            }
            #pragma unroll
            for (int mt = 0; mt < 4; mt++)
                #pragma unroll
                for (int nt = 0; nt < 4; nt++)
                    MMA_TF32(c[mt][nt], a[mt], b[nt]);
        }

        if (t + 1 < nk) storeS((t + 1) & 1);
        __syncthreads();
    }

    #pragma unroll
    for (int mt = 0; mt < 4; mt++) {
        int row0 = bm + warp_m + mt * 16 + g;
        #pragma unroll
        for (int nt = 0; nt < 4; nt++) {
            int col = bn + warp_n + nt * 8 + tg * 2;
            float2 bb = *(const float2*)&bias[col];
            float2 o0, o1;
            o0.x = c[mt][nt][0] + bb.x;  o0.y = c[mt][nt][1] + bb.y;
            o1.x = c[mt][nt][2] + bb.x;  o1.y = c[mt][nt][3] + bb.y;
            if (RELU) {
                o0.x = fmaxf(o0.x, 0.f); o0.y = fmaxf(o0.y, 0.f);
                o1.x = fmaxf(o1.x, 0.f); o1.y = fmaxf(o1.y, 0.f);
            }
            *(float2*)&C[(size_t)row0 * N + col]       = o0;
            *(float2*)&C[(size_t)(row0 + 8) * N + col] = o1;
        }
    }
}

// ================= TF32 GEMM, 64x64 tiles (latency-optimized, recurrence) ==========
constexpr int TFS_BUF = (64 + 64) * TF_LD;
constexpr int TFS_SMEM = 2 * TFS_BUF * (int)sizeof(float);  // 36864 B

__global__ __launch_bounds__(128)
void gemm_tf32_small(const float* __restrict__ A, const float* __restrict__ W,
                     const float* __restrict__ bias, float* __restrict__ C,
                     int M, int N, int K)
{
    extern __shared__ float smem[];
    const int tid    = threadIdx.x;
    const int lane   = tid & 31;
    const int warp   = tid >> 5;
    const int g      = lane >> 2;
    const int tg     = lane & 3;
    const int warp_m = (warp & 1) * 32;
    const int warp_n = (warp >> 1) * 32;
    const int bm     = blockIdx.y * 64;
    const int bn     = blockIdx.x * 64;

    float c[2][4][4];
    #pragma unroll
    for (int i = 0; i < 2; i++)
        #pragma unroll
        for (int j = 0; j < 4; j++)
            #pragma unroll
            for (int r = 0; r < 4; r++) c[i][j][r] = 0.f;

    const int lr = tid >> 3;     // 0..15
    const int lc = tid & 7;

    float4 ra[4], rw[4];
    auto loadG = [&](int t) {
        const size_t ko = (size_t)t * TF_BK + lc * 4;
        #pragma unroll
        for (int i = 0; i < 4; i++) {
            int r = lr + i * 16;
            ra[i] = *(const float4*)&A[(size_t)(bm + r) * K + ko];
            rw[i] = *(const float4*)&W[(size_t)(bn + r) * K + ko];
        }
    };
    auto storeS = [&](int buf) {
        float* As = smem + buf * TFS_BUF;
        float* Bs = As + 64 * TF_LD;
        #pragma unroll
        for (int i = 0; i < 4; i++) {
            int r = lr + i * 16;
            uint4 ua = make_uint4(f2tf32(ra[i].x), f2tf32(ra[i].y), f2tf32(ra[i].z), f2tf32(ra[i].w));
            uint4 uw = make_uint4(f2tf32(rw[i].x), f2tf32(rw[i].y), f2tf32(rw[i].z), f2tf32(rw[i].w));
            *(uint4*)&As[r * TF_LD + lc * 4] = ua;
            *(uint4*)&Bs[r * TF_LD + lc * 4] = uw;
        }
    };

    const int nk = K / TF_BK;
    loadG(0);
    storeS(0);
    __syncthreads();

    for (int t = 0; t < nk; t++) {
        if (t + 1 < nk) loadG(t + 1);

        const int buf = t & 1;
        const uint32_t* Asu = (const uint32_t*)(smem + buf * TFS_BUF);
        const uint32_t* Bsu = Asu + 64 * TF_LD;

        #pragma unroll
        for (int ks = 0; ks < 4; ks++) {
            uint32_t a[2][4], b[4][2];
            #pragma unroll
            for (int mt = 0; mt < 2; mt++) {
                int base = (warp_m + mt * 16 + g) * TF_LD + ks * 8 + tg;
                a[mt][0] = Asu[base];
                a[mt][1] = Asu[base + 8 * TF_LD];
                a[mt][2] = Asu[base + 4];
                a[mt][3] = Asu[base + 8 * TF_LD + 4];
            }
            #pragma unroll
            for (int nt = 0; nt < 4; nt++) {
                int base = (warp_n + nt * 8 + g) * TF_LD + ks * 8 + tg;
                b[nt][0] = Bsu[base];
                b[nt][1] = Bsu[base + 4];
            }
            #pragma unroll
            for (int mt = 0; mt < 2; mt++)
                #pragma unroll
                for (int nt = 0; nt < 4; nt++)
                    MMA_TF32(c[mt][nt], a[mt], b[nt]);
        }

        if (t + 1 < nk) storeS((t + 1) & 1);
        __syncthreads();
    }

    #pragma unroll
    for (int mt = 0; mt < 2; mt++) {
        int row0 = bm + warp_m + mt * 16 + g;
        #pragma unroll
        for (int nt = 0; nt < 4; nt++) {
            int col = bn + warp_n + nt * 8 + tg * 2;
            float2 bb = *(const float2*)&bias[col];
            float2 o0, o1;
            o0.x = c[mt][nt][0] + bb.x;  o0.y = c[mt][nt][1] + bb.y;
            o1.x = c[mt][nt][2] + bb.x;  o1.y = c[mt][nt][3] + bb.y;
            *(float2*)&C[(size_t)row0 * N + col]       = o0;
            *(float2*)&C[(size_t)(row0 + 8) * N + col] = o1;
        }
    }
}

// ================= exact FFMA2 SGEMM (final projection only) =================
template<int BM, int BN, int BK, int TM, int TN>
__global__ __launch_bounds__((BM/TM)*(BN/TN))
void gemm_bias(const float* __restrict__ A, const float* __restrict__ W,
               const float* __restrict__ bias, float* __restrict__ C,
               int M, int N, int K)
{
    constexpr int THREADS = (BM/TM)*(BN/TN);
    __shared__ __align__(16) float As[BK][BM];
    __shared__ __align__(16) float Bs[BK][BN];
    const int tid  = threadIdx.x;
    const int bm   = blockIdx.y * BM;
    const int bn   = blockIdx.x * BN;
    const int tcol = tid % (BN/TN);
    const int trow = tid / (BN/TN);

    ull acc2[TM][TN/2];
    #pragma unroll
    for (int i = 0; i < TM; i++)
        #pragma unroll
        for (int j = 0; j < TN/2; j++) acc2[i][j] = 0ull;

    constexpr int AF4 = BM * (BK/4);
    constexpr int BF4 = BN * (BK/4);

    for (int k0 = 0; k0 < K; k0 += BK) {
        #pragma unroll
        for (int i = tid; i < AF4; i += THREADS) {
            int r  = i / (BK/4);
            int c4 = i % (BK/4);
            float4 v = *(const float4*)&A[(size_t)(bm + r) * K + k0 + c4*4];
            As[c4*4+0][r] = v.x; As[c4*4+1][r] = v.y;
            As[c4*4+2][r] = v.z; As[c4*4+3][r] = v.w;
        }
        #pragma unroll
        for (int i = tid; i < BF4; i += THREADS) {
            int r  = i / (BK/4);
            int c4 = i % (BK/4);
            float4 v = *(const float4*)&W[(size_t)(bn + r) * K + k0 + c4*4];
            Bs[c4*4+0][r] = v.x; Bs[c4*4+1][r] = v.y;
            Bs[c4*4+2][r] = v.z; Bs[c4*4+3][r] = v.w;
        }
        __syncthreads();

        #pragma unroll
        for (int k = 0; k < BK; k++) {
            float ra[TM];
            #pragma unroll
            for (int i = 0; i < TM; i += 4) {
                float4 v = *(const float4*)&As[k][trow*TM + i];
                ra[i] = v.x; ra[i+1] = v.y; ra[i+2] = v.z; ra[i+3] = v.w;
            }
            ull ras[TM];
            #pragma unroll
            for (int i = 0; i < TM; i++) PACK2(ras[i], ra[i], ra[i]);

            ull rb2[TN/2];
            #pragma unroll
            for (int j4 = 0; j4 < TN/4; j4++) {
                ulonglong2 v = *(const ulonglong2*)&Bs[k][tcol*TN + j4*4];
                rb2[2*j4]   = v.x;
                rb2[2*j4+1] = v.y;
            }
            #pragma unroll
            for (int i = 0; i < TM; i++)
                #pragma unroll
                for (int j = 0; j < TN/2; j++)
                    FMA2(acc2[i][j], ras[i], rb2[j], acc2[i][j]);
        }
        __syncthreads();
    }

    #pragma unroll
    for (int i = 0; i < TM; i++) {
        size_t row = (size_t)(bm + trow*TM + i);
        float oc[TN];
        #pragma unroll
        for (int j = 0; j < TN/2; j++) UNPACK2(oc[2*j], oc[2*j+1], acc2[i][j]);
        #pragma unroll
        for (int j = 0; j < TN; j += 4) {
            int col = bn + tcol*TN + j;
            float4 b4 = *(const float4*)&bias[col];
            float4 o;
            o.x = oc[j+0] + b4.x;
            o.y = oc[j+1] + b4.y;
            o.z = oc[j+2] + b4.z;
            o.w = oc[j+3] + b4.w;
            *(float4*)&C[row * N + col] = o;
        }
    }
}

// ---------------- misc small kernels ----------------
__global__ void transpose1024(const float* __restrict__ in, float* __restrict__ out)
{
    __shared__ float tile[32][33];
    int x = blockIdx.x * 32 + threadIdx.x;
    int y = blockIdx.y * 32 + threadIdx.y;
    #pragma unroll
    for (int j = 0; j < 32; j += 8)
        tile[threadIdx.y + j][threadIdx.x] = in[(size_t)(y + j) * DM + x];
    __syncthreads();
    x = blockIdx.y * 32 + threadIdx.x;
    y = blockIdx.x * 32 + threadIdx.y;
    #pragma unroll
    for (int j = 0; j < 32; j += 8)
        out[(size_t)(y + j) * DM + x] = tile[threadIdx.x][threadIdx.y + j];
}

__global__ void bias_dot(const float* __restrict__ W, const float* __restrict__ b1,
                         const float* __restrict__ b2, float* __restrict__ out, int K)
{
    int n    = blockIdx.x * (blockDim.x / 32) + (threadIdx.x >> 5);
    int lane = threadIdx.x & 31;
    float s = 0.f;
    for (int j = lane; j < K; j += 32) s = fmaf(W[(size_t)n * K + j], b1[j], s);
    #pragma unroll
    for (int o = 16; o; o >>= 1) s += __shfl_xor_sync(0xffffffffu, s, o);
    if (lane == 0) out[n] = s + b2[n];
}

__global__ void zero_kernel(float* p, int n)
{
    int i = blockIdx.x * blockDim.x + threadIdx.x;
    if (i < n) p[i] = 0.f;
}

// ---------------- flash-style attention (packed f32x2 math) ----------------
constexpr int ATTN_SMEM = (2 * KW * DH + 2 * 256) * (int)sizeof(float); // 133120 B

__global__ __launch_bounds__(256)
void attn_kernel(const float* __restrict__ qbase, long long q_ws, int q_rs,
                 const float* __restrict__ kbase, long long k_ws, int k_rs,
                 const float* __restrict__ vbase, long long v_ws, int v_rs,
                 float* __restrict__ obase,       long long o_ws, int o_rs,
                 float scale)
{
    extern __shared__ float sm[];
    float* Ks   = sm;
    float* Vs   = sm + KW * DH;
    float* mbuf = sm + 2 * KW * DH;
    float* lbuf = mbuf + 256;

    const int h  = blockIdx.x;
    const int qt = blockIdx.y;
    const int w  = blockIdx.z;
    const int tid = threadIdx.x;

    const float* Kp = kbase + (size_t)w * k_ws + h * DH;
    const float* Vp = vbase + (size_t)w * v_ws + h * DH;

    for (int idx = tid; idx < KW * (DH/4); idx += 256) {
        int r  = idx >> 4;
        int c4 = idx & 15;
        *(float4*)(Ks + r * DH + c4*4) = *(const float4*)(Kp + (size_t)r * k_rs + c4*4);
        *(float4*)(Vs + r * DH + c4*4) = *(const float4*)(Vp + (size_t)r * v_rs + c4*4);
    }
    __syncthreads();

    const int q = tid & 63;
    const int c = tid >> 6;
    const int qrow = qt * 64 + q;

    const float* Qr = qbase + (size_t)w * q_ws + (size_t)qrow * q_rs + h * DH;
    ull qp[DH/2];
    #pragma unroll
    for (int d4 = 0; d4 < 16; d4++) {
        ulonglong2 v = *(const ulonglong2*)(Qr + d4*4);
        qp[2*d4]   = v.x;
        qp[2*d4+1] = v.y;
    }

    float m = -1e30f, l = 0.f;
    ull accp[DH/2];
    #pragma unroll
    for (int t = 0; t < DH/2; t++) accp[t] = 0ull;

    const int k0 = c * 64;
    for (int kk = 0; kk < 64; kk++) {
        const float* Krow = Ks + (k0 + kk) * DH;
        ull s0 = 0ull, s1 = 0ull, s2 = 0ull, s3 = 0ull;
        #pragma unroll
        for (int d4 = 0; d4 < 16; d4 += 2) {
            ulonglong2 a = *(const ulonglong2*)(Krow + d4*4);
            ulonglong2 b = *(const ulonglong2*)(Krow + d4*4 + 4);
            FMA2(s0, qp[2*d4+0], a.x, s0);
            FMA2(s1, qp[2*d4+1], a.y, s1);
            FMA2(s2, qp[2*d4+2], b.x, s2);
            FMA2(s3, qp[2*d4+3], b.y, s3);
        }
        float a0,a1,b0,b1,c0,c1,d0,d1;
        UNPACK2(a0,a1,s0); UNPACK2(b0,b1,s1); UNPACK2(c0,c1,s2); UNPACK2(d0,d1,s3);
        float s = ((a0+a1)+(b0+b1)) + ((c0+c1)+(d0+d1));
        s *= scale;

        if (s > m) {
            float corr = __expf(m - s);
            l *= corr;
            ull cp; PACK2(cp, corr, corr);
            #pragma unroll
            for (int t = 0; t < DH/2; t++) MUL2(accp[t], accp[t], cp);
            m = s;
        }
        float p = __expf(s - m);
        l += p;
        ull pp; PACK2(pp, p, p);
        const float* Vrow = Vs + (k0 + kk) * DH;
        #pragma unroll
        for (int d4 = 0; d4 < 16; d4 += 2) {
            ulonglong2 a = *(const ulonglong2*)(Vrow + d4*4);
            ulonglong2 b = *(const ulonglong2*)(Vrow + d4*4 + 4);
            FMA2(accp[2*d4+0], pp, a.x, accp[2*d4+0]);
            FMA2(accp[2*d4+1], pp, a.y, accp[2*d4+1]);
            FMA2(accp[2*d4+2], pp, b.x, accp[2*d4+2]);
            FMA2(accp[2*d4+3], pp, b.y, accp[2*d4+3]);
        }
    }
    __syncthreads();

    float* accbuf = Ks;
    mbuf[tid] = m;
    lbuf[tid] = l;
    #pragma unroll
    for (int d4 = 0; d4 < 16; d4++)
        *(ulonglong2*)(accbuf + (size_t)tid * DH + d4*4) =
            make_ulonglong2(accp[2*d4], accp[2*d4+1]);
    __syncthreads();

    float m0 = mbuf[q], m1 = mbuf[64+q], m2 = mbuf[128+q], m3 = mbuf[192+q];
    float mg = fmaxf(fmaxf(m0, m1), fmaxf(m2, m3));
    float e0 = __expf(m0 - mg), e1 = __expf(m1 - mg);
    float e2 = __expf(m2 - mg), e3 = __expf(m3 - mg);
    float lg = lbuf[q]*e0 + lbuf[64+q]*e1 + lbuf[128+q]*e2 + lbuf[192+q]*e3;
    float inv = 1.f / lg;

    float* Or = obase + (size_t)w * o_ws + (size_t)qrow * o_rs + h * DH;
    #pragma unroll
    for (int d = c*16; d < c*16 + 16; d++) {
        float o = accbuf[(size_t)(0*64+q)*DH + d] * e0
                + accbuf[(size_t)(1*64+q)*DH + d] * e1
                + accbuf[(size_t)(2*64+q)*DH + d] * e2
                + accbuf[(size_t)(3*64+q)*DH + d] * e3;
        Or[d] = o * inv;
    }
}

// ---------------- host ----------------
extern "C" void kernel_launch(void* const* d_in, const int* in_sizes, int n_in,
                              void* d_out, int out_size)
{
    const float* path   = (const float*)d_in[0];
    const float* w_in1  = (const float*)d_in[1];
    const float* b_in1  = (const float*)d_in[2];
    const float* w_out1 = (const float*)d_in[3];
    const float* b_out1 = (const float*)d_in[4];
    const float* w_lin  = (const float*)d_in[5];
    const float* b_lin  = (const float*)d_in[6];
    const float* w_in2  = (const float*)d_in[7];
    const float* b_in2  = (const float*)d_in[8];
    const float* w_out2 = (const float*)d_in[9];
    const float* b_out2 = (const float*)d_in[10];

    float *qkv1, *attn1, *x, *q2, *kv, *st, *wt, *wt2, *wcomb, *bcomb, *wkv, *bkv, *zb;
    cudaGetSymbolAddress((void**)&qkv1,  g_qkv1);
    cudaGetSymbolAddress((void**)&attn1, g_attn1);
    cudaGetSymbolAddress((void**)&x,     g_x);
    cudaGetSymbolAddress((void**)&q2,    g_q2);
    cudaGetSymbolAddress((void**)&kv,    g_kv);
    cudaGetSymbolAddress((void**)&st,    g_st);
    cudaGetSymbolAddress((void**)&wt,    g_wt);
    cudaGetSymbolAddress((void**)&wt2,   g_wt2);
    cudaGetSymbolAddress((void**)&wcomb, g_wcomb);
    cudaGetSymbolAddress((void**)&bcomb, g_bcomb);
    cudaGetSymbolAddress((void**)&wkv,   g_wkv);
    cudaGetSymbolAddress((void**)&bkv,   g_bkv);
    cudaGetSymbolAddress((void**)&zb,    g_zb);

    cudaFuncSetAttribute(attn_kernel, cudaFuncAttributeMaxDynamicSharedMemorySize, ATTN_SMEM);
    cudaFuncSetAttribute(gemm_tf32<false>, cudaFuncAttributeMaxDynamicSharedMemorySize, TF_SMEM);
    cudaFuncSetAttribute(gemm_tf32<true>,  cudaFuncAttributeMaxDynamicSharedMemorySize, TF_SMEM);
    cudaFuncSetAttribute(gemm_tf32_small,  cudaFuncAttributeMaxDynamicSharedMemorySize, TFS_SMEM);

    auto g64   = gemm_bias<64,64,16,4,4>;
    auto t32   = gemm_tf32<false>;
    auto t32r  = gemm_tf32<true>;

    const float* wkv2 = w_in2 + (size_t)ODIM * ODIM;
    const float* bkv2 = b_in2 + ODIM;

    // ---- prologue (tf32 weight folds) ----
    zero_kernel<<<(DM+255)/256, 256>>>(zb, DM);                                  // 0
    transpose1024<<<dim3(32,32), dim3(32,8)>>>(w_out1, wt);                      // 1
    transpose1024<<<dim3(32,32), dim3(32,8)>>>(w_out2, wt2);                     // 2
    t32<<<dim3(DM/128, DM/128), 256, TF_SMEM>>>(w_lin, wt, zb, wcomb, DM, DM, DM);      // 3
    t32<<<dim3(DM/128, 2*ODIM/128), 256, TF_SMEM>>>(wkv2, wt2, zb, wkv, 2*ODIM, DM, DM);// 4

    // ---- stage 1: QKV of every path row (tf32; ncu target @ launch 5) ----
    t32<<<dim3(3*DM/128, SEQ/128), 256, TF_SMEM>>>(path, w_in1, b_in1, qkv1, SEQ, 3*DM, DM); // 5

    bias_dot<<<DM/8, 256>>>(w_lin, b_out1, b_lin, bcomb, DM);                    // 6
    bias_dot<<<2*ODIM/8, 256>>>(wkv2, b_out2, bkv2, bkv, DM);                    // 7

    // ---- stage 2: batched window self-attention (exact fp32) ----
    attn_kernel<<<dim3(NH, KW/64, NWIN), 256, ATTN_SMEM>>>(
        qkv1,        (long long)STR * 3*DM, 3*DM,
        qkv1 + DM,   (long long)STR * 3*DM, 3*DM,
        qkv1 + 2*DM, (long long)STR * 3*DM, 3*DM,
        attn1,       (long long)KW * DM,    DM,
        0.125f);

    // ---- stage 3: fused outproj1 + linear + relu (tf32) ----
    t32r<<<dim3(ODIM/128, ROWS/128), 256, TF_SMEM>>>(attn1, wcomb, bcomb, x, ROWS, ODIM, DM);

    // ---- stage 4a: bulk Q2 projections (tf32) ----
    t32<<<dim3(ODIM/128, ROWS/128), 256, TF_SMEM>>>(x, w_in2, b_in2, q2, ROWS, ODIM, ODIM);

    // ---- stage 4b: recurrence (tf32 KV proj + fp32 attention) ----
    gemm_tf32_small<<<dim3(2*ODIM/64, KW/64), 128, TFS_SMEM>>>(
        x, wkv2, bkv2, kv, KW, 2*ODIM, ODIM);
    attn_kernel<<<dim3(NH, KW/64, 1), 256, ATTN_SMEM>>>(
        q2 + (size_t)1 * KW * ODIM, 0, ODIM,
        kv,        0, 2*ODIM,
        kv + ODIM, 0, 2*ODIM,
        st,        0, ODIM,
        0.125f);
    for (int i = 2; i < NWIN; i++) {
        gemm_tf32_small<<<dim3(2*ODIM/64, KW/64), 128, TFS_SMEM>>>(
            st, wkv, bkv, kv, KW, 2*ODIM, ODIM);
        attn_kernel<<<dim3(NH, KW/64, 1), 256, ATTN_SMEM>>>(
            q2 + (size_t)i * KW * ODIM, 0, ODIM,
            kv,        0, 2*ODIM,
            kv + ODIM, 0, 2*ODIM,
            st,        0, ODIM,
            0.125f);
    }
    // ---- final out-projection (exact fp32 -> d_out) ----
    g64<<<dim3(ODIM/64, KW/64), 256>>>(st, w_out2, b_out2, (float*)d_out, KW, ODIM, ODIM);
}

// round 5
// speedup vs baseline: 3.1289x; 1.3003x over previous
#include <cuda_runtime.h>
#include <math.h>
#include <stdint.h>

// ---------------- problem constants ----------------
constexpr int SEQ  = 4096;
constexpr int DM   = 1024;
constexpr int ODIM = 1024;
constexpr int KW   = 256;
constexpr int STR  = 16;
constexpr int NH   = 16;
constexpr int DH   = 64;
constexpr int NWIN = (SEQ - KW) / STR;   // 240
constexpr int ROWS = NWIN * KW;          // 61440

typedef unsigned long long ull;

// packed fp32x2 helpers
#define PACK2(o, lo, hi)   asm("mov.b64 %0, {%1,%2};" : "=l"(o) : "f"(lo), "f"(hi))
#define UNPACK2(lo, hi, i) asm("mov.b64 {%0,%1}, %2;" : "=f"(lo), "=f"(hi) : "l"(i))
#define FMA2(d, a, b, c)   asm("fma.rn.f32x2 %0, %1, %2, %3;" : "=l"(d) : "l"(a), "l"(b), "l"(c))
#define MUL2(d, a, b)      asm("mul.rn.f32x2 %0, %1, %2;" : "=l"(d) : "l"(a), "l"(b))

__device__ __forceinline__ uint32_t f2tf32(float f) {
    uint32_t u; asm("cvt.rna.tf32.f32 %0, %1;" : "=r"(u) : "f"(f)); return u;
}

#define MMA_TF32(c, a, b) \
    asm volatile("mma.sync.aligned.m16n8k8.row.col.f32.tf32.tf32.f32 " \
        "{%0,%1,%2,%3},{%4,%5,%6,%7},{%8,%9},{%0,%1,%2,%3};" \
        : "+f"((c)[0]), "+f"((c)[1]), "+f"((c)[2]), "+f"((c)[3]) \
        : "r"((a)[0]), "r"((a)[1]), "r"((a)[2]), "r"((a)[3]), "r"((b)[0]), "r"((b)[1]))

// ---------------- scratch ----------------
__device__ float g_qkv1[SEQ * 3 * DM];
__device__ float g_attn1[ROWS * DM];
__device__ float g_x[ROWS * ODIM];
__device__ float g_q2[ROWS * ODIM];
__device__ float g_kv[KW * 2 * ODIM];
__device__ float g_st[KW * ODIM];
__device__ float g_wt[DM * DM];
__device__ float g_wt2[DM * DM];
__device__ float g_wcomb[DM * DM];
__device__ float g_bcomb[DM];
__device__ float g_wkv[2 * ODIM * DM];
__device__ float g_bkv[2 * ODIM];
__device__ float g_zb[DM];

// persistent-kernel barrier state (monotonic; replay-safe)
__device__ unsigned g_bar_arrive  = 0;
__device__ unsigned g_bar_release = 0;

// ================= TF32 tensor-core GEMM, 128x128 tiles =================
constexpr int TF_BK = 32;
constexpr int TF_LD = TF_BK + 4;                       // 36 floats
constexpr int TF_BUF = (128 + 128) * TF_LD;
constexpr int TF_SMEM = 2 * TF_BUF * (int)sizeof(float);  // 73728 B

template<bool RELU>
__global__ __launch_bounds__(256)
void gemm_tf32(const float* __restrict__ A, const float* __restrict__ W,
               const float* __restrict__ bias, float* __restrict__ C,
               int M, int N, int K)
{
    extern __shared__ float smem[];
    const int tid    = threadIdx.x;
    const int lane   = tid & 31;
    const int warp   = tid >> 5;
    const int g      = lane >> 2;
    const int tg     = lane & 3;
    const int warp_m = (warp & 1) * 64;
    const int warp_n = (warp >> 1) * 32;
    const int bm     = blockIdx.y * 128;
    const int bn     = blockIdx.x * 128;

    float c[4][4][4];
    #pragma unroll
    for (int i = 0; i < 4; i++)
        #pragma unroll
        for (int j = 0; j < 4; j++)
            #pragma unroll
            for (int r = 0; r < 4; r++) c[i][j][r] = 0.f;

    const int lr = tid >> 3;
    const int lc = tid & 7;

    float4 ra[4], rw[4];
    auto loadG = [&](int t) {
        const size_t ko = (size_t)t * TF_BK + lc * 4;
        #pragma unroll
        for (int i = 0; i < 4; i++) {
            int r = lr + i * 32;
            ra[i] = *(const float4*)&A[(size_t)(bm + r) * K + ko];
            rw[i] = *(const float4*)&W[(size_t)(bn + r) * K + ko];
        }
    };
    auto storeS = [&](int buf) {
        float* As = smem + buf * TF_BUF;
        float* Bs = As + 128 * TF_LD;
        #pragma unroll
        for (int i = 0; i < 4; i++) {
            int r = lr + i * 32;
            uint4 ua = make_uint4(f2tf32(ra[i].x), f2tf32(ra[i].y), f2tf32(ra[i].z), f2tf32(ra[i].w));
            uint4 uw = make_uint4(f2tf32(rw[i].x), f2tf32(rw[i].y), f2tf32(rw[i].z), f2tf32(rw[i].w));
            *(uint4*)&As[r * TF_LD + lc * 4] = ua;
            *(uint4*)&Bs[r * TF_LD + lc * 4] = uw;
        }
    };

    const int nk = K / TF_BK;
    loadG(0);
    storeS(0);
    __syncthreads();

    for (int t = 0; t < nk; t++) {
        if (t + 1 < nk) loadG(t + 1);

        const int buf = t & 1;
        const uint32_t* Asu = (const uint32_t*)(smem + buf * TF_BUF);
        const uint32_t* Bsu = Asu + 128 * TF_LD;

        #pragma unroll
        for (int ks = 0; ks < 4; ks++) {
            uint32_t a[4][4], b[4][2];
            #pragma unroll
            for (int mt = 0; mt < 4; mt++) {
                int base = (warp_m + mt * 16 + g) * TF_LD + ks * 8 + tg;
                a[mt][0] = Asu[base];
                a[mt][1] = Asu[base + 8 * TF_LD];
                a[mt][2] = Asu[base + 4];
                a[mt][3] = Asu[base + 8 * TF_LD + 4];
            }
            #pragma unroll
            for (int nt = 0; nt < 4; nt++) {
                int base = (warp_n + nt * 8 + g) * TF_LD + ks * 8 + tg;
                b[nt][0] = Bsu[base];
                b[nt][1] = Bsu[base + 4];
            }
            #pragma unroll
            for (int mt = 0; mt < 4; mt++)
                #pragma unroll
                for (int nt = 0; nt < 4; nt++)
                    MMA_TF32(c[mt][nt], a[mt], b[nt]);
        }

        if (t + 1 < nk) storeS((t + 1) & 1);
        __syncthreads();
    }

    #pragma unroll
    for (int mt = 0; mt < 4; mt++) {
        int row0 = bm + warp_m + mt * 16 + g;
        #pragma unroll
        for (int nt = 0; nt < 4; nt++) {
            int col = bn + warp_n + nt * 8 + tg * 2;
            float2 bb = *(const float2*)&bias[col];
            float2 o0, o1;
            o0.x = c[mt][nt][0] + bb.x;  o0.y = c[mt][nt][1] + bb.y;
            o1.x = c[mt][nt][2] + bb.x;  o1.y = c[mt][nt][3] + bb.y;
            if (RELU) {
                o0.x = fmaxf(o0.x, 0.f); o0.y = fmaxf(o0.y, 0.f);
                o1.x = fmaxf(o1.x, 0.f); o1.y = fmaxf(o1.y, 0.f);
            }
            *(float2*)&C[(size_t)row0 * N + col]       = o0;
            *(float2*)&C[(size_t)(row0 + 8) * N + col] = o1;
        }
    }
}

// ================= exact FFMA2 SGEMM (final projection only) =================
template<int BM, int BN, int BK, int TM, int TN>
__global__ __launch_bounds__((BM/TM)*(BN/TN))
void gemm_bias(const float* __restrict__ A, const float* __restrict__ W,
               const float* __restrict__ bias, float* __restrict__ C,
               int M, int N, int K)
{
    constexpr int THREADS = (BM/TM)*(BN/TN);
    __shared__ __align__(16) float As[BK][BM];
    __shared__ __align__(16) float Bs[BK][BN];
    const int tid  = threadIdx.x;
    const int bm   = blockIdx.y * BM;
    const int bn   = blockIdx.x * BN;
    const int tcol = tid % (BN/TN);
    const int trow = tid / (BN/TN);

    ull acc2[TM][TN/2];
    #pragma unroll
    for (int i = 0; i < TM; i++)
        #pragma unroll
        for (int j = 0; j < TN/2; j++) acc2[i][j] = 0ull;

    constexpr int AF4 = BM * (BK/4);
    constexpr int BF4 = BN * (BK/4);

    for (int k0 = 0; k0 < K; k0 += BK) {
        #pragma unroll
        for (int i = tid; i < AF4; i += THREADS) {
            int r  = i / (BK/4);
            int c4 = i % (BK/4);
            float4 v = *(const float4*)&A[(size_t)(bm + r) * K + k0 + c4*4];
            As[c4*4+0][r] = v.x; As[c4*4+1][r] = v.y;
            As[c4*4+2][r] = v.z; As[c4*4+3][r] = v.w;
        }
        #pragma unroll
        for (int i = tid; i < BF4; i += THREADS) {
            int r  = i / (BK/4);
            int c4 = i % (BK/4);
            float4 v = *(const float4*)&W[(size_t)(bn + r) * K + k0 + c4*4];
            Bs[c4*4+0][r] = v.x; Bs[c4*4+1][r] = v.y;
            Bs[c4*4+2][r] = v.z; Bs[c4*4+3][r] = v.w;
        }
        __syncthreads();

        #pragma unroll
        for (int k = 0; k < BK; k++) {
            float ra[TM];
            #pragma unroll
            for (int i = 0; i < TM; i += 4) {
                float4 v = *(const float4*)&As[k][trow*TM + i];
                ra[i] = v.x; ra[i+1] = v.y; ra[i+2] = v.z; ra[i+3] = v.w;
            }
            ull ras[TM];
            #pragma unroll
            for (int i = 0; i < TM; i++) PACK2(ras[i], ra[i], ra[i]);

            ull rb2[TN/2];
            #pragma unroll
            for (int j4 = 0; j4 < TN/4; j4++) {
                ulonglong2 v = *(const ulonglong2*)&Bs[k][tcol*TN + j4*4];
                rb2[2*j4]   = v.x;
                rb2[2*j4+1] = v.y;
            }
            #pragma unroll
            for (int i = 0; i < TM; i++)
                #pragma unroll
                for (int j = 0; j < TN/2; j++)
                    FMA2(acc2[i][j], ras[i], rb2[j], acc2[i][j]);
        }
        __syncthreads();
    }

    #pragma unroll
    for (int i = 0; i < TM; i++) {
        size_t row = (size_t)(bm + trow*TM + i);
        float oc[TN];
        #pragma unroll
        for (int j = 0; j < TN/2; j++) UNPACK2(oc[2*j], oc[2*j+1], acc2[i][j]);
        #pragma unroll
        for (int j = 0; j < TN; j += 4) {
            int col = bn + tcol*TN + j;
            float4 b4 = *(const float4*)&bias[col];
            float4 o;
            o.x = oc[j+0] + b4.x;
            o.y = oc[j+1] + b4.y;
            o.z = oc[j+2] + b4.z;
            o.w = oc[j+3] + b4.w;
            *(float4*)&C[row * N + col] = o;
        }
    }
}

// ---------------- misc small kernels ----------------
__global__ void transpose1024(const float* __restrict__ in, float* __restrict__ out)
{
    __shared__ float tile[32][33];
    int x = blockIdx.x * 32 + threadIdx.x;
    int y = blockIdx.y * 32 + threadIdx.y;
    #pragma unroll
    for (int j = 0; j < 32; j += 8)
        tile[threadIdx.y + j][threadIdx.x] = in[(size_t)(y + j) * DM + x];
    __syncthreads();
    x = blockIdx.y * 32 + threadIdx.x;
    y = blockIdx.x * 32 + threadIdx.y;
    #pragma unroll
    for (int j = 0; j < 32; j += 8)
        out[(size_t)(y + j) * DM + x] = tile[threadIdx.x][threadIdx.y + j];
}

__global__ void bias_dot(const float* __restrict__ W, const float* __restrict__ b1,
                         const float* __restrict__ b2, float* __restrict__ out, int K)
{
    int n    = blockIdx.x * (blockDim.x / 32) + (threadIdx.x >> 5);
    int lane = threadIdx.x & 31;
    float s = 0.f;
    for (int j = lane; j < K; j += 32) s = fmaf(W[(size_t)n * K + j], b1[j], s);
    #pragma unroll
    for (int o = 16; o; o >>= 1) s += __shfl_xor_sync(0xffffffffu, s, o);
    if (lane == 0) out[n] = s + b2[n];
}

__global__ void zero_kernel(float* p, int n)
{
    int i = blockIdx.x * blockDim.x + threadIdx.x;
    if (i < n) p[i] = 0.f;
}

// ---------------- flash-style attention (stage 2 bulk; packed f32x2) ----------------
constexpr int ATTN_SMEM = (2 * KW * DH + 2 * 256) * (int)sizeof(float); // 133120 B

__global__ __launch_bounds__(256)
void attn_kernel(const float* __restrict__ qbase, long long q_ws, int q_rs,
                 const float* __restrict__ kbase, long long k_ws, int k_rs,
                 const float* __restrict__ vbase, long long v_ws, int v_rs,
                 float* __restrict__ obase,       long long o_ws, int o_rs,
                 float scale)
{
    extern __shared__ float sm[];
    float* Ks   = sm;
    float* Vs   = sm + KW * DH;
    float* mbuf = sm + 2 * KW * DH;
    float* lbuf = mbuf + 256;

    const int h  = blockIdx.x;
    const int qt = blockIdx.y;
    const int w  = blockIdx.z;
    const int tid = threadIdx.x;

    const float* Kp = kbase + (size_t)w * k_ws + h * DH;
    const float* Vp = vbase + (size_t)w * v_ws + h * DH;

    for (int idx = tid; idx < KW * (DH/4); idx += 256) {
        int r  = idx >> 4;
        int c4 = idx & 15;
        *(float4*)(Ks + r * DH + c4*4) = *(const float4*)(Kp + (size_t)r * k_rs + c4*4);
        *(float4*)(Vs + r * DH + c4*4) = *(const float4*)(Vp + (size_t)r * v_rs + c4*4);
    }
    __syncthreads();

    const int q = tid & 63;
    const int c = tid >> 6;
    const int qrow = qt * 64 + q;

    const float* Qr = qbase + (size_t)w * q_ws + (size_t)qrow * q_rs + h * DH;
    ull qp[DH/2];
    #pragma unroll
    for (int d4 = 0; d4 < 16; d4++) {
        ulonglong2 v = *(const ulonglong2*)(Qr + d4*4);
        qp[2*d4]   = v.x;
        qp[2*d4+1] = v.y;
    }

    float m = -1e30f, l = 0.f;
    ull accp[DH/2];
    #pragma unroll
    for (int t = 0; t < DH/2; t++) accp[t] = 0ull;

    const int k0 = c * 64;
    for (int kk = 0; kk < 64; kk++) {
        const float* Krow = Ks + (k0 + kk) * DH;
        ull s0 = 0ull, s1 = 0ull, s2 = 0ull, s3 = 0ull;
        #pragma unroll
        for (int d4 = 0; d4 < 16; d4 += 2) {
            ulonglong2 a = *(const ulonglong2*)(Krow + d4*4);
            ulonglong2 b = *(const ulonglong2*)(Krow + d4*4 + 4);
            FMA2(s0, qp[2*d4+0], a.x, s0);
            FMA2(s1, qp[2*d4+1], a.y, s1);
            FMA2(s2, qp[2*d4+2], b.x, s2);
            FMA2(s3, qp[2*d4+3], b.y, s3);
        }
        float a0,a1,b0,b1,c0,c1,d0,d1;
        UNPACK2(a0,a1,s0); UNPACK2(b0,b1,s1); UNPACK2(c0,c1,s2); UNPACK2(d0,d1,s3);
        float s = ((a0+a1)+(b0+b1)) + ((c0+c1)+(d0+d1));
        s *= scale;

        if (s > m) {
            float corr = __expf(m - s);
            l *= corr;
            ull cp; PACK2(cp, corr, corr);
            #pragma unroll
            for (int t = 0; t < DH/2; t++) MUL2(accp[t], accp[t], cp);
            m = s;
        }
        float p = __expf(s - m);
        l += p;
        ull pp; PACK2(pp, p, p);
        const float* Vrow = Vs + (k0 + kk) * DH;
        #pragma unroll
        for (int d4 = 0; d4 < 16; d4 += 2) {
            ulonglong2 a = *(const ulonglong2*)(Vrow + d4*4);
            ulonglong2 b = *(const ulonglong2*)(Vrow + d4*4 + 4);
            FMA2(accp[2*d4+0], pp, a.x, accp[2*d4+0]);
            FMA2(accp[2*d4+1], pp, a.y, accp[2*d4+1]);
            FMA2(accp[2*d4+2], pp, b.x, accp[2*d4+2]);
            FMA2(accp[2*d4+3], pp, b.y, accp[2*d4+3]);
        }
    }
    __syncthreads();

    float* accbuf = Ks;
    mbuf[tid] = m;
    lbuf[tid] = l;
    #pragma unroll
    for (int d4 = 0; d4 < 16; d4++)
        *(ulonglong2*)(accbuf + (size_t)tid * DH + d4*4) =
            make_ulonglong2(accp[2*d4], accp[2*d4+1]);
    __syncthreads();

    float m0 = mbuf[q], m1 = mbuf[64+q], m2 = mbuf[128+q], m3 = mbuf[192+q];
    float mg = fmaxf(fmaxf(m0, m1), fmaxf(m2, m3));
    float e0 = __expf(m0 - mg), e1 = __expf(m1 - mg);
    float e2 = __expf(m2 - mg), e3 = __expf(m3 - mg);
    float lg = lbuf[q]*e0 + lbuf[64+q]*e1 + lbuf[128+q]*e2 + lbuf[192+q]*e3;
    float inv = 1.f / lg;

    float* Or = obase + (size_t)w * o_ws + (size_t)qrow * o_rs + h * DH;
    #pragma unroll
    for (int d = c*16; d < c*16 + 16; d++) {
        float o = accbuf[(size_t)(0*64+q)*DH + d] * e0
                + accbuf[(size_t)(1*64+q)*DH + d] * e1
                + accbuf[(size_t)(2*64+q)*DH + d] * e2
                + accbuf[(size_t)(3*64+q)*DH + d] * e3;
        Or[d] = o * inv;
    }
}

// ================= persistent recurrence kernel =================
// grid = 128 CTAs (<=148 SMs, 1 CTA/SM by smem), 256 threads.
// Loops i = 1..239. Phase A: kv = A @ Wkv^T + b  (128 tf32 64x64 tiles).
// Phase B: st = attn(q2[i], kv)  (16 heads x 8 q-tiles of 32 = 128 units).
constexpr int REC_NB   = 128;
constexpr int REC_SMEM = (32768 + 512) * (int)sizeof(float);   // 133120 B
constexpr int REC_ABUF = 128 * TF_LD;                          // floats per A/B stage buffer

__device__ __forceinline__ void grid_bar(unsigned base, unsigned bar_id)
{
    __syncthreads();
    if (threadIdx.x == 0) {
        __threadfence();   // publish our writes; gpu-scope fence also invalidates L1D
        unsigned a = atomicAdd(&g_bar_arrive, 1u);
        if ((a & (REC_NB - 1u)) == (REC_NB - 1u)) {
            atomicAdd(&g_bar_release, 1u);
        } else {
            while (*(volatile unsigned*)&g_bar_release - base < bar_id) __nanosleep(32);
        }
        __threadfence();   // acquire side: invalidate stale L1 before consuming peers' data
    }
    __syncthreads();
}

__global__ __launch_bounds__(256)
void recurrence_kernel(const float* __restrict__ x,
                       const float* __restrict__ q2,
                       const float* __restrict__ wkv2, const float* __restrict__ bkv2,
                       const float* __restrict__ wkvF, const float* __restrict__ bkvF,
                       float* __restrict__ kv, float* __restrict__ st)
{
    extern __shared__ float sm[];
    const int tid = threadIdx.x;
    const int bid = blockIdx.x;

    __shared__ unsigned s_base;
    if (tid == 0) s_base = *(volatile unsigned*)&g_bar_release;
    __syncthreads();
    const unsigned base = s_base;
    unsigned bar_id = 0;

    // phase A ids
    const int lane = tid & 31, warp = tid >> 5;
    const int g = lane >> 2, tg = lane & 3;
    const int warp_m = (warp & 1) * 32;
    const int warp_n = (warp >> 1) * 16;
    const int tm = bid >> 5;            // 0..3   (M tile)
    const int tn = bid & 31;            // 0..31  (N tile)
    const int lr = tid >> 3, lc = tid & 7;

    // phase B ids
    const int h  = bid >> 3;            // head 0..15
    const int qt = bid & 7;             // q-tile 0..7 (32 queries)
    const int q  = tid & 31;
    const int ck = tid >> 5;            // key chunk 0..7 (32 keys)

    for (int i = 1; i < NWIN; i++) {
        // ================= Phase A: KV projection =================
        {
            const float* A  = (i == 1) ? x    : st;
            const float* W  = (i == 1) ? wkv2 : wkvF;
            const float* bb = (i == 1) ? bkv2 : bkvF;

            float cacc[2][2][4];
            #pragma unroll
            for (int mt = 0; mt < 2; mt++)
                #pragma unroll
                for (int nt = 0; nt < 2; nt++)
                    #pragma unroll
                    for (int r = 0; r < 4; r++) cacc[mt][nt][r] = 0.f;

            float4 ra[2], rw[2];
            auto loadG = [&](int t) {
                size_t ko = (size_t)t * TF_BK + lc * 4;
                ra[0] = __ldcg((const float4*)&A[(size_t)(tm*64 + lr)      * 1024 + ko]);
                ra[1] = __ldcg((const float4*)&A[(size_t)(tm*64 + lr + 32) * 1024 + ko]);
                rw[0] = *(const float4*)&W[(size_t)(tn*64 + lr)      * 1024 + ko];
                rw[1] = *(const float4*)&W[(size_t)(tn*64 + lr + 32) * 1024 + ko];
            };
            auto storeS = [&](int buf) {
                float* As = sm + buf * REC_ABUF;
                float* Bs = As + 64 * TF_LD;
                uint4 u0 = make_uint4(f2tf32(ra[0].x), f2tf32(ra[0].y), f2tf32(ra[0].z), f2tf32(ra[0].w));
                uint4 u1 = make_uint4(f2tf32(ra[1].x), f2tf32(ra[1].y), f2tf32(ra[1].z), f2tf32(ra[1].w));
                uint4 w0 = make_uint4(f2tf32(rw[0].x), f2tf32(rw[0].y), f2tf32(rw[0].z), f2tf32(rw[0].w));
                uint4 w1 = make_uint4(f2tf32(rw[1].x), f2tf32(rw[1].y), f2tf32(rw[1].z), f2tf32(rw[1].w));
                *(uint4*)&As[lr * TF_LD + lc*4]        = u0;
                *(uint4*)&As[(lr+32) * TF_LD + lc*4]   = u1;
                *(uint4*)&Bs[lr * TF_LD + lc*4]        = w0;
                *(uint4*)&Bs[(lr+32) * TF_LD + lc*4]   = w1;
            };

            loadG(0);
            storeS(0);
            __syncthreads();

            for (int t = 0; t < 32; t++) {
                if (t + 1 < 32) loadG(t + 1);
                const uint32_t* Asu = (const uint32_t*)(sm + (t & 1) * REC_ABUF);
                const uint32_t* Bsu = Asu + 64 * TF_LD;
                #pragma unroll
                for (int ks = 0; ks < 4; ks++) {
                    uint32_t a[2][4], b[2][2];
                    #pragma unroll
                    for (int mt = 0; mt < 2; mt++) {
                        int bse = (warp_m + mt*16 + g) * TF_LD + ks*8 + tg;
                        a[mt][0] = Asu[bse];
                        a[mt][1] = Asu[bse + 8*TF_LD];
                        a[mt][2] = Asu[bse + 4];
                        a[mt][3] = Asu[bse + 8*TF_LD + 4];
                    }
                    #pragma unroll
                    for (int nt = 0; nt < 2; nt++) {
                        int bse = (warp_n + nt*8 + g) * TF_LD + ks*8 + tg;
                        b[nt][0] = Bsu[bse];
                        b[nt][1] = Bsu[bse + 4];
                    }
                    #pragma unroll
                    for (int mt = 0; mt < 2; mt++)
                        #pragma unroll
                        for (int nt = 0; nt < 2; nt++)
                            MMA_TF32(cacc[mt][nt], a[mt], b[nt]);
                }
                if (t + 1 < 32) storeS((t + 1) & 1);
                __syncthreads();
            }

            #pragma unroll
            for (int mt = 0; mt < 2; mt++) {
                int row0 = tm*64 + warp_m + mt*16 + g;
                #pragma unroll
                for (int nt = 0; nt < 2; nt++) {
                    int col = tn*64 + warp_n + nt*8 + tg*2;
                    float2 bb2 = *(const float2*)&bb[col];
                    float2 o0, o1;
                    o0.x = cacc[mt][nt][0] + bb2.x;  o0.y = cacc[mt][nt][1] + bb2.y;
                    o1.x = cacc[mt][nt][2] + bb2.x;  o1.y = cacc[mt][nt][3] + bb2.y;
                    *(float2*)&kv[(size_t)row0 * 2048 + col]       = o0;
                    *(float2*)&kv[(size_t)(row0 + 8) * 2048 + col] = o1;
                }
            }
        }
        grid_bar(base, ++bar_id);

        // ================= Phase B: attention =================
        {
            float* Ks   = sm;                  // 256 x 64
            float* Vs   = sm + 16384;          // 256 x 64
            float* mbuf = sm + 32768;
            float* lbuf = mbuf + 256;

            const float* Kp = kv + h * DH;
            const float* Vp = kv + 1024 + h * DH;
            for (int idx = tid; idx < 256 * 16; idx += 256) {
                int r  = idx >> 4;
                int c4 = idx & 15;
                *(float4*)(Ks + r*64 + c4*4) = __ldcg((const float4*)(Kp + (size_t)r*2048 + c4*4));
                *(float4*)(Vs + r*64 + c4*4) = __ldcg((const float4*)(Vp + (size_t)r*2048 + c4*4));
            }
            __syncthreads();

            const float* Qr = q2 + (size_t)i * KW * ODIM + (size_t)(qt*32 + q) * 1024 + h * DH;
            ull qp[32];
            #pragma unroll
            for (int d4 = 0; d4 < 16; d4++) {
                ulonglong2 v = *(const ulonglong2*)(Qr + d4*4);
                qp[2*d4]   = v.x;
                qp[2*d4+1] = v.y;
            }

            float m = -1e30f, l = 0.f;
            ull accp[32];
            #pragma unroll
            for (int t = 0; t < 32; t++) accp[t] = 0ull;

            const int k0 = ck * 32;
            for (int kk = 0; kk < 32; kk++) {
                const float* Krow = Ks + (k0 + kk) * 64;
                ull s0 = 0ull, s1 = 0ull, s2 = 0ull, s3 = 0ull;
                #pragma unroll
                for (int d4 = 0; d4 < 16; d4 += 2) {
                    ulonglong2 a = *(const ulonglong2*)(Krow + d4*4);
                    ulonglong2 b = *(const ulonglong2*)(Krow + d4*4 + 4);
                    FMA2(s0, qp[2*d4+0], a.x, s0);
                    FMA2(s1, qp[2*d4+1], a.y, s1);
                    FMA2(s2, qp[2*d4+2], b.x, s2);
                    FMA2(s3, qp[2*d4+3], b.y, s3);
                }
                float a0,a1,b0,b1,c0,c1,d0,d1;
                UNPACK2(a0,a1,s0); UNPACK2(b0,b1,s1); UNPACK2(c0,c1,s2); UNPACK2(d0,d1,s3);
                float s = ((a0+a1)+(b0+b1)) + ((c0+c1)+(d0+d1));
                s *= 0.125f;

                if (s > m) {
                    float corr = __expf(m - s);
                    l *= corr;
                    ull cp; PACK2(cp, corr, corr);
                    #pragma unroll
                    for (int t = 0; t < 32; t++) MUL2(accp[t], accp[t], cp);
                    m = s;
                }
                float p = __expf(s - m);
                l += p;
                ull pp; PACK2(pp, p, p);
                const float* Vrow = Vs + (k0 + kk) * 64;
                #pragma unroll
                for (int d4 = 0; d4 < 16; d4 += 2) {
                    ulonglong2 a = *(const ulonglong2*)(Vrow + d4*4);
                    ulonglong2 b = *(const ulonglong2*)(Vrow + d4*4 + 4);
                    FMA2(accp[2*d4+0], pp, a.x, accp[2*d4+0]);
                    FMA2(accp[2*d4+1], pp, a.y, accp[2*d4+1]);
                    FMA2(accp[2*d4+2], pp, b.x, accp[2*d4+2]);
                    FMA2(accp[2*d4+3], pp, b.y, accp[2*d4+3]);
                }
            }
            __syncthreads();

            // merge 8 key-chunk partials per query; stride-65 buffer = conflict-free
            float* accbuf = sm;
            mbuf[tid] = m;
            lbuf[tid] = l;
            #pragma unroll
            for (int t = 0; t < 32; t++) {
                float f0, f1;
                UNPACK2(f0, f1, accp[t]);
                accbuf[tid*65 + 2*t]     = f0;
                accbuf[tid*65 + 2*t + 1] = f1;
            }
            __syncthreads();

            float mv[8], ev[8];
            float mg = -1e30f;
            #pragma unroll
            for (int cc = 0; cc < 8; cc++) { mv[cc] = mbuf[cc*32 + q]; mg = fmaxf(mg, mv[cc]); }
            float lg = 0.f;
            #pragma unroll
            for (int cc = 0; cc < 8; cc++) { ev[cc] = __expf(mv[cc] - mg); lg += lbuf[cc*32 + q] * ev[cc]; }
            float inv = 1.f / lg;

            float* Orow = st + (size_t)(qt*32 + q) * 1024 + h * DH;
            #pragma unroll
            for (int j = 0; j < 8; j++) {
                int d = ck*8 + j;
                float o = 0.f;
                #pragma unroll
                for (int cc = 0; cc < 8; cc++)
                    o += accbuf[(cc*32 + q)*65 + d] * ev[cc];
                Orow[d] = o * inv;
            }
        }
        grid_bar(base, ++bar_id);
    }
}

// ---------------- host ----------------
extern "C" void kernel_launch(void* const* d_in, const int* in_sizes, int n_in,
                              void* d_out, int out_size)
{
    const float* path   = (const float*)d_in[0];
    const float* w_in1  = (const float*)d_in[1];
    const float* b_in1  = (const float*)d_in[2];
    const float* w_out1 = (const float*)d_in[3];
    const float* b_out1 = (const float*)d_in[4];
    const float* w_lin  = (const float*)d_in[5];
    const float* b_lin  = (const float*)d_in[6];
    const float* w_in2  = (const float*)d_in[7];
    const float* b_in2  = (const float*)d_in[8];
    const float* w_out2 = (const float*)d_in[9];
    const float* b_out2 = (const float*)d_in[10];

    float *qkv1, *attn1, *x, *q2, *kv, *st, *wt, *wt2, *wcomb, *bcomb, *wkv, *bkv, *zb;
    cudaGetSymbolAddress((void**)&qkv1,  g_qkv1);
    cudaGetSymbolAddress((void**)&attn1, g_attn1);
    cudaGetSymbolAddress((void**)&x,     g_x);
    cudaGetSymbolAddress((void**)&q2,    g_q2);
    cudaGetSymbolAddress((void**)&kv,    g_kv);
    cudaGetSymbolAddress((void**)&st,    g_st);
    cudaGetSymbolAddress((void**)&wt,    g_wt);
    cudaGetSymbolAddress((void**)&wt2,   g_wt2);
    cudaGetSymbolAddress((void**)&wcomb, g_wcomb);
    cudaGetSymbolAddress((void**)&bcomb, g_bcomb);
    cudaGetSymbolAddress((void**)&wkv,   g_wkv);
    cudaGetSymbolAddress((void**)&bkv,   g_bkv);
    cudaGetSymbolAddress((void**)&zb,    g_zb);

    cudaFuncSetAttribute(attn_kernel,        cudaFuncAttributeMaxDynamicSharedMemorySize, ATTN_SMEM);
    cudaFuncSetAttribute(gemm_tf32<false>,   cudaFuncAttributeMaxDynamicSharedMemorySize, TF_SMEM);
    cudaFuncSetAttribute(gemm_tf32<true>,    cudaFuncAttributeMaxDynamicSharedMemorySize, TF_SMEM);
    cudaFuncSetAttribute(recurrence_kernel,  cudaFuncAttributeMaxDynamicSharedMemorySize, REC_SMEM);

    auto g64  = gemm_bias<64,64,16,4,4>;
    auto t32  = gemm_tf32<false>;
    auto t32r = gemm_tf32<true>;

    const float* wkv2 = w_in2 + (size_t)ODIM * ODIM;
    const float* bkv2 = b_in2 + ODIM;

    // ---- prologue (tf32 weight folds) ----
    zero_kernel<<<(DM+255)/256, 256>>>(zb, DM);                                   // 0
    transpose1024<<<dim3(32,32), dim3(32,8)>>>(w_out1, wt);                       // 1
    transpose1024<<<dim3(32,32), dim3(32,8)>>>(w_out2, wt2);                      // 2
    t32<<<dim3(DM/128, DM/128), 256, TF_SMEM>>>(w_lin, wt, zb, wcomb, DM, DM, DM);       // 3
    t32<<<dim3(DM/128, 2*ODIM/128), 256, TF_SMEM>>>(wkv2, wt2, zb, wkv, 2*ODIM, DM, DM); // 4

    // ---- stage 1: QKV of every path row (tf32; ncu target @ launch 5) ----
    t32<<<dim3(3*DM/128, SEQ/128), 256, TF_SMEM>>>(path, w_in1, b_in1, qkv1, SEQ, 3*DM, DM); // 5

    bias_dot<<<DM/8, 256>>>(w_lin, b_out1, b_lin, bcomb, DM);                     // 6
    bias_dot<<<2*ODIM/8, 256>>>(wkv2, b_out2, bkv2, bkv, DM);                     // 7

    // ---- stage 2: batched window self-attention (exact fp32) ----
    attn_kernel<<<dim3(NH, KW/64, NWIN), 256, ATTN_SMEM>>>(
        qkv1,        (long long)STR * 3*DM, 3*DM,
        qkv1 + DM,   (long long)STR * 3*DM, 3*DM,
        qkv1 + 2*DM, (long long)STR * 3*DM, 3*DM,
        attn1,       (long long)KW * DM,    DM,
        0.125f);

    // ---- stage 3: fused outproj1 + linear + relu (tf32) ----
    t32r<<<dim3(ODIM/128, ROWS/128), 256, TF_SMEM>>>(attn1, wcomb, bcomb, x, ROWS, ODIM, DM);

    // ---- stage 4a: bulk Q2 projections (tf32) ----
    t32<<<dim3(ODIM/128, ROWS/128), 256, TF_SMEM>>>(x, w_in2, b_in2, q2, ROWS, ODIM, ODIM);

    // ---- stage 4b: ONE persistent kernel for all 239 recurrence steps ----
    recurrence_kernel<<<REC_NB, 256, REC_SMEM>>>(x, q2, wkv2, bkv2, wkv, bkv, kv, st);

    // ---- final out-projection (exact fp32 -> d_out) ----
    g64<<<dim3(ODIM/64, KW/64), 256>>>(st, w_out2, b_out2, (float*)d_out, KW, ODIM, ODIM);
}

// round 6
// speedup vs baseline: 3.2716x; 1.0456x over previous
#include <cuda_runtime.h>
#include <math.h>
#include <stdint.h>

// ---------------- problem constants ----------------
constexpr int SEQ  = 4096;
constexpr int DM   = 1024;
constexpr int ODIM = 1024;
constexpr int KW   = 256;
constexpr int STR  = 16;
constexpr int NH   = 16;
constexpr int DH   = 64;
constexpr int NWIN = (SEQ - KW) / STR;   // 240
constexpr int ROWS = NWIN * KW;          // 61440

typedef unsigned long long ull;

// packed fp32x2 helpers
#define PACK2(o, lo, hi)   asm("mov.b64 %0, {%1,%2};" : "=l"(o) : "f"(lo), "f"(hi))
#define UNPACK2(lo, hi, i) asm("mov.b64 {%0,%1}, %2;" : "=f"(lo), "=f"(hi) : "l"(i))
#define FMA2(d, a, b, c)   asm("fma.rn.f32x2 %0, %1, %2, %3;" : "=l"(d) : "l"(a), "l"(b), "l"(c))
#define MUL2(d, a, b)      asm("mul.rn.f32x2 %0, %1, %2;" : "=l"(d) : "l"(a), "l"(b))

__device__ __forceinline__ uint32_t f2tf32(float f) {
    uint32_t u; asm("cvt.rna.tf32.f32 %0, %1;" : "=r"(u) : "f"(f)); return u;
}

__device__ __forceinline__ uint32_t smaddr(const void* p) {
    return (uint32_t)__cvta_generic_to_shared(p);
}

#define LDSM4(r0, r1, r2, r3, addr) \
    asm volatile("ldmatrix.sync.aligned.m8n8.x4.shared.b16 {%0,%1,%2,%3}, [%4];" \
        : "=r"(r0), "=r"(r1), "=r"(r2), "=r"(r3) : "r"(addr))

#define MMA_TF32(c, a, b) \
    asm volatile("mma.sync.aligned.m16n8k8.row.col.f32.tf32.tf32.f32 " \
        "{%0,%1,%2,%3},{%4,%5,%6,%7},{%8,%9},{%0,%1,%2,%3};" \
        : "+f"((c)[0]), "+f"((c)[1]), "+f"((c)[2]), "+f"((c)[3]) \
        : "r"((a)[0]), "r"((a)[1]), "r"((a)[2]), "r"((a)[3]), "r"((b)[0]), "r"((b)[1]))

// ---------------- scratch ----------------
__device__ float g_qkv1[SEQ * 3 * DM];
__device__ float g_attn1[ROWS * DM];
__device__ float g_x[ROWS * ODIM];
__device__ float g_q2[ROWS * ODIM];
__device__ float g_kv[KW * 2 * ODIM];
__device__ float g_st[KW * ODIM];
__device__ float g_wt[DM * DM];
__device__ float g_wt2[DM * DM];
__device__ float g_wcomb[DM * DM];
__device__ float g_bcomb[DM];
__device__ float g_wkv[2 * ODIM * DM];
__device__ float g_bkv[2 * ODIM];
__device__ float g_zb[DM];

// persistent-kernel barrier state (monotonic; replay-safe)
__device__ unsigned g_bar_arrive  = 0;
__device__ unsigned g_bar_release = 0;

// ================= TF32 tensor-core GEMM, 128x128 tiles, ldmatrix =================
constexpr int TF_BK = 32;
constexpr int TF_LD = TF_BK + 4;                       // 36 floats (9x16B, odd -> LDSM conflict-free)
constexpr int TF_BUF = (128 + 128) * TF_LD;
constexpr int TF_SMEM = 2 * TF_BUF * (int)sizeof(float);  // 73728 B

template<bool RELU>
__global__ __launch_bounds__(256)
void gemm_tf32(const float* __restrict__ A, const float* __restrict__ W,
               const float* __restrict__ bias, float* __restrict__ C,
               int M, int N, int K)
{
    extern __shared__ float smem[];
    const int tid    = threadIdx.x;
    const int lane   = tid & 31;
    const int warp   = tid >> 5;
    const int warp_m = (warp & 1) * 64;
    const int warp_n = (warp >> 1) * 32;
    const int bm     = blockIdx.y * 128;
    const int bn     = blockIdx.x * 128;

    // ldmatrix per-lane address components
    const int ar = (lane & 7) + ((lane >> 3) & 1) * 8;   // A row within 16
    const int ac = (lane >> 4) * 4;                      // A col half (0/4)
    const int br = (lane & 7) + (lane >> 4) * 8;         // B row within nt-pair (16)
    const int bc = ((lane >> 3) & 1) * 4;                // B col half

    float c[4][4][4];
    #pragma unroll
    for (int i = 0; i < 4; i++)
        #pragma unroll
        for (int j = 0; j < 4; j++)
            #pragma unroll
            for (int r = 0; r < 4; r++) c[i][j][r] = 0.f;

    const int lr = tid >> 3;
    const int lc = tid & 7;

    float4 ra[4], rw[4];
    auto loadG = [&](int t) {
        const size_t ko = (size_t)t * TF_BK + lc * 4;
        #pragma unroll
        for (int i = 0; i < 4; i++) {
            int r = lr + i * 32;
            ra[i] = *(const float4*)&A[(size_t)(bm + r) * K + ko];
            rw[i] = *(const float4*)&W[(size_t)(bn + r) * K + ko];
        }
    };
    auto storeS = [&](int buf) {
        float* As = smem + buf * TF_BUF;
        float* Bs = As + 128 * TF_LD;
        #pragma unroll
        for (int i = 0; i < 4; i++) {
            int r = lr + i * 32;
            uint4 ua = make_uint4(f2tf32(ra[i].x), f2tf32(ra[i].y), f2tf32(ra[i].z), f2tf32(ra[i].w));
            uint4 uw = make_uint4(f2tf32(rw[i].x), f2tf32(rw[i].y), f2tf32(rw[i].z), f2tf32(rw[i].w));
            *(uint4*)&As[r * TF_LD + lc * 4] = ua;
            *(uint4*)&Bs[r * TF_LD + lc * 4] = uw;
        }
    };

    const int nk = K / TF_BK;
    loadG(0);
    storeS(0);
    __syncthreads();

    for (int t = 0; t < nk; t++) {
        if (t + 1 < nk) loadG(t + 1);

        const float* bufp = smem + (t & 1) * TF_BUF;
        const uint32_t a_base = smaddr(bufp + (warp_m + ar) * TF_LD + ac);
        const uint32_t b_base = smaddr(bufp + 128 * TF_LD + (warp_n + br) * TF_LD + bc);

        #pragma unroll
        for (int ks = 0; ks < 4; ks++) {
            uint32_t a[4][4], b[4][2];
            #pragma unroll
            for (int mt = 0; mt < 4; mt++)
                LDSM4(a[mt][0], a[mt][1], a[mt][2], a[mt][3],
                      a_base + (uint32_t)((mt * 16 * TF_LD + ks * 8) * 4));
            #pragma unroll
            for (int np = 0; np < 2; np++)
                LDSM4(b[2*np][0], b[2*np][1], b[2*np+1][0], b[2*np+1][1],
                      b_base + (uint32_t)((np * 16 * TF_LD + ks * 8) * 4));
            #pragma unroll
            for (int mt = 0; mt < 4; mt++)
                #pragma unroll
                for (int nt = 0; nt < 4; nt++)
                    MMA_TF32(c[mt][nt], a[mt], b[nt]);
        }

        if (t + 1 < nk) storeS((t + 1) & 1);
        __syncthreads();
    }

    const int g  = lane >> 2;
    const int tg = lane & 3;
    #pragma unroll
    for (int mt = 0; mt < 4; mt++) {
        int row0 = bm + warp_m + mt * 16 + g;
        #pragma unroll
        for (int nt = 0; nt < 4; nt++) {
            int col = bn + warp_n + nt * 8 + tg * 2;
            float2 bb = *(const float2*)&bias[col];
            float2 o0, o1;
            o0.x = c[mt][nt][0] + bb.x;  o0.y = c[mt][nt][1] + bb.y;
            o1.x = c[mt][nt][2] + bb.x;  o1.y = c[mt][nt][3] + bb.y;
            if (RELU) {
                o0.x = fmaxf(o0.x, 0.f); o0.y = fmaxf(o0.y, 0.f);
                o1.x = fmaxf(o1.x, 0.f); o1.y = fmaxf(o1.y, 0.f);
            }
            *(float2*)&C[(size_t)row0 * N + col]       = o0;
            *(float2*)&C[(size_t)(row0 + 8) * N + col] = o1;
        }
    }
}

// ================= exact FFMA2 SGEMM (final projection only) =================
template<int BM, int BN, int BK, int TM, int TN>
__global__ __launch_bounds__((BM/TM)*(BN/TN))
void gemm_bias(const float* __restrict__ A, const float* __restrict__ W,
               const float* __restrict__ bias, float* __restrict__ C,
               int M, int N, int K)
{
    constexpr int THREADS = (BM/TM)*(BN/TN);
    __shared__ __align__(16) float As[BK][BM];
    __shared__ __align__(16) float Bs[BK][BN];
    const int tid  = threadIdx.x;
    const int bm   = blockIdx.y * BM;
    const int bn   = blockIdx.x * BN;
    const int tcol = tid % (BN/TN);
    const int trow = tid / (BN/TN);

    ull acc2[TM][TN/2];
    #pragma unroll
    for (int i = 0; i < TM; i++)
        #pragma unroll
        for (int j = 0; j < TN/2; j++) acc2[i][j] = 0ull;

    constexpr int AF4 = BM * (BK/4);
    constexpr int BF4 = BN * (BK/4);

    for (int k0 = 0; k0 < K; k0 += BK) {
        #pragma unroll
        for (int i = tid; i < AF4; i += THREADS) {
            int r  = i / (BK/4);
            int c4 = i % (BK/4);
            float4 v = *(const float4*)&A[(size_t)(bm + r) * K + k0 + c4*4];
            As[c4*4+0][r] = v.x; As[c4*4+1][r] = v.y;
            As[c4*4+2][r] = v.z; As[c4*4+3][r] = v.w;
        }
        #pragma unroll
        for (int i = tid; i < BF4; i += THREADS) {
            int r  = i / (BK/4);
            int c4 = i % (BK/4);
            float4 v = *(const float4*)&W[(size_t)(bn + r) * K + k0 + c4*4];
            Bs[c4*4+0][r] = v.x; Bs[c4*4+1][r] = v.y;
            Bs[c4*4+2][r] = v.z; Bs[c4*4+3][r] = v.w;
        }
        __syncthreads();

        #pragma unroll
        for (int k = 0; k < BK; k++) {
            float ra[TM];
            #pragma unroll
            for (int i = 0; i < TM; i += 4) {
                float4 v = *(const float4*)&As[k][trow*TM + i];
                ra[i] = v.x; ra[i+1] = v.y; ra[i+2] = v.z; ra[i+3] = v.w;
            }
            ull ras[TM];
            #pragma unroll
            for (int i = 0; i < TM; i++) PACK2(ras[i], ra[i], ra[i]);

            ull rb2[TN/2];
            #pragma unroll
            for (int j4 = 0; j4 < TN/4; j4++) {
                ulonglong2 v = *(const ulonglong2*)&Bs[k][tcol*TN + j4*4];
                rb2[2*j4]   = v.x;
                rb2[2*j4+1] = v.y;
            }
            #pragma unroll
            for (int i = 0; i < TM; i++)
                #pragma unroll
                for (int j = 0; j < TN/2; j++)
                    FMA2(acc2[i][j], ras[i], rb2[j], acc2[i][j]);
        }
        __syncthreads();
    }

    #pragma unroll
    for (int i = 0; i < TM; i++) {
        size_t row = (size_t)(bm + trow*TM + i);
        float oc[TN];
        #pragma unroll
        for (int j = 0; j < TN/2; j++) UNPACK2(oc[2*j], oc[2*j+1], acc2[i][j]);
        #pragma unroll
        for (int j = 0; j < TN; j += 4) {
            int col = bn + tcol*TN + j;
            float4 b4 = *(const float4*)&bias[col];
            float4 o;
            o.x = oc[j+0] + b4.x;
            o.y = oc[j+1] + b4.y;
            o.z = oc[j+2] + b4.z;
            o.w = oc[j+3] + b4.w;
            *(float4*)&C[row * N + col] = o;
        }
    }
}

// ---------------- misc small kernels ----------------
__global__ void transpose1024(const float* __restrict__ in, float* __restrict__ out)
{
    __shared__ float tile[32][33];
    int x = blockIdx.x * 32 + threadIdx.x;
    int y = blockIdx.y * 32 + threadIdx.y;
    #pragma unroll
    for (int j = 0; j < 32; j += 8)
        tile[threadIdx.y + j][threadIdx.x] = in[(size_t)(y + j) * DM + x];
    __syncthreads();
    x = blockIdx.y * 32 + threadIdx.x;
    y = blockIdx.x * 32 + threadIdx.y;
    #pragma unroll
    for (int j = 0; j < 32; j += 8)
        out[(size_t)(y + j) * DM + x] = tile[threadIdx.x][threadIdx.y + j];
}

__global__ void bias_dot(const float* __restrict__ W, const float* __restrict__ b1,
                         const float* __restrict__ b2, float* __restrict__ out, int K)
{
    int n    = blockIdx.x * (blockDim.x / 32) + (threadIdx.x >> 5);
    int lane = threadIdx.x & 31;
    float s = 0.f;
    for (int j = lane; j < K; j += 32) s = fmaf(W[(size_t)n * K + j], b1[j], s);
    #pragma unroll
    for (int o = 16; o; o >>= 1) s += __shfl_xor_sync(0xffffffffu, s, o);
    if (lane == 0) out[n] = s + b2[n];
}

__global__ void zero_kernel(float* p, int n)
{
    int i = blockIdx.x * blockDim.x + threadIdx.x;
    if (i < n) p[i] = 0.f;
}

// ---------------- flash-style attention (stage 2 bulk; packed f32x2) ----------------
constexpr int ATTN_SMEM = (2 * KW * DH + 2 * 256) * (int)sizeof(float); // 133120 B

__global__ __launch_bounds__(256)
void attn_kernel(const float* __restrict__ qbase, long long q_ws, int q_rs,
                 const float* __restrict__ kbase, long long k_ws, int k_rs,
                 const float* __restrict__ vbase, long long v_ws, int v_rs,
                 float* __restrict__ obase,       long long o_ws, int o_rs,
                 float scale)
{
    extern __shared__ float sm[];
    float* Ks   = sm;
    float* Vs   = sm + KW * DH;
    float* mbuf = sm + 2 * KW * DH;
    float* lbuf = mbuf + 256;

    const int h  = blockIdx.x;
    const int qt = blockIdx.y;
    const int w  = blockIdx.z;
    const int tid = threadIdx.x;

    const float* Kp = kbase + (size_t)w * k_ws + h * DH;
    const float* Vp = vbase + (size_t)w * v_ws + h * DH;

    for (int idx = tid; idx < KW * (DH/4); idx += 256) {
        int r  = idx >> 4;
        int c4 = idx & 15;
        *(float4*)(Ks + r * DH + c4*4) = *(const float4*)(Kp + (size_t)r * k_rs + c4*4);
        *(float4*)(Vs + r * DH + c4*4) = *(const float4*)(Vp + (size_t)r * v_rs + c4*4);
    }
    __syncthreads();

    const int q = tid & 63;
    const int c = tid >> 6;
    const int qrow = qt * 64 + q;

    const float* Qr = qbase + (size_t)w * q_ws + (size_t)qrow * q_rs + h * DH;
    ull qp[DH/2];
    #pragma unroll
    for (int d4 = 0; d4 < 16; d4++) {
        ulonglong2 v = *(const ulonglong2*)(Qr + d4*4);
        qp[2*d4]   = v.x;
        qp[2*d4+1] = v.y;
    }

    float m = -1e30f, l = 0.f;
    ull accp[DH/2];
    #pragma unroll
    for (int t = 0; t < DH/2; t++) accp[t] = 0ull;

    const int k0 = c * 64;
    for (int kk = 0; kk < 64; kk++) {
        const float* Krow = Ks + (k0 + kk) * DH;
        ull s0 = 0ull, s1 = 0ull, s2 = 0ull, s3 = 0ull;
        #pragma unroll
        for (int d4 = 0; d4 < 16; d4 += 2) {
            ulonglong2 a = *(const ulonglong2*)(Krow + d4*4);
            ulonglong2 b = *(const ulonglong2*)(Krow + d4*4 + 4);
            FMA2(s0, qp[2*d4+0], a.x, s0);
            FMA2(s1, qp[2*d4+1], a.y, s1);
            FMA2(s2, qp[2*d4+2], b.x, s2);
            FMA2(s3, qp[2*d4+3], b.y, s3);
        }
        float a0,a1,b0,b1,c0,c1,d0,d1;
        UNPACK2(a0,a1,s0); UNPACK2(b0,b1,s1); UNPACK2(c0,c1,s2); UNPACK2(d0,d1,s3);
        float s = ((a0+a1)+(b0+b1)) + ((c0+c1)+(d0+d1));
        s *= scale;

        if (s > m) {
            float corr = __expf(m - s);
            l *= corr;
            ull cp; PACK2(cp, corr, corr);
            #pragma unroll
            for (int t = 0; t < DH/2; t++) MUL2(accp[t], accp[t], cp);
            m = s;
        }
        float p = __expf(s - m);
        l += p;
        ull pp; PACK2(pp, p, p);
        const float* Vrow = Vs + (k0 + kk) * DH;
        #pragma unroll
        for (int d4 = 0; d4 < 16; d4 += 2) {
            ulonglong2 a = *(const ulonglong2*)(Vrow + d4*4);
            ulonglong2 b = *(const ulonglong2*)(Vrow + d4*4 + 4);
            FMA2(accp[2*d4+0], pp, a.x, accp[2*d4+0]);
            FMA2(accp[2*d4+1], pp, a.y, accp[2*d4+1]);
            FMA2(accp[2*d4+2], pp, b.x, accp[2*d4+2]);
            FMA2(accp[2*d4+3], pp, b.y, accp[2*d4+3]);
        }
    }
    __syncthreads();

    float* accbuf = Ks;
    mbuf[tid] = m;
    lbuf[tid] = l;
    #pragma unroll
    for (int d4 = 0; d4 < 16; d4++)
        *(ulonglong2*)(accbuf + (size_t)tid * DH + d4*4) =
            make_ulonglong2(accp[2*d4], accp[2*d4+1]);
    __syncthreads();

    float m0 = mbuf[q], m1 = mbuf[64+q], m2 = mbuf[128+q], m3 = mbuf[192+q];
    float mg = fmaxf(fmaxf(m0, m1), fmaxf(m2, m3));
    float e0 = __expf(m0 - mg), e1 = __expf(m1 - mg);
    float e2 = __expf(m2 - mg), e3 = __expf(m3 - mg);
    float lg = lbuf[q]*e0 + lbuf[64+q]*e1 + lbuf[128+q]*e2 + lbuf[192+q]*e3;
    float inv = 1.f / lg;

    float* Or = obase + (size_t)w * o_ws + (size_t)qrow * o_rs + h * DH;
    #pragma unroll
    for (int d = c*16; d < c*16 + 16; d++) {
        float o = accbuf[(size_t)(0*64+q)*DH + d] * e0
                + accbuf[(size_t)(1*64+q)*DH + d] * e1
                + accbuf[(size_t)(2*64+q)*DH + d] * e2
                + accbuf[(size_t)(3*64+q)*DH + d] * e3;
        Or[d] = o * inv;
    }
}

// ================= persistent recurrence kernel =================
constexpr int REC_NB   = 128;
constexpr int REC_SMEM = (32768 + 512) * (int)sizeof(float);   // 133120 B
constexpr int REC_ABUF = 128 * TF_LD;

__device__ __forceinline__ void grid_bar(unsigned base, unsigned bar_id)
{
    __syncthreads();
    if (threadIdx.x == 0) {
        __threadfence();
        unsigned a = atomicAdd(&g_bar_arrive, 1u);
        if ((a & (REC_NB - 1u)) == (REC_NB - 1u)) {
            atomicAdd(&g_bar_release, 1u);
        } else {
            while (*(volatile unsigned*)&g_bar_release - base < bar_id) __nanosleep(32);
        }
        __threadfence();
    }
    __syncthreads();
}

__global__ __launch_bounds__(256)
void recurrence_kernel(const float* __restrict__ x,
                       const float* __restrict__ q2,
                       const float* __restrict__ wkv2, const float* __restrict__ bkv2,
                       const float* __restrict__ wkvF, const float* __restrict__ bkvF,
                       float* __restrict__ kv, float* __restrict__ st)
{
    extern __shared__ float sm[];
    const int tid = threadIdx.x;
    const int bid = blockIdx.x;

    __shared__ unsigned s_base;
    if (tid == 0) s_base = *(volatile unsigned*)&g_bar_release;
    __syncthreads();
    const unsigned base = s_base;
    unsigned bar_id = 0;

    // phase A ids
    const int lane = tid & 31, warp = tid >> 5;
    const int g = lane >> 2, tg = lane & 3;
    const int warp_m = (warp & 1) * 32;
    const int warp_n = (warp >> 1) * 16;
    const int tm = bid >> 5;
    const int tn = bid & 31;
    const int lr = tid >> 3, lc = tid & 7;

    // ldmatrix address components
    const int ar = (lane & 7) + ((lane >> 3) & 1) * 8;
    const int ac = (lane >> 4) * 4;
    const int br = (lane & 7) + (lane >> 4) * 8;
    const int bc = ((lane >> 3) & 1) * 4;

    // phase B ids
    const int h  = bid >> 3;
    const int qt = bid & 7;
    const int q  = tid & 31;
    const int ck = tid >> 5;

    for (int i = 1; i < NWIN; i++) {
        // ================= Phase A: KV projection =================
        {
            const float* A  = (i == 1) ? x    : st;
            const float* W  = (i == 1) ? wkv2 : wkvF;
            const float* bb = (i == 1) ? bkv2 : bkvF;

            float cacc[2][2][4];
            #pragma unroll
            for (int mt = 0; mt < 2; mt++)
                #pragma unroll
                for (int nt = 0; nt < 2; nt++)
                    #pragma unroll
                    for (int r = 0; r < 4; r++) cacc[mt][nt][r] = 0.f;

            float4 ra[2], rw[2];
            auto loadG = [&](int t) {
                size_t ko = (size_t)t * TF_BK + lc * 4;
                ra[0] = __ldcg((const float4*)&A[(size_t)(tm*64 + lr)      * 1024 + ko]);
                ra[1] = __ldcg((const float4*)&A[(size_t)(tm*64 + lr + 32) * 1024 + ko]);
                rw[0] = *(const float4*)&W[(size_t)(tn*64 + lr)      * 1024 + ko];
                rw[1] = *(const float4*)&W[(size_t)(tn*64 + lr + 32) * 1024 + ko];
            };
            auto storeS = [&](int buf) {
                float* As = sm + buf * REC_ABUF;
                float* Bs = As + 64 * TF_LD;
                uint4 u0 = make_uint4(f2tf32(ra[0].x), f2tf32(ra[0].y), f2tf32(ra[0].z), f2tf32(ra[0].w));
                uint4 u1 = make_uint4(f2tf32(ra[1].x), f2tf32(ra[1].y), f2tf32(ra[1].z), f2tf32(ra[1].w));
                uint4 w0 = make_uint4(f2tf32(rw[0].x), f2tf32(rw[0].y), f2tf32(rw[0].z), f2tf32(rw[0].w));
                uint4 w1 = make_uint4(f2tf32(rw[1].x), f2tf32(rw[1].y), f2tf32(rw[1].z), f2tf32(rw[1].w));
                *(uint4*)&As[lr * TF_LD + lc*4]        = u0;
                *(uint4*)&As[(lr+32) * TF_LD + lc*4]   = u1;
                *(uint4*)&Bs[lr * TF_LD + lc*4]        = w0;
                *(uint4*)&Bs[(lr+32) * TF_LD + lc*4]   = w1;
            };

            loadG(0);
            storeS(0);
            __syncthreads();

            for (int t = 0; t < 32; t++) {
                if (t + 1 < 32) loadG(t + 1);

                const float* bufp = sm + (t & 1) * REC_ABUF;
                const uint32_t a_base = smaddr(bufp + (warp_m + ar) * TF_LD + ac);
                const uint32_t b_base = smaddr(bufp + 64 * TF_LD + (warp_n + br) * TF_LD + bc);

                #pragma unroll
                for (int ks = 0; ks < 4; ks++) {
                    uint32_t a[2][4], b[2][2];
                    #pragma unroll
                    for (int mt = 0; mt < 2; mt++)
                        LDSM4(a[mt][0], a[mt][1], a[mt][2], a[mt][3],
                              a_base + (uint32_t)((mt * 16 * TF_LD + ks * 8) * 4));
                    LDSM4(b[0][0], b[0][1], b[1][0], b[1][1],
                          b_base + (uint32_t)((ks * 8) * 4));
                    #pragma unroll
                    for (int mt = 0; mt < 2; mt++)
                        #pragma unroll
                        for (int nt = 0; nt < 2; nt++)
                            MMA_TF32(cacc[mt][nt], a[mt], b[nt]);
                }
                if (t + 1 < 32) storeS((t + 1) & 1);
                __syncthreads();
            }

            #pragma unroll
            for (int mt = 0; mt < 2; mt++) {
                int row0 = tm*64 + warp_m + mt*16 + g;
                #pragma unroll
                for (int nt = 0; nt < 2; nt++) {
                    int col = tn*64 + warp_n + nt*8 + tg*2;
                    float2 bb2 = *(const float2*)&bb[col];
                    float2 o0, o1;
                    o0.x = cacc[mt][nt][0] + bb2.x;  o0.y = cacc[mt][nt][1] + bb2.y;
                    o1.x = cacc[mt][nt][2] + bb2.x;  o1.y = cacc[mt][nt][3] + bb2.y;
                    *(float2*)&kv[(size_t)row0 * 2048 + col]       = o0;
                    *(float2*)&kv[(size_t)(row0 + 8) * 2048 + col] = o1;
                }
            }
        }
        grid_bar(base, ++bar_id);

        // ================= Phase B: attention =================
        {
            float* Ks   = sm;
            float* Vs   = sm + 16384;
            float* mbuf = sm + 32768;
            float* lbuf = mbuf + 256;

            const float* Kp = kv + h * DH;
            const float* Vp = kv + 1024 + h * DH;
            for (int idx = tid; idx < 256 * 16; idx += 256) {
                int r  = idx >> 4;
                int c4 = idx & 15;
                *(float4*)(Ks + r*64 + c4*4) = __ldcg((const float4*)(Kp + (size_t)r*2048 + c4*4));
                *(float4*)(Vs + r*64 + c4*4) = __ldcg((const float4*)(Vp + (size_t)r*2048 + c4*4));
            }
            __syncthreads();

            const float* Qr = q2 + (size_t)i * KW * ODIM + (size_t)(qt*32 + q) * 1024 + h * DH;
            ull qp[32];
            #pragma unroll
            for (int d4 = 0; d4 < 16; d4++) {
                ulonglong2 v = *(const ulonglong2*)(Qr + d4*4);
                qp[2*d4]   = v.x;
                qp[2*d4+1] = v.y;
            }

            float m = -1e30f, l = 0.f;
            ull accp[32];
            #pragma unroll
            for (int t = 0; t < 32; t++) accp[t] = 0ull;

            const int k0 = ck * 32;
            for (int kk = 0; kk < 32; kk++) {
                const float* Krow = Ks + (k0 + kk) * 64;
                ull s0 = 0ull, s1 = 0ull, s2 = 0ull, s3 = 0ull;
                #pragma unroll
                for (int d4 = 0; d4 < 16; d4 += 2) {
                    ulonglong2 a = *(const ulonglong2*)(Krow + d4*4);
                    ulonglong2 b = *(const ulonglong2*)(Krow + d4*4 + 4);
                    FMA2(s0, qp[2*d4+0], a.x, s0);
                    FMA2(s1, qp[2*d4+1], a.y, s1);
                    FMA2(s2, qp[2*d4+2], b.x, s2);
                    FMA2(s3, qp[2*d4+3], b.y, s3);
                }
                float a0,a1,b0,b1,c0,c1,d0,d1;
                UNPACK2(a0,a1,s0); UNPACK2(b0,b1,s1); UNPACK2(c0,c1,s2); UNPACK2(d0,d1,s3);
                float s = ((a0+a1)+(b0+b1)) + ((c0+c1)+(d0+d1));
                s *= 0.125f;

                if (s > m) {
                    float corr = __expf(m - s);
                    l *= corr;
                    ull cp; PACK2(cp, corr, corr);
                    #pragma unroll
                    for (int t = 0; t < 32; t++) MUL2(accp[t], accp[t], cp);
                    m = s;
                }
                float p = __expf(s - m);
                l += p;
                ull pp; PACK2(pp, p, p);
                const float* Vrow = Vs + (k0 + kk) * 64;
                #pragma unroll
                for (int d4 = 0; d4 < 16; d4 += 2) {
                    ulonglong2 a = *(const ulonglong2*)(Vrow + d4*4);
                    ulonglong2 b = *(const ulonglong2*)(Vrow + d4*4 + 4);
                    FMA2(accp[2*d4+0], pp, a.x, accp[2*d4+0]);
                    FMA2(accp[2*d4+1], pp, a.y, accp[2*d4+1]);
                    FMA2(accp[2*d4+2], pp, b.x, accp[2*d4+2]);
                    FMA2(accp[2*d4+3], pp, b.y, accp[2*d4+3]);
                }
            }
            __syncthreads();

            float* accbuf = sm;
            mbuf[tid] = m;
            lbuf[tid] = l;
            #pragma unroll
            for (int t = 0; t < 32; t++) {
                float f0, f1;
                UNPACK2(f0, f1, accp[t]);
                accbuf[tid*65 + 2*t]     = f0;
                accbuf[tid*65 + 2*t + 1] = f1;
            }
            __syncthreads();

            float mv[8], ev[8];
            float mg = -1e30f;
            #pragma unroll
            for (int cc = 0; cc < 8; cc++) { mv[cc] = mbuf[cc*32 + q]; mg = fmaxf(mg, mv[cc]); }
            float lg = 0.f;
            #pragma unroll
            for (int cc = 0; cc < 8; cc++) { ev[cc] = __expf(mv[cc] - mg); lg += lbuf[cc*32 + q] * ev[cc]; }
            float inv = 1.f / lg;

            float* Orow = st + (size_t)(qt*32 + q) * 1024 + h * DH;
            #pragma unroll
            for (int j = 0; j < 8; j++) {
                int d = ck*8 + j;
                float o = 0.f;
                #pragma unroll
                for (int cc = 0; cc < 8; cc++)
                    o += accbuf[(cc*32 + q)*65 + d] * ev[cc];
                Orow[d] = o * inv;
            }
        }
        grid_bar(base, ++bar_id);
    }
}

// ---------------- host ----------------
extern "C" void kernel_launch(void* const* d_in, const int* in_sizes, int n_in,
                              void* d_out, int out_size)
{
    const float* path   = (const float*)d_in[0];
    const float* w_in1  = (const float*)d_in[1];
    const float* b_in1  = (const float*)d_in[2];
    const float* w_out1 = (const float*)d_in[3];
    const float* b_out1 = (const float*)d_in[4];
    const float* w_lin  = (const float*)d_in[5];
    const float* b_lin  = (const float*)d_in[6];
    const float* w_in2  = (const float*)d_in[7];
    const float* b_in2  = (const float*)d_in[8];
    const float* w_out2 = (const float*)d_in[9];
    const float* b_out2 = (const float*)d_in[10];

    float *qkv1, *attn1, *x, *q2, *kv, *st, *wt, *wt2, *wcomb, *bcomb, *wkv, *bkv, *zb;
    cudaGetSymbolAddress((void**)&qkv1,  g_qkv1);
    cudaGetSymbolAddress((void**)&attn1, g_attn1);
    cudaGetSymbolAddress((void**)&x,     g_x);
    cudaGetSymbolAddress((void**)&q2,    g_q2);
    cudaGetSymbolAddress((void**)&kv,    g_kv);
    cudaGetSymbolAddress((void**)&st,    g_st);
    cudaGetSymbolAddress((void**)&wt,    g_wt);
    cudaGetSymbolAddress((void**)&wt2,   g_wt2);
    cudaGetSymbolAddress((void**)&wcomb, g_wcomb);
    cudaGetSymbolAddress((void**)&bcomb, g_bcomb);
    cudaGetSymbolAddress((void**)&wkv,   g_wkv);
    cudaGetSymbolAddress((void**)&bkv,   g_bkv);
    cudaGetSymbolAddress((void**)&zb,    g_zb);

    cudaFuncSetAttribute(attn_kernel,        cudaFuncAttributeMaxDynamicSharedMemorySize, ATTN_SMEM);
    cudaFuncSetAttribute(gemm_tf32<false>,   cudaFuncAttributeMaxDynamicSharedMemorySize, TF_SMEM);
    cudaFuncSetAttribute(gemm_tf32<true>,    cudaFuncAttributeMaxDynamicSharedMemorySize, TF_SMEM);
    cudaFuncSetAttribute(recurrence_kernel,  cudaFuncAttributeMaxDynamicSharedMemorySize, REC_SMEM);

    auto g64  = gemm_bias<64,64,16,4,4>;
    auto t32  = gemm_tf32<false>;
    auto t32r = gemm_tf32<true>;

    const float* wkv2 = w_in2 + (size_t)ODIM * ODIM;
    const float* bkv2 = b_in2 + ODIM;

    // ---- prologue (tf32 weight folds) ----
    zero_kernel<<<(DM+255)/256, 256>>>(zb, DM);                                   // 0
    transpose1024<<<dim3(32,32), dim3(32,8)>>>(w_out1, wt);                       // 1
    transpose1024<<<dim3(32,32), dim3(32,8)>>>(w_out2, wt2);                      // 2
    t32<<<dim3(DM/128, DM/128), 256, TF_SMEM>>>(w_lin, wt, zb, wcomb, DM, DM, DM);       // 3
    t32<<<dim3(DM/128, 2*ODIM/128), 256, TF_SMEM>>>(wkv2, wt2, zb, wkv, 2*ODIM, DM, DM); // 4

    // ---- stage 1: QKV of every path row (tf32; ncu target @ launch 5) ----
    t32<<<dim3(3*DM/128, SEQ/128), 256, TF_SMEM>>>(path, w_in1, b_in1, qkv1, SEQ, 3*DM, DM); // 5

    bias_dot<<<DM/8, 256>>>(w_lin, b_out1, b_lin, bcomb, DM);                     // 6
    bias_dot<<<2*ODIM/8, 256>>>(wkv2, b_out2, bkv2, bkv, DM);                     // 7

    // ---- stage 2: batched window self-attention (exact fp32) ----
    attn_kernel<<<dim3(NH, KW/64, NWIN), 256, ATTN_SMEM>>>(
        qkv1,        (long long)STR * 3*DM, 3*DM,
        qkv1 + DM,   (long long)STR * 3*DM, 3*DM,
        qkv1 + 2*DM, (long long)STR * 3*DM, 3*DM,
        attn1,       (long long)KW * DM,    DM,
        0.125f);

    // ---- stage 3: fused outproj1 + linear + relu (tf32) ----
    t32r<<<dim3(ODIM/128, ROWS/128), 256, TF_SMEM>>>(attn1, wcomb, bcomb, x, ROWS, ODIM, DM);

    // ---- stage 4a: bulk Q2 projections (tf32) ----
    t32<<<dim3(ODIM/128, ROWS/128), 256, TF_SMEM>>>(x, w_in2, b_in2, q2, ROWS, ODIM, ODIM);

    // ---- stage 4b: ONE persistent kernel for all 239 recurrence steps ----
    recurrence_kernel<<<REC_NB, 256, REC_SMEM>>>(x, q2, wkv2, bkv2, wkv, bkv, kv, st);

    // ---- final out-projection (exact fp32 -> d_out) ----
    g64<<<dim3(ODIM/64, KW/64), 256>>>(st, w_out2, b_out2, (float*)d_out, KW, ODIM, ODIM);
}

// round 7
// speedup vs baseline: 3.4321x; 1.0491x over previous
#include <cuda_runtime.h>
#include <math.h>
#include <stdint.h>

// ---------------- problem constants ----------------
constexpr int SEQ  = 4096;
constexpr int DM   = 1024;
constexpr int ODIM = 1024;
constexpr int KW   = 256;
constexpr int STR  = 16;
constexpr int NH   = 16;
constexpr int DH   = 64;
constexpr int NWIN = (SEQ - KW) / STR;   // 240
constexpr int ROWS = NWIN * KW;          // 61440

typedef unsigned long long ull;

// packed fp32x2 helpers
#define PACK2(o, lo, hi)   asm("mov.b64 %0, {%1,%2};" : "=l"(o) : "f"(lo), "f"(hi))
#define UNPACK2(lo, hi, i) asm("mov.b64 {%0,%1}, %2;" : "=f"(lo), "=f"(hi) : "l"(i))
#define FMA2(d, a, b, c)   asm("fma.rn.f32x2 %0, %1, %2, %3;" : "=l"(d) : "l"(a), "l"(b), "l"(c))
#define MUL2(d, a, b)      asm("mul.rn.f32x2 %0, %1, %2;" : "=l"(d) : "l"(a), "l"(b))

__device__ __forceinline__ uint32_t smaddr(const void* p) {
    return (uint32_t)__cvta_generic_to_shared(p);
}

#define CP_ASYNC16(sm_u32, gptr) \
    asm volatile("cp.async.cg.shared.global [%0], [%1], 16;" :: "r"(sm_u32), "l"(gptr))
#define CP_COMMIT() asm volatile("cp.async.commit_group;")
#define CP_WAIT0()  asm volatile("cp.async.wait_group 0;")

#define LDSM4(r0, r1, r2, r3, addr) \
    asm volatile("ldmatrix.sync.aligned.m8n8.x4.shared.b16 {%0,%1,%2,%3}, [%4];" \
        : "=r"(r0), "=r"(r1), "=r"(r2), "=r"(r3) : "r"(addr))

#define MMA_TF32(c, a, b) \
    asm volatile("mma.sync.aligned.m16n8k8.row.col.f32.tf32.tf32.f32 " \
        "{%0,%1,%2,%3},{%4,%5,%6,%7},{%8,%9},{%0,%1,%2,%3};" \
        : "+f"((c)[0]), "+f"((c)[1]), "+f"((c)[2]), "+f"((c)[3]) \
        : "r"((a)[0]), "r"((a)[1]), "r"((a)[2]), "r"((a)[3]), "r"((b)[0]), "r"((b)[1]))

// ---------------- scratch ----------------
__device__ float g_qkv1[SEQ * 3 * DM];
__device__ float g_attn1[ROWS * DM];
__device__ float g_x[ROWS * ODIM];
__device__ float g_q2[ROWS * ODIM];
__device__ float g_kv[KW * 2 * ODIM];
__device__ float g_st[KW * ODIM];
__device__ float g_wt[DM * DM];
__device__ float g_wt2[DM * DM];
__device__ float g_wcomb[DM * DM];
__device__ float g_bcomb[DM];
__device__ float g_wkv[2 * ODIM * DM];
__device__ float g_bkv[2 * ODIM];
__device__ float g_zb[DM];

// persistent-kernel barrier state (monotonic; replay-safe)
__device__ unsigned g_bar_arrive  = 0;
__device__ unsigned g_bar_release = 0;

// ================= TF32 tensor-core GEMM, 128x128 tiles, cp.async + ldmatrix ======
constexpr int TF_BK = 32;
constexpr int TF_LD = TF_BK + 4;                       // 36 floats
constexpr int TF_BUF = (128 + 128) * TF_LD;
constexpr int TF_SMEM = 2 * TF_BUF * (int)sizeof(float);  // 73728 B (x2 CTAs = 147KB)

template<bool RELU>
__global__ __launch_bounds__(256, 2)
void gemm_tf32(const float* __restrict__ A, const float* __restrict__ W,
               const float* __restrict__ bias, float* __restrict__ C,
               int M, int N, int K)
{
    extern __shared__ float smem[];
    const int tid    = threadIdx.x;
    const int lane   = tid & 31;
    const int warp   = tid >> 5;
    const int warp_m = (warp & 1) * 64;
    const int warp_n = (warp >> 1) * 32;
    const int bm     = blockIdx.y * 128;
    const int bn     = blockIdx.x * 128;

    const int ar = (lane & 7) + ((lane >> 3) & 1) * 8;
    const int ac = (lane >> 4) * 4;
    const int br = (lane & 7) + (lane >> 4) * 8;
    const int bc = ((lane >> 3) & 1) * 4;

    float c[4][4][4];
    #pragma unroll
    for (int i = 0; i < 4; i++)
        #pragma unroll
        for (int j = 0; j < 4; j++)
            #pragma unroll
            for (int r = 0; r < 4; r++) c[i][j][r] = 0.f;

    const int lr = tid >> 3;
    const int lc = tid & 7;

    auto issue = [&](int t) {
        const size_t ko = (size_t)t * TF_BK + lc * 4;
        float* As = smem + (t & 1) * TF_BUF;
        float* Bs = As + 128 * TF_LD;
        #pragma unroll
        for (int i = 0; i < 4; i++) {
            int r = lr + i * 32;
            CP_ASYNC16(smaddr(&As[r * TF_LD + lc * 4]), &A[(size_t)(bm + r) * K + ko]);
            CP_ASYNC16(smaddr(&Bs[r * TF_LD + lc * 4]), &W[(size_t)(bn + r) * K + ko]);
        }
        CP_COMMIT();
    };

    const int nk = K / TF_BK;
    issue(0);

    for (int t = 0; t < nk; t++) {
        CP_WAIT0();
        __syncthreads();
        if (t + 1 < nk) issue(t + 1);

        const float* bufp = smem + (t & 1) * TF_BUF;
        const uint32_t a_base = smaddr(bufp + (warp_m + ar) * TF_LD + ac);
        const uint32_t b_base = smaddr(bufp + 128 * TF_LD + (warp_n + br) * TF_LD + bc);

        #pragma unroll
        for (int ks = 0; ks < 4; ks++) {
            uint32_t a[4][4], b[4][2];
            #pragma unroll
            for (int mt = 0; mt < 4; mt++)
                LDSM4(a[mt][0], a[mt][1], a[mt][2], a[mt][3],
                      a_base + (uint32_t)((mt * 16 * TF_LD + ks * 8) * 4));
            #pragma unroll
            for (int np = 0; np < 2; np++)
                LDSM4(b[2*np][0], b[2*np][1], b[2*np+1][0], b[2*np+1][1],
                      b_base + (uint32_t)((np * 16 * TF_LD + ks * 8) * 4));
            #pragma unroll
            for (int mt = 0; mt < 4; mt++)
                #pragma unroll
                for (int nt = 0; nt < 4; nt++)
                    MMA_TF32(c[mt][nt], a[mt], b[nt]);
        }
        __syncthreads();
    }

    const int g  = lane >> 2;
    const int tg = lane & 3;
    #pragma unroll
    for (int mt = 0; mt < 4; mt++) {
        int row0 = bm + warp_m + mt * 16 + g;
        #pragma unroll
        for (int nt = 0; nt < 4; nt++) {
            int col = bn + warp_n + nt * 8 + tg * 2;
            float2 bb = *(const float2*)&bias[col];
            float2 o0, o1;
            o0.x = c[mt][nt][0] + bb.x;  o0.y = c[mt][nt][1] + bb.y;
            o1.x = c[mt][nt][2] + bb.x;  o1.y = c[mt][nt][3] + bb.y;
            if (RELU) {
                o0.x = fmaxf(o0.x, 0.f); o0.y = fmaxf(o0.y, 0.f);
                o1.x = fmaxf(o1.x, 0.f); o1.y = fmaxf(o1.y, 0.f);
            }
            *(float2*)&C[(size_t)row0 * N + col]       = o0;
            *(float2*)&C[(size_t)(row0 + 8) * N + col] = o1;
        }
    }
}

// ================= exact FFMA2 SGEMM (final projection only) =================
template<int BM, int BN, int BK, int TM, int TN>
__global__ __launch_bounds__((BM/TM)*(BN/TN))
void gemm_bias(const float* __restrict__ A, const float* __restrict__ W,
               const float* __restrict__ bias, float* __restrict__ C,
               int M, int N, int K)
{
    constexpr int THREADS = (BM/TM)*(BN/TN);
    __shared__ __align__(16) float As[BK][BM];
    __shared__ __align__(16) float Bs[BK][BN];
    const int tid  = threadIdx.x;
    const int bm   = blockIdx.y * BM;
    const int bn   = blockIdx.x * BN;
    const int tcol = tid % (BN/TN);
    const int trow = tid / (BN/TN);

    ull acc2[TM][TN/2];
    #pragma unroll
    for (int i = 0; i < TM; i++)
        #pragma unroll
        for (int j = 0; j < TN/2; j++) acc2[i][j] = 0ull;

    constexpr int AF4 = BM * (BK/4);
    constexpr int BF4 = BN * (BK/4);

    for (int k0 = 0; k0 < K; k0 += BK) {
        #pragma unroll
        for (int i = tid; i < AF4; i += THREADS) {
            int r  = i / (BK/4);
            int c4 = i % (BK/4);
            float4 v = *(const float4*)&A[(size_t)(bm + r) * K + k0 + c4*4];
            As[c4*4+0][r] = v.x; As[c4*4+1][r] = v.y;
            As[c4*4+2][r] = v.z; As[c4*4+3][r] = v.w;
        }
        #pragma unroll
        for (int i = tid; i < BF4; i += THREADS) {
            int r  = i / (BK/4);
            int c4 = i % (BK/4);
            float4 v = *(const float4*)&W[(size_t)(bn + r) * K + k0 + c4*4];
            Bs[c4*4+0][r] = v.x; Bs[c4*4+1][r] = v.y;
            Bs[c4*4+2][r] = v.z; Bs[c4*4+3][r] = v.w;
        }
        __syncthreads();

        #pragma unroll
        for (int k = 0; k < BK; k++) {
            float ra[TM];
            #pragma unroll
            for (int i = 0; i < TM; i += 4) {
                float4 v = *(const float4*)&As[k][trow*TM + i];
                ra[i] = v.x; ra[i+1] = v.y; ra[i+2] = v.z; ra[i+3] = v.w;
            }
            ull ras[TM];
            #pragma unroll
            for (int i = 0; i < TM; i++) PACK2(ras[i], ra[i], ra[i]);

            ull rb2[TN/2];
            #pragma unroll
            for (int j4 = 0; j4 < TN/4; j4++) {
                ulonglong2 v = *(const ulonglong2*)&Bs[k][tcol*TN + j4*4];
                rb2[2*j4]   = v.x;
                rb2[2*j4+1] = v.y;
            }
            #pragma unroll
            for (int i = 0; i < TM; i++)
                #pragma unroll
                for (int j = 0; j < TN/2; j++)
                    FMA2(acc2[i][j], ras[i], rb2[j], acc2[i][j]);
        }
        __syncthreads();
    }

    #pragma unroll
    for (int i = 0; i < TM; i++) {
        size_t row = (size_t)(bm + trow*TM + i);
        float oc[TN];
        #pragma unroll
        for (int j = 0; j < TN/2; j++) UNPACK2(oc[2*j], oc[2*j+1], acc2[i][j]);
        #pragma unroll
        for (int j = 0; j < TN; j += 4) {
            int col = bn + tcol*TN + j;
            float4 b4 = *(const float4*)&bias[col];
            float4 o;
            o.x = oc[j+0] + b4.x;
            o.y = oc[j+1] + b4.y;
            o.z = oc[j+2] + b4.z;
            o.w = oc[j+3] + b4.w;
            *(float4*)&C[row * N + col] = o;
        }
    }
}

// ---------------- misc small kernels ----------------
__global__ void transpose1024(const float* __restrict__ in, float* __restrict__ out)
{
    __shared__ float tile[32][33];
    int x = blockIdx.x * 32 + threadIdx.x;
    int y = blockIdx.y * 32 + threadIdx.y;
    #pragma unroll
    for (int j = 0; j < 32; j += 8)
        tile[threadIdx.y + j][threadIdx.x] = in[(size_t)(y + j) * DM + x];
    __syncthreads();
    x = blockIdx.y * 32 + threadIdx.x;
    y = blockIdx.x * 32 + threadIdx.y;
    #pragma unroll
    for (int j = 0; j < 32; j += 8)
        out[(size_t)(y + j) * DM + x] = tile[threadIdx.x][threadIdx.y + j];
}

__global__ void bias_dot(const float* __restrict__ W, const float* __restrict__ b1,
                         const float* __restrict__ b2, float* __restrict__ out, int K)
{
    int n    = blockIdx.x * (blockDim.x / 32) + (threadIdx.x >> 5);
    int lane = threadIdx.x & 31;
    float s = 0.f;
    for (int j = lane; j < K; j += 32) s = fmaf(W[(size_t)n * K + j], b1[j], s);
    #pragma unroll
    for (int o = 16; o; o >>= 1) s += __shfl_xor_sync(0xffffffffu, s, o);
    if (lane == 0) out[n] = s + b2[n];
}

__global__ void zero_kernel(float* p, int n)
{
    int i = blockIdx.x * blockDim.x + threadIdx.x;
    if (i < n) p[i] = 0.f;
}

// ---------------- flash-style attention (stage 2 bulk; packed f32x2) ----------------
constexpr int ATTN_SMEM = (2 * KW * DH + 2 * 256) * (int)sizeof(float); // 133120 B

__global__ __launch_bounds__(256)
void attn_kernel(const float* __restrict__ qbase, long long q_ws, int q_rs,
                 const float* __restrict__ kbase, long long k_ws, int k_rs,
                 const float* __restrict__ vbase, long long v_ws, int v_rs,
                 float* __restrict__ obase,       long long o_ws, int o_rs,
                 float scale)
{
    extern __shared__ float sm[];
    float* Ks   = sm;
    float* Vs   = sm + KW * DH;
    float* mbuf = sm + 2 * KW * DH;
    float* lbuf = mbuf + 256;

    const int h  = blockIdx.x;
    const int qt = blockIdx.y;
    const int w  = blockIdx.z;
    const int tid = threadIdx.x;

    const float* Kp = kbase + (size_t)w * k_ws + h * DH;
    const float* Vp = vbase + (size_t)w * v_ws + h * DH;

    for (int idx = tid; idx < KW * (DH/4); idx += 256) {
        int r  = idx >> 4;
        int c4 = idx & 15;
        CP_ASYNC16(smaddr(Ks + r * DH + c4*4), Kp + (size_t)r * k_rs + c4*4);
        CP_ASYNC16(smaddr(Vs + r * DH + c4*4), Vp + (size_t)r * v_rs + c4*4);
    }
    CP_COMMIT();

    const int q = tid & 63;
    const int c = tid >> 6;
    const int qrow = qt * 64 + q;

    const float* Qr = qbase + (size_t)w * q_ws + (size_t)qrow * q_rs + h * DH;
    ull qp[DH/2];
    #pragma unroll
    for (int d4 = 0; d4 < 16; d4++) {
        ulonglong2 v = *(const ulonglong2*)(Qr + d4*4);
        qp[2*d4]   = v.x;
        qp[2*d4+1] = v.y;
    }

    CP_WAIT0();
    __syncthreads();

    float m = -1e30f, l = 0.f;
    ull accp[DH/2];
    #pragma unroll
    for (int t = 0; t < DH/2; t++) accp[t] = 0ull;

    const int k0 = c * 64;
    for (int kk = 0; kk < 64; kk++) {
        const float* Krow = Ks + (k0 + kk) * DH;
        ull s0 = 0ull, s1 = 0ull, s2 = 0ull, s3 = 0ull;
        #pragma unroll
        for (int d4 = 0; d4 < 16; d4 += 2) {
            ulonglong2 a = *(const ulonglong2*)(Krow + d4*4);
            ulonglong2 b = *(const ulonglong2*)(Krow + d4*4 + 4);
            FMA2(s0, qp[2*d4+0], a.x, s0);
            FMA2(s1, qp[2*d4+1], a.y, s1);
            FMA2(s2, qp[2*d4+2], b.x, s2);
            FMA2(s3, qp[2*d4+3], b.y, s3);
        }
        float a0,a1,b0,b1,c0,c1,d0,d1;
        UNPACK2(a0,a1,s0); UNPACK2(b0,b1,s1); UNPACK2(c0,c1,s2); UNPACK2(d0,d1,s3);
        float s = ((a0+a1)+(b0+b1)) + ((c0+c1)+(d0+d1));
        s *= scale;

        if (s > m) {
            float corr = __expf(m - s);
            l *= corr;
            ull cp; PACK2(cp, corr, corr);
            #pragma unroll
            for (int t = 0; t < DH/2; t++) MUL2(accp[t], accp[t], cp);
            m = s;
        }
        float p = __expf(s - m);
        l += p;
        ull pp; PACK2(pp, p, p);
        const float* Vrow = Vs + (k0 + kk) * DH;
        #pragma unroll
        for (int d4 = 0; d4 < 16; d4 += 2) {
            ulonglong2 a = *(const ulonglong2*)(Vrow + d4*4);
            ulonglong2 b = *(const ulonglong2*)(Vrow + d4*4 + 4);
            FMA2(accp[2*d4+0], pp, a.x, accp[2*d4+0]);
            FMA2(accp[2*d4+1], pp, a.y, accp[2*d4+1]);
            FMA2(accp[2*d4+2], pp, b.x, accp[2*d4+2]);
            FMA2(accp[2*d4+3], pp, b.y, accp[2*d4+3]);
        }
    }
    __syncthreads();

    float* accbuf = Ks;
    mbuf[tid] = m;
    lbuf[tid] = l;
    #pragma unroll
    for (int d4 = 0; d4 < 16; d4++)
        *(ulonglong2*)(accbuf + (size_t)tid * DH + d4*4) =
            make_ulonglong2(accp[2*d4], accp[2*d4+1]);
    __syncthreads();

    float m0 = mbuf[q], m1 = mbuf[64+q], m2 = mbuf[128+q], m3 = mbuf[192+q];
    float mg = fmaxf(fmaxf(m0, m1), fmaxf(m2, m3));
    float e0 = __expf(m0 - mg), e1 = __expf(m1 - mg);
    float e2 = __expf(m2 - mg), e3 = __expf(m3 - mg);
    float lg = lbuf[q]*e0 + lbuf[64+q]*e1 + lbuf[128+q]*e2 + lbuf[192+q]*e3;
    float inv = 1.f / lg;

    float* Or = obase + (size_t)w * o_ws + (size_t)qrow * o_rs + h * DH;
    #pragma unroll
    for (int d = c*16; d < c*16 + 16; d++) {
        float o = accbuf[(size_t)(0*64+q)*DH + d] * e0
                + accbuf[(size_t)(1*64+q)*DH + d] * e1
                + accbuf[(size_t)(2*64+q)*DH + d] * e2
                + accbuf[(size_t)(3*64+q)*DH + d] * e3;
        Or[d] = o * inv;
    }
}

// ================= persistent recurrence kernel =================
constexpr int REC_NB   = 128;
constexpr int REC_SMEM = (32768 + 512) * (int)sizeof(float);   // 133120 B
constexpr int REC_ABUF = 128 * TF_LD;

__device__ __forceinline__ void grid_bar(unsigned base, unsigned bar_id)
{
    __syncthreads();
    if (threadIdx.x == 0) {
        __threadfence();
        unsigned a = atomicAdd(&g_bar_arrive, 1u);
        if ((a & (REC_NB - 1u)) == (REC_NB - 1u)) {
            atomicAdd(&g_bar_release, 1u);
        } else {
            while (*(volatile unsigned*)&g_bar_release - base < bar_id) { }
        }
        __threadfence();
    }
    __syncthreads();
}

__global__ __launch_bounds__(256)
void recurrence_kernel(const float* __restrict__ x,
                       const float* __restrict__ q2,
                       const float* __restrict__ wkv2, const float* __restrict__ bkv2,
                       const float* __restrict__ wkvF, const float* __restrict__ bkvF,
                       float* __restrict__ kv, float* __restrict__ st)
{
    extern __shared__ float sm[];
    const int tid = threadIdx.x;
    const int bid = blockIdx.x;

    __shared__ unsigned s_base;
    if (tid == 0) s_base = *(volatile unsigned*)&g_bar_release;
    __syncthreads();
    const unsigned base = s_base;
    unsigned bar_id = 0;

    const int lane = tid & 31, warp = tid >> 5;
    const int g = lane >> 2, tg = lane & 3;
    const int warp_m = (warp & 1) * 32;
    const int warp_n = (warp >> 1) * 16;
    const int tm = bid >> 5;
    const int tn = bid & 31;
    const int lr = tid >> 3, lc = tid & 7;

    const int ar = (lane & 7) + ((lane >> 3) & 1) * 8;
    const int ac = (lane >> 4) * 4;
    const int br = (lane & 7) + (lane >> 4) * 8;
    const int bc = ((lane >> 3) & 1) * 4;

    const int h  = bid >> 3;
    const int qt = bid & 7;
    const int q  = tid & 31;
    const int ck = tid >> 5;

    for (int i = 1; i < NWIN; i++) {
        // ================= Phase A: KV projection (cp.async 2-stage) =================
        {
            const float* A  = (i == 1) ? x    : st;
            const float* W  = (i == 1) ? wkv2 : wkvF;
            const float* bb = (i == 1) ? bkv2 : bkvF;

            float cacc[2][2][4];
            #pragma unroll
            for (int mt = 0; mt < 2; mt++)
                #pragma unroll
                for (int nt = 0; nt < 2; nt++)
                    #pragma unroll
                    for (int r = 0; r < 4; r++) cacc[mt][nt][r] = 0.f;

            auto issue = [&](int t) {
                size_t ko = (size_t)t * TF_BK + lc * 4;
                float* As = sm + (t & 1) * REC_ABUF;
                float* Bs = As + 64 * TF_LD;
                CP_ASYNC16(smaddr(&As[lr * TF_LD + lc*4]),      &A[(size_t)(tm*64 + lr)      * 1024 + ko]);
                CP_ASYNC16(smaddr(&As[(lr+32) * TF_LD + lc*4]), &A[(size_t)(tm*64 + lr + 32) * 1024 + ko]);
                CP_ASYNC16(smaddr(&Bs[lr * TF_LD + lc*4]),      &W[(size_t)(tn*64 + lr)      * 1024 + ko]);
                CP_ASYNC16(smaddr(&Bs[(lr+32) * TF_LD + lc*4]), &W[(size_t)(tn*64 + lr + 32) * 1024 + ko]);
                CP_COMMIT();
            };

            issue(0);
            for (int t = 0; t < 32; t++) {
                CP_WAIT0();
                __syncthreads();
                if (t + 1 < 32) issue(t + 1);

                const float* bufp = sm + (t & 1) * REC_ABUF;
                const uint32_t a_base = smaddr(bufp + (warp_m + ar) * TF_LD + ac);
                const uint32_t b_base = smaddr(bufp + 64 * TF_LD + (warp_n + br) * TF_LD + bc);

                #pragma unroll
                for (int ks = 0; ks < 4; ks++) {
                    uint32_t a[2][4], b[2][2];
                    #pragma unroll
                    for (int mt = 0; mt < 2; mt++)
                        LDSM4(a[mt][0], a[mt][1], a[mt][2], a[mt][3],
                              a_base + (uint32_t)((mt * 16 * TF_LD + ks * 8) * 4));
                    LDSM4(b[0][0], b[0][1], b[1][0], b[1][1],
                          b_base + (uint32_t)((ks * 8) * 4));
                    #pragma unroll
                    for (int mt = 0; mt < 2; mt++)
                        #pragma unroll
                        for (int nt = 0; nt < 2; nt++)
                            MMA_TF32(cacc[mt][nt], a[mt], b[nt]);
                }
                __syncthreads();
            }

            #pragma unroll
            for (int mt = 0; mt < 2; mt++) {
                int row0 = tm*64 + warp_m + mt*16 + g;
                #pragma unroll
                for (int nt = 0; nt < 2; nt++) {
                    int col = tn*64 + warp_n + nt*8 + tg*2;
                    float2 bb2 = *(const float2*)&bb[col];
                    float2 o0, o1;
                    o0.x = cacc[mt][nt][0] + bb2.x;  o0.y = cacc[mt][nt][1] + bb2.y;
                    o1.x = cacc[mt][nt][2] + bb2.x;  o1.y = cacc[mt][nt][3] + bb2.y;
                    *(float2*)&kv[(size_t)row0 * 2048 + col]       = o0;
                    *(float2*)&kv[(size_t)(row0 + 8) * 2048 + col] = o1;
                }
            }
        }
        grid_bar(base, ++bar_id);

        // ================= Phase B: attention =================
        {
            float* Ks   = sm;
            float* Vs   = sm + 16384;
            float* mbuf = sm + 32768;
            float* lbuf = mbuf + 256;

            const float* Kp = kv + h * DH;
            const float* Vp = kv + 1024 + h * DH;
            for (int idx = tid; idx < 256 * 16; idx += 256) {
                int r  = idx >> 4;
                int c4 = idx & 15;
                CP_ASYNC16(smaddr(Ks + r*64 + c4*4), Kp + (size_t)r*2048 + c4*4);
                CP_ASYNC16(smaddr(Vs + r*64 + c4*4), Vp + (size_t)r*2048 + c4*4);
            }
            CP_COMMIT();

            const float* Qr = q2 + (size_t)i * KW * ODIM + (size_t)(qt*32 + q) * 1024 + h * DH;
            ull qp[32];
            #pragma unroll
            for (int d4 = 0; d4 < 16; d4++) {
                ulonglong2 v = *(const ulonglong2*)(Qr + d4*4);
                qp[2*d4]   = v.x;
                qp[2*d4+1] = v.y;
            }

            CP_WAIT0();
            __syncthreads();

            float m = -1e30f, l = 0.f;
            ull accp[32];
            #pragma unroll
            for (int t = 0; t < 32; t++) accp[t] = 0ull;

            const int k0 = ck * 32;
            for (int kk = 0; kk < 32; kk++) {
                const float* Krow = Ks + (k0 + kk) * 64;
                ull s0 = 0ull, s1 = 0ull, s2 = 0ull, s3 = 0ull;
                #pragma unroll
                for (int d4 = 0; d4 < 16; d4 += 2) {
                    ulonglong2 a = *(const ulonglong2*)(Krow + d4*4);
                    ulonglong2 b = *(const ulonglong2*)(Krow + d4*4 + 4);
                    FMA2(s0, qp[2*d4+0], a.x, s0);
                    FMA2(s1, qp[2*d4+1], a.y, s1);
                    FMA2(s2, qp[2*d4+2], b.x, s2);
                    FMA2(s3, qp[2*d4+3], b.y, s3);
                }
                float a0,a1,b0,b1,c0,c1,d0,d1;
                UNPACK2(a0,a1,s0); UNPACK2(b0,b1,s1); UNPACK2(c0,c1,s2); UNPACK2(d0,d1,s3);
                float s = ((a0+a1)+(b0+b1)) + ((c0+c1)+(d0+d1));
                s *= 0.125f;

                if (s > m) {
                    float corr = __expf(m - s);
                    l *= corr;
                    ull cp; PACK2(cp, corr, corr);
                    #pragma unroll
                    for (int t = 0; t < 32; t++) MUL2(accp[t], accp[t], cp);
                    m = s;
                }
                float p = __expf(s - m);
                l += p;
                ull pp; PACK2(pp, p, p);
                const float* Vrow = Vs + (k0 + kk) * 64;
                #pragma unroll
                for (int d4 = 0; d4 < 16; d4 += 2) {
                    ulonglong2 a = *(const ulonglong2*)(Vrow + d4*4);
                    ulonglong2 b = *(const ulonglong2*)(Vrow + d4*4 + 4);
                    FMA2(accp[2*d4+0], pp, a.x, accp[2*d4+0]);
                    FMA2(accp[2*d4+1], pp, a.y, accp[2*d4+1]);
                    FMA2(accp[2*d4+2], pp, b.x, accp[2*d4+2]);
                    FMA2(accp[2*d4+3], pp, b.y, accp[2*d4+3]);
                }
            }
            __syncthreads();

            float* accbuf = sm;
            mbuf[tid] = m;
            lbuf[tid] = l;
            #pragma unroll
            for (int t = 0; t < 32; t++) {
                float f0, f1;
                UNPACK2(f0, f1, accp[t]);
                accbuf[tid*65 + 2*t]     = f0;
                accbuf[tid*65 + 2*t + 1] = f1;
            }
            __syncthreads();

            float mv[8], ev[8];
            float mg = -1e30f;
            #pragma unroll
            for (int cc = 0; cc < 8; cc++) { mv[cc] = mbuf[cc*32 + q]; mg = fmaxf(mg, mv[cc]); }
            float lg = 0.f;
            #pragma unroll
            for (int cc = 0; cc < 8; cc++) { ev[cc] = __expf(mv[cc] - mg); lg += lbuf[cc*32 + q] * ev[cc]; }
            float inv = 1.f / lg;

            float* Orow = st + (size_t)(qt*32 + q) * 1024 + h * DH;
            #pragma unroll
            for (int j = 0; j < 8; j++) {
                int d = ck*8 + j;
                float o = 0.f;
                #pragma unroll
                for (int cc = 0; cc < 8; cc++)
                    o += accbuf[(cc*32 + q)*65 + d] * ev[cc];
                Orow[d] = o * inv;
            }
        }
        grid_bar(base, ++bar_id);
    }
}

// ---------------- host ----------------
extern "C" void kernel_launch(void* const* d_in, const int* in_sizes, int n_in,
                              void* d_out, int out_size)
{
    const float* path   = (const float*)d_in[0];
    const float* w_in1  = (const float*)d_in[1];
    const float* b_in1  = (const float*)d_in[2];
    const float* w_out1 = (const float*)d_in[3];
    const float* b_out1 = (const float*)d_in[4];
    const float* w_lin  = (const float*)d_in[5];
    const float* b_lin  = (const float*)d_in[6];
    const float* w_in2  = (const float*)d_in[7];
    const float* b_in2  = (const float*)d_in[8];
    const float* w_out2 = (const float*)d_in[9];
    const float* b_out2 = (const float*)d_in[10];

    float *qkv1, *attn1, *x, *q2, *kv, *st, *wt, *wt2, *wcomb, *bcomb, *wkv, *bkv, *zb;
    cudaGetSymbolAddress((void**)&qkv1,  g_qkv1);
    cudaGetSymbolAddress((void**)&attn1, g_attn1);
    cudaGetSymbolAddress((void**)&x,     g_x);
    cudaGetSymbolAddress((void**)&q2,    g_q2);
    cudaGetSymbolAddress((void**)&kv,    g_kv);
    cudaGetSymbolAddress((void**)&st,    g_st);
    cudaGetSymbolAddress((void**)&wt,    g_wt);
    cudaGetSymbolAddress((void**)&wt2,   g_wt2);
    cudaGetSymbolAddress((void**)&wcomb, g_wcomb);
    cudaGetSymbolAddress((void**)&bcomb, g_bcomb);
    cudaGetSymbolAddress((void**)&wkv,   g_wkv);
    cudaGetSymbolAddress((void**)&bkv,   g_bkv);
    cudaGetSymbolAddress((void**)&zb,    g_zb);

    cudaFuncSetAttribute(attn_kernel,        cudaFuncAttributeMaxDynamicSharedMemorySize, ATTN_SMEM);
    cudaFuncSetAttribute(gemm_tf32<false>,   cudaFuncAttributeMaxDynamicSharedMemorySize, TF_SMEM);
    cudaFuncSetAttribute(gemm_tf32<true>,    cudaFuncAttributeMaxDynamicSharedMemorySize, TF_SMEM);
    cudaFuncSetAttribute(recurrence_kernel,  cudaFuncAttributeMaxDynamicSharedMemorySize, REC_SMEM);
    // allow 2 CTAs/SM for the bulk GEMM (147KB of the 228KB carveout)
    cudaFuncSetAttribute(gemm_tf32<false>,   cudaFuncAttributePreferredSharedMemoryCarveout, 100);
    cudaFuncSetAttribute(gemm_tf32<true>,    cudaFuncAttributePreferredSharedMemoryCarveout, 100);

    auto g64  = gemm_bias<64,64,16,4,4>;
    auto t32  = gemm_tf32<false>;
    auto t32r = gemm_tf32<true>;

    const float* wkv2 = w_in2 + (size_t)ODIM * ODIM;
    const float* bkv2 = b_in2 + ODIM;

    // ---- prologue (tf32 weight folds) ----
    zero_kernel<<<(DM+255)/256, 256>>>(zb, DM);                                   // 0
    transpose1024<<<dim3(32,32), dim3(32,8)>>>(w_out1, wt);                       // 1
    transpose1024<<<dim3(32,32), dim3(32,8)>>>(w_out2, wt2);                      // 2
    t32<<<dim3(DM/128, DM/128), 256, TF_SMEM>>>(w_lin, wt, zb, wcomb, DM, DM, DM);       // 3
    t32<<<dim3(DM/128, 2*ODIM/128), 256, TF_SMEM>>>(wkv2, wt2, zb, wkv, 2*ODIM, DM, DM); // 4

    // ---- stage 1: QKV of every path row ----
    t32<<<dim3(3*DM/128, SEQ/128), 256, TF_SMEM>>>(path, w_in1, b_in1, qkv1, SEQ, 3*DM, DM); // 5

    bias_dot<<<DM/8, 256>>>(w_lin, b_out1, b_lin, bcomb, DM);                     // 6
    bias_dot<<<2*ODIM/8, 256>>>(wkv2, b_out2, bkv2, bkv, DM);                     // 7

    // ---- stage 2: batched window self-attention (exact fp32) ----
    attn_kernel<<<dim3(NH, KW/64, NWIN), 256, ATTN_SMEM>>>(
        qkv1,        (long long)STR * 3*DM, 3*DM,
        qkv1 + DM,   (long long)STR * 3*DM, 3*DM,
        qkv1 + 2*DM, (long long)STR * 3*DM, 3*DM,
        attn1,       (long long)KW * DM,    DM,
        0.125f);

    // ---- stage 3: fused outproj1 + linear + relu (tf32) ----
    t32r<<<dim3(ODIM/128, ROWS/128), 256, TF_SMEM>>>(attn1, wcomb, bcomb, x, ROWS, ODIM, DM);

    // ---- stage 4a: bulk Q2 projections (tf32) ----
    t32<<<dim3(ODIM/128, ROWS/128), 256, TF_SMEM>>>(x, w_in2, b_in2, q2, ROWS, ODIM, ODIM);

    // ---- stage 4b: ONE persistent kernel for all 239 recurrence steps ----
    recurrence_kernel<<<REC_NB, 256, REC_SMEM>>>(x, q2, wkv2, bkv2, wkv, bkv, kv, st);

    // ---- final out-projection (exact fp32 -> d_out) ----
    g64<<<dim3(ODIM/64, KW/64), 256>>>(st, w_out2, b_out2, (float*)d_out, KW, ODIM, ODIM);
}

// round 8
// speedup vs baseline: 3.5154x; 1.0243x over previous
#include <cuda_runtime.h>
#include <math.h>
#include <stdint.h>

// ---------------- problem constants ----------------
constexpr int SEQ  = 4096;
constexpr int DM   = 1024;
constexpr int ODIM = 1024;
constexpr int KW   = 256;
constexpr int STR  = 16;
constexpr int NH   = 16;
constexpr int DH   = 64;
constexpr int NWIN = (SEQ - KW) / STR;   // 240
constexpr int ROWS = NWIN * KW;          // 61440

typedef unsigned long long ull;

// packed fp32x2 helpers
#define PACK2(o, lo, hi)   asm("mov.b64 %0, {%1,%2};" : "=l"(o) : "f"(lo), "f"(hi))
#define UNPACK2(lo, hi, i) asm("mov.b64 {%0,%1}, %2;" : "=f"(lo), "=f"(hi) : "l"(i))
#define FMA2(d, a, b, c)   asm("fma.rn.f32x2 %0, %1, %2, %3;" : "=l"(d) : "l"(a), "l"(b), "l"(c))
#define MUL2(d, a, b)      asm("mul.rn.f32x2 %0, %1, %2;" : "=l"(d) : "l"(a), "l"(b))

__device__ __forceinline__ uint32_t smaddr(const void* p) {
    return (uint32_t)__cvta_generic_to_shared(p);
}

#define CP_ASYNC16(sm_u32, gptr) \
    asm volatile("cp.async.cg.shared.global [%0], [%1], 16;" :: "r"(sm_u32), "l"(gptr))
#define CP_COMMIT() asm volatile("cp.async.commit_group;")
#define CP_WAIT0()  asm volatile("cp.async.wait_group 0;")
#define CP_WAIT1()  asm volatile("cp.async.wait_group 1;")

#define LDSM4(r0, r1, r2, r3, addr) \
    asm volatile("ldmatrix.sync.aligned.m8n8.x4.shared.b16 {%0,%1,%2,%3}, [%4];" \
        : "=r"(r0), "=r"(r1), "=r"(r2), "=r"(r3) : "r"(addr))

#define MMA_TF32(c, a, b) \
    asm volatile("mma.sync.aligned.m16n8k8.row.col.f32.tf32.tf32.f32 " \
        "{%0,%1,%2,%3},{%4,%5,%6,%7},{%8,%9},{%0,%1,%2,%3};" \
        : "+f"((c)[0]), "+f"((c)[1]), "+f"((c)[2]), "+f"((c)[3]) \
        : "r"((a)[0]), "r"((a)[1]), "r"((a)[2]), "r"((a)[3]), "r"((b)[0]), "r"((b)[1]))

// ---------------- scratch ----------------
__device__ float g_qkv1[SEQ * 3 * DM];
__device__ float g_attn1[ROWS * DM];
__device__ float g_x[ROWS * ODIM];
__device__ float g_q2[ROWS * ODIM];
__device__ float g_kv[2 * KW * 2 * ODIM];   // double-buffered by step parity
__device__ float g_st[2 * KW * ODIM];       // double-buffered by step parity
__device__ float g_wt[DM * DM];
__device__ float g_wt2[DM * DM];
__device__ float g_wcomb[DM * DM];
__device__ float g_bcomb[DM];
__device__ float g_wkv[2 * ODIM * DM];
__device__ float g_bkv[2 * ODIM];
__device__ float g_zb[DM];

// persistent-kernel sync state (monotonic; replay-safe)
__device__ unsigned g_bar_arrive  = 0;
__device__ unsigned g_bar_release = 0;
__device__ unsigned g_flagA[32];            // per kv column-stripe: +4 per step
__device__ unsigned g_flagB[8];             // per st row-block:     +16 per step

// ================= TF32 tensor-core GEMM, 128x128 tiles, 3-stage cp.async =========
constexpr int TF_BK = 32;
constexpr int TF_LD = TF_BK + 4;                       // 36 floats
constexpr int TF_BUF = (128 + 128) * TF_LD;            // floats per stage
constexpr int TF_SMEM = 3 * TF_BUF * (int)sizeof(float);  // 110592 B

template<bool RELU>
__global__ __launch_bounds__(256, 2)
void gemm_tf32(const float* __restrict__ A, const float* __restrict__ W,
               const float* __restrict__ bias, float* __restrict__ C,
               int M, int N, int K)
{
    extern __shared__ float smem[];
    const int tid    = threadIdx.x;
    const int lane   = tid & 31;
    const int warp   = tid >> 5;
    const int warp_m = (warp & 1) * 64;
    const int warp_n = (warp >> 1) * 32;
    const int bm     = blockIdx.y * 128;
    const int bn     = blockIdx.x * 128;

    const int ar = (lane & 7) + ((lane >> 3) & 1) * 8;
    const int ac = (lane >> 4) * 4;
    const int br = (lane & 7) + (lane >> 4) * 8;
    const int bc = ((lane >> 3) & 1) * 4;

    float c[4][4][4];
    #pragma unroll
    for (int i = 0; i < 4; i++)
        #pragma unroll
        for (int j = 0; j < 4; j++)
            #pragma unroll
            for (int r = 0; r < 4; r++) c[i][j][r] = 0.f;

    const int lr = tid >> 3;
    const int lc = tid & 7;

    auto issue = [&](int t) {
        const size_t ko = (size_t)t * TF_BK + lc * 4;
        float* As = smem + (t % 3) * TF_BUF;
        float* Bs = As + 128 * TF_LD;
        #pragma unroll
        for (int i = 0; i < 4; i++) {
            int r = lr + i * 32;
            CP_ASYNC16(smaddr(&As[r * TF_LD + lc * 4]), &A[(size_t)(bm + r) * K + ko]);
            CP_ASYNC16(smaddr(&Bs[r * TF_LD + lc * 4]), &W[(size_t)(bn + r) * K + ko]);
        }
        CP_COMMIT();
    };

    const int nk = K / TF_BK;
    issue(0);
    if (nk > 1) issue(1);

    for (int t = 0; t < nk; t++) {
        if (t == nk - 1) { CP_WAIT0(); } else { CP_WAIT1(); }
        __syncthreads();
        if (t + 2 < nk) issue(t + 2);

        const float* bufp = smem + (t % 3) * TF_BUF;
        const uint32_t a_base = smaddr(bufp + (warp_m + ar) * TF_LD + ac);
        const uint32_t b_base = smaddr(bufp + 128 * TF_LD + (warp_n + br) * TF_LD + bc);

        #pragma unroll
        for (int ks = 0; ks < 4; ks++) {
            uint32_t a[4][4], b[4][2];
            #pragma unroll
            for (int mt = 0; mt < 4; mt++)
                LDSM4(a[mt][0], a[mt][1], a[mt][2], a[mt][3],
                      a_base + (uint32_t)((mt * 16 * TF_LD + ks * 8) * 4));
            #pragma unroll
            for (int np = 0; np < 2; np++)
                LDSM4(b[2*np][0], b[2*np][1], b[2*np+1][0], b[2*np+1][1],
                      b_base + (uint32_t)((np * 16 * TF_LD + ks * 8) * 4));
            #pragma unroll
            for (int mt = 0; mt < 4; mt++)
                #pragma unroll
                for (int nt = 0; nt < 4; nt++)
                    MMA_TF32(c[mt][nt], a[mt], b[nt]);
        }
    }

    const int g  = lane >> 2;
    const int tg = lane & 3;
    #pragma unroll
    for (int mt = 0; mt < 4; mt++) {
        int row0 = bm + warp_m + mt * 16 + g;
        #pragma unroll
        for (int nt = 0; nt < 4; nt++) {
            int col = bn + warp_n + nt * 8 + tg * 2;
            float2 bb = *(const float2*)&bias[col];
            float2 o0, o1;
            o0.x = c[mt][nt][0] + bb.x;  o0.y = c[mt][nt][1] + bb.y;
            o1.x = c[mt][nt][2] + bb.x;  o1.y = c[mt][nt][3] + bb.y;
            if (RELU) {
                o0.x = fmaxf(o0.x, 0.f); o0.y = fmaxf(o0.y, 0.f);
                o1.x = fmaxf(o1.x, 0.f); o1.y = fmaxf(o1.y, 0.f);
            }
            *(float2*)&C[(size_t)row0 * N + col]       = o0;
            *(float2*)&C[(size_t)(row0 + 8) * N + col] = o1;
        }
    }
}

// ================= exact FFMA2 SGEMM (final projection only) =================
template<int BM, int BN, int BK, int TM, int TN>
__global__ __launch_bounds__((BM/TM)*(BN/TN))
void gemm_bias(const float* __restrict__ A, const float* __restrict__ W,
               const float* __restrict__ bias, float* __restrict__ C,
               int M, int N, int K)
{
    constexpr int THREADS = (BM/TM)*(BN/TN);
    __shared__ __align__(16) float As[BK][BM];
    __shared__ __align__(16) float Bs[BK][BN];
    const int tid  = threadIdx.x;
    const int bm   = blockIdx.y * BM;
    const int bn   = blockIdx.x * BN;
    const int tcol = tid % (BN/TN);
    const int trow = tid / (BN/TN);

    ull acc2[TM][TN/2];
    #pragma unroll
    for (int i = 0; i < TM; i++)
        #pragma unroll
        for (int j = 0; j < TN/2; j++) acc2[i][j] = 0ull;

    constexpr int AF4 = BM * (BK/4);
    constexpr int BF4 = BN * (BK/4);

    for (int k0 = 0; k0 < K; k0 += BK) {
        #pragma unroll
        for (int i = tid; i < AF4; i += THREADS) {
            int r  = i / (BK/4);
            int c4 = i % (BK/4);
            float4 v = *(const float4*)&A[(size_t)(bm + r) * K + k0 + c4*4];
            As[c4*4+0][r] = v.x; As[c4*4+1][r] = v.y;
            As[c4*4+2][r] = v.z; As[c4*4+3][r] = v.w;
        }
        #pragma unroll
        for (int i = tid; i < BF4; i += THREADS) {
            int r  = i / (BK/4);
            int c4 = i % (BK/4);
            float4 v = *(const float4*)&W[(size_t)(bn + r) * K + k0 + c4*4];
            Bs[c4*4+0][r] = v.x; Bs[c4*4+1][r] = v.y;
            Bs[c4*4+2][r] = v.z; Bs[c4*4+3][r] = v.w;
        }
        __syncthreads();

        #pragma unroll
        for (int k = 0; k < BK; k++) {
            float ra[TM];
            #pragma unroll
            for (int i = 0; i < TM; i += 4) {
                float4 v = *(const float4*)&As[k][trow*TM + i];
                ra[i] = v.x; ra[i+1] = v.y; ra[i+2] = v.z; ra[i+3] = v.w;
            }
            ull ras[TM];
            #pragma unroll
            for (int i = 0; i < TM; i++) PACK2(ras[i], ra[i], ra[i]);

            ull rb2[TN/2];
            #pragma unroll
            for (int j4 = 0; j4 < TN/4; j4++) {
                ulonglong2 v = *(const ulonglong2*)&Bs[k][tcol*TN + j4*4];
                rb2[2*j4]   = v.x;
                rb2[2*j4+1] = v.y;
            }
            #pragma unroll
            for (int i = 0; i < TM; i++)
                #pragma unroll
                for (int j = 0; j < TN/2; j++)
                    FMA2(acc2[i][j], ras[i], rb2[j], acc2[i][j]);
        }
        __syncthreads();
    }

    #pragma unroll
    for (int i = 0; i < TM; i++) {
        size_t row = (size_t)(bm + trow*TM + i);
        float oc[TN];
        #pragma unroll
        for (int j = 0; j < TN/2; j++) UNPACK2(oc[2*j], oc[2*j+1], acc2[i][j]);
        #pragma unroll
        for (int j = 0; j < TN; j += 4) {
            int col = bn + tcol*TN + j;
            float4 b4 = *(const float4*)&bias[col];
            float4 o;
            o.x = oc[j+0] + b4.x;
            o.y = oc[j+1] + b4.y;
            o.z = oc[j+2] + b4.z;
            o.w = oc[j+3] + b4.w;
            *(float4*)&C[row * N + col] = o;
        }
    }
}

// ---------------- misc small kernels ----------------
__global__ void transpose1024(const float* __restrict__ in, float* __restrict__ out)
{
    __shared__ float tile[32][33];
    int x = blockIdx.x * 32 + threadIdx.x;
    int y = blockIdx.y * 32 + threadIdx.y;
    #pragma unroll
    for (int j = 0; j < 32; j += 8)
        tile[threadIdx.y + j][threadIdx.x] = in[(size_t)(y + j) * DM + x];
    __syncthreads();
    x = blockIdx.y * 32 + threadIdx.x;
    y = blockIdx.x * 32 + threadIdx.y;
    #pragma unroll
    for (int j = 0; j < 32; j += 8)
        out[(size_t)(y + j) * DM + x] = tile[threadIdx.x][threadIdx.y + j];
}

__global__ void bias_dot(const float* __restrict__ W, const float* __restrict__ b1,
                         const float* __restrict__ b2, float* __restrict__ out, int K)
{
    int n    = blockIdx.x * (blockDim.x / 32) + (threadIdx.x >> 5);
    int lane = threadIdx.x & 31;
    float s = 0.f;
    for (int j = lane; j < K; j += 32) s = fmaf(W[(size_t)n * K + j], b1[j], s);
    #pragma unroll
    for (int o = 16; o; o >>= 1) s += __shfl_xor_sync(0xffffffffu, s, o);
    if (lane == 0) out[n] = s + b2[n];
}

__global__ void zero_kernel(float* p, int n)
{
    int i = blockIdx.x * blockDim.x + threadIdx.x;
    if (i < n) p[i] = 0.f;
}

// ---------------- flash-style attention (stage 2 bulk; packed f32x2) ----------------
constexpr int ATTN_SMEM = (2 * KW * DH + 2 * 256) * (int)sizeof(float); // 133120 B

__global__ __launch_bounds__(256)
void attn_kernel(const float* __restrict__ qbase, long long q_ws, int q_rs,
                 const float* __restrict__ kbase, long long k_ws, int k_rs,
                 const float* __restrict__ vbase, long long v_ws, int v_rs,
                 float* __restrict__ obase,       long long o_ws, int o_rs,
                 float scale)
{
    extern __shared__ float sm[];
    float* Ks   = sm;
    float* Vs   = sm + KW * DH;
    float* mbuf = sm + 2 * KW * DH;
    float* lbuf = mbuf + 256;

    const int h  = blockIdx.x;
    const int qt = blockIdx.y;
    const int w  = blockIdx.z;
    const int tid = threadIdx.x;

    const float* Kp = kbase + (size_t)w * k_ws + h * DH;
    const float* Vp = vbase + (size_t)w * v_ws + h * DH;

    for (int idx = tid; idx < KW * (DH/4); idx += 256) {
        int r  = idx >> 4;
        int c4 = idx & 15;
        CP_ASYNC16(smaddr(Ks + r * DH + c4*4), Kp + (size_t)r * k_rs + c4*4);
        CP_ASYNC16(smaddr(Vs + r * DH + c4*4), Vp + (size_t)r * v_rs + c4*4);
    }
    CP_COMMIT();

    const int q = tid & 63;
    const int c = tid >> 6;
    const int qrow = qt * 64 + q;

    const float* Qr = qbase + (size_t)w * q_ws + (size_t)qrow * q_rs + h * DH;
    ull qp[DH/2];
    #pragma unroll
    for (int d4 = 0; d4 < 16; d4++) {
        ulonglong2 v = *(const ulonglong2*)(Qr + d4*4);
        qp[2*d4]   = v.x;
        qp[2*d4+1] = v.y;
    }

    CP_WAIT0();
    __syncthreads();

    float m = -1e30f, l = 0.f;
    ull accp[DH/2];
    #pragma unroll
    for (int t = 0; t < DH/2; t++) accp[t] = 0ull;

    const int k0 = c * 64;
    for (int kk = 0; kk < 64; kk++) {
        const float* Krow = Ks + (k0 + kk) * DH;
        ull s0 = 0ull, s1 = 0ull, s2 = 0ull, s3 = 0ull;
        #pragma unroll
        for (int d4 = 0; d4 < 16; d4 += 2) {
            ulonglong2 a = *(const ulonglong2*)(Krow + d4*4);
            ulonglong2 b = *(const ulonglong2*)(Krow + d4*4 + 4);
            FMA2(s0, qp[2*d4+0], a.x, s0);
            FMA2(s1, qp[2*d4+1], a.y, s1);
            FMA2(s2, qp[2*d4+2], b.x, s2);
            FMA2(s3, qp[2*d4+3], b.y, s3);
        }
        float a0,a1,b0,b1,c0,c1,d0,d1;
        UNPACK2(a0,a1,s0); UNPACK2(b0,b1,s1); UNPACK2(c0,c1,s2); UNPACK2(d0,d1,s3);
        float s = ((a0+a1)+(b0+b1)) + ((c0+c1)+(d0+d1));
        s *= scale;

        if (s > m) {
            float corr = __expf(m - s);
            l *= corr;
            ull cp; PACK2(cp, corr, corr);
            #pragma unroll
            for (int t = 0; t < DH/2; t++) MUL2(accp[t], accp[t], cp);
            m = s;
        }
        float p = __expf(s - m);
        l += p;
        ull pp; PACK2(pp, p, p);
        const float* Vrow = Vs + (k0 + kk) * DH;
        #pragma unroll
        for (int d4 = 0; d4 < 16; d4 += 2) {
            ulonglong2 a = *(const ulonglong2*)(Vrow + d4*4);
            ulonglong2 b = *(const ulonglong2*)(Vrow + d4*4 + 4);
            FMA2(accp[2*d4+0], pp, a.x, accp[2*d4+0]);
            FMA2(accp[2*d4+1], pp, a.y, accp[2*d4+1]);
            FMA2(accp[2*d4+2], pp, b.x, accp[2*d4+2]);
            FMA2(accp[2*d4+3], pp, b.y, accp[2*d4+3]);
        }
    }
    __syncthreads();

    float* accbuf = Ks;
    mbuf[tid] = m;
    lbuf[tid] = l;
    #pragma unroll
    for (int d4 = 0; d4 < 16; d4++)
        *(ulonglong2*)(accbuf + (size_t)tid * DH + d4*4) =
            make_ulonglong2(accp[2*d4], accp[2*d4+1]);
    __syncthreads();

    float m0 = mbuf[q], m1 = mbuf[64+q], m2 = mbuf[128+q], m3 = mbuf[192+q];
    float mg = fmaxf(fmaxf(m0, m1), fmaxf(m2, m3));
    float e0 = __expf(m0 - mg), e1 = __expf(m1 - mg);
    float e2 = __expf(m2 - mg), e3 = __expf(m3 - mg);
    float lg = lbuf[q]*e0 + lbuf[64+q]*e1 + lbuf[128+q]*e2 + lbuf[192+q]*e3;
    float inv = 1.f / lg;

    float* Or = obase + (size_t)w * o_ws + (size_t)qrow * o_rs + h * DH;
    #pragma unroll
    for (int d = c*16; d < c*16 + 16; d++) {
        float o = accbuf[(size_t)(0*64+q)*DH + d] * e0
                + accbuf[(size_t)(1*64+q)*DH + d] * e1
                + accbuf[(size_t)(2*64+q)*DH + d] * e2
                + accbuf[(size_t)(3*64+q)*DH + d] * e3;
        Or[d] = o * inv;
    }
}

// ================= persistent recurrence kernel (flag-synced) =================
constexpr int REC_NB   = 128;
constexpr int REC_SMEM = (32768 + 512) * (int)sizeof(float);   // 133120 B
constexpr int REC_ABUF = 128 * TF_LD;                          // floats per A-stage

__device__ __forceinline__ void grid_bar(unsigned base, unsigned bar_id)
{
    __syncthreads();
    if (threadIdx.x == 0) {
        __threadfence();
        unsigned a = atomicAdd(&g_bar_arrive, 1u);
        if ((a & (REC_NB - 1u)) == (REC_NB - 1u)) {
            atomicAdd(&g_bar_release, 1u);
        } else {
            while (*(volatile unsigned*)&g_bar_release - base < bar_id) { }
        }
        __threadfence();
    }
    __syncthreads();
}

__global__ __launch_bounds__(256)
void recurrence_kernel(const float* __restrict__ x,
                       const float* __restrict__ q2,
                       const float* __restrict__ wkv2, const float* __restrict__ bkv2,
                       const float* __restrict__ wkvF, const float* __restrict__ bkvF,
                       float* __restrict__ kv, float* __restrict__ st)
{
    extern __shared__ float sm[];
    const int tid = threadIdx.x;
    const int bid = blockIdx.x;

    __shared__ unsigned s_base;
    if (tid == 0) s_base = *(volatile unsigned*)&g_bar_release;
    __syncthreads();
    const unsigned base = s_base;

    // zero flags behind the (replay-safe) global barrier
    if (bid == 0) {
        if (tid < 32)              g_flagA[tid]      = 0;
        else if (tid < 40)         g_flagB[tid - 32] = 0;
    }
    grid_bar(base, 1);

    const int lane = tid & 31, warp = tid >> 5;
    const int g = lane >> 2, tg = lane & 3;
    const int warp_m = (warp & 1) * 32;
    const int warp_n = (warp >> 1) * 16;
    const int tm = bid >> 5;            // 0..3   A: M-tile
    const int tn = bid & 31;            // 0..31  A: N-stripe of kv
    const int lr = tid >> 3, lc = tid & 7;

    const int ar = (lane & 7) + ((lane >> 3) & 1) * 8;
    const int ac = (lane >> 4) * 4;
    const int br = (lane & 7) + (lane >> 4) * 8;
    const int bc = ((lane >> 3) & 1) * 4;

    const int h  = bid >> 3;            // 0..15  B: head
    const int qt = bid & 7;             // 0..7   B: q row-block (32 rows)
    const int q  = tid & 31;
    const int ck = tid >> 5;

    for (int i = 1; i < NWIN; i++) {
        float* kvb        = kv + (size_t)(i & 1) * KW * 2 * ODIM;
        float* stb        = st + (size_t)(i & 1) * KW * ODIM;
        const float* stprev = st + (size_t)((i - 1) & 1) * KW * ODIM;

        // ================= Phase A: KV projection =================
        {
            // wait: st rows of my M-tile ready (16 B-CTAs per row-block)
            if (i > 1 && tid == 0) {
                unsigned tgt = 16u * (unsigned)(i - 1);
                while (*(volatile unsigned*)&g_flagB[2*tm]     < tgt) { }
                while (*(volatile unsigned*)&g_flagB[2*tm + 1] < tgt) { }
            }
            __syncthreads();   // also orders prev-iter smem reads vs new cp.async

            const float* A  = (i == 1) ? x    : stprev;
            const float* W  = (i == 1) ? wkv2 : wkvF;
            const float* bb = (i == 1) ? bkv2 : bkvF;

            float cacc[2][2][4];
            #pragma unroll
            for (int mt = 0; mt < 2; mt++)
                #pragma unroll
                for (int nt = 0; nt < 2; nt++)
                    #pragma unroll
                    for (int r = 0; r < 4; r++) cacc[mt][nt][r] = 0.f;

            auto issue = [&](int t) {
                size_t ko = (size_t)t * TF_BK + lc * 4;
                float* As = sm + (t % 3) * REC_ABUF;
                float* Bs = As + 64 * TF_LD;
                CP_ASYNC16(smaddr(&As[lr * TF_LD + lc*4]),      &A[(size_t)(tm*64 + lr)      * 1024 + ko]);
                CP_ASYNC16(smaddr(&As[(lr+32) * TF_LD + lc*4]), &A[(size_t)(tm*64 + lr + 32) * 1024 + ko]);
                CP_ASYNC16(smaddr(&Bs[lr * TF_LD + lc*4]),      &W[(size_t)(tn*64 + lr)      * 1024 + ko]);
                CP_ASYNC16(smaddr(&Bs[(lr+32) * TF_LD + lc*4]), &W[(size_t)(tn*64 + lr + 32) * 1024 + ko]);
                CP_COMMIT();
            };

            issue(0);
            issue(1);
            for (int t = 0; t < 32; t++) {
                if (t == 31) { CP_WAIT0(); } else { CP_WAIT1(); }
                __syncthreads();
                if (t + 2 < 32) issue(t + 2);

                const float* bufp = sm + (t % 3) * REC_ABUF;
                const uint32_t a_base = smaddr(bufp + (warp_m + ar) * TF_LD + ac);
                const uint32_t b_base = smaddr(bufp + 64 * TF_LD + (warp_n + br) * TF_LD + bc);

                #pragma unroll
                for (int ks = 0; ks < 4; ks++) {
                    uint32_t a[2][4], b[2][2];
                    #pragma unroll
                    for (int mt = 0; mt < 2; mt++)
                        LDSM4(a[mt][0], a[mt][1], a[mt][2], a[mt][3],
                              a_base + (uint32_t)((mt * 16 * TF_LD + ks * 8) * 4));
                    LDSM4(b[0][0], b[0][1], b[1][0], b[1][1],
                          b_base + (uint32_t)((ks * 8) * 4));
                    #pragma unroll
                    for (int mt = 0; mt < 2; mt++)
                        #pragma unroll
                        for (int nt = 0; nt < 2; nt++)
                            MMA_TF32(cacc[mt][nt], a[mt], b[nt]);
                }
            }

            #pragma unroll
            for (int mt = 0; mt < 2; mt++) {
                int row0 = tm*64 + warp_m + mt*16 + g;
                #pragma unroll
                for (int nt = 0; nt < 2; nt++) {
                    int col = tn*64 + warp_n + nt*8 + tg*2;
                    float2 bb2 = *(const float2*)&bb[col];
                    float2 o0, o1;
                    o0.x = cacc[mt][nt][0] + bb2.x;  o0.y = cacc[mt][nt][1] + bb2.y;
                    o1.x = cacc[mt][nt][2] + bb2.x;  o1.y = cacc[mt][nt][3] + bb2.y;
                    *(float2*)&kvb[(size_t)row0 * 2048 + col]       = o0;
                    *(float2*)&kvb[(size_t)(row0 + 8) * 2048 + col] = o1;
                }
            }
            __threadfence();
            __syncthreads();
            if (tid == 0) atomicAdd(&g_flagA[tn], 1u);
        }

        // ================= Phase B: attention =================
        {
            // wait: kv stripes for my head ready (4 A-CTAs per stripe)
            if (tid == 0) {
                unsigned tgt = 4u * (unsigned)i;
                while (*(volatile unsigned*)&g_flagA[h]      < tgt) { }
                while (*(volatile unsigned*)&g_flagA[16 + h] < tgt) { }
            }
            __syncthreads();   // also orders phase-A smem reads vs B cp.async

            float* Ks   = sm;
            float* Vs   = sm + 16384;
            float* mbuf = sm + 32768;
            float* lbuf = mbuf + 256;

            const float* Kp = kvb + h * DH;
            const float* Vp = kvb + 1024 + h * DH;
            for (int idx = tid; idx < 256 * 16; idx += 256) {
                int r  = idx >> 4;
                int c4 = idx & 15;
                CP_ASYNC16(smaddr(Ks + r*64 + c4*4), Kp + (size_t)r*2048 + c4*4);
                CP_ASYNC16(smaddr(Vs + r*64 + c4*4), Vp + (size_t)r*2048 + c4*4);
            }
            CP_COMMIT();

            const float* Qr = q2 + (size_t)i * KW * ODIM + (size_t)(qt*32 + q) * 1024 + h * DH;
            ull qp[32];
            #pragma unroll
            for (int d4 = 0; d4 < 16; d4++) {
                ulonglong2 v = *(const ulonglong2*)(Qr + d4*4);
                qp[2*d4]   = v.x;
                qp[2*d4+1] = v.y;
            }

            CP_WAIT0();
            __syncthreads();

            float m = -1e30f, l = 0.f;
            ull accp[32];
            #pragma unroll
            for (int t = 0; t < 32; t++) accp[t] = 0ull;

            const int k0 = ck * 32;
            for (int kk = 0; kk < 32; kk++) {
                const float* Krow = Ks + (k0 + kk) * 64;
                ull s0 = 0ull, s1 = 0ull, s2 = 0ull, s3 = 0ull;
                #pragma unroll
                for (int d4 = 0; d4 < 16; d4 += 2) {
                    ulonglong2 a = *(const ulonglong2*)(Krow + d4*4);
                    ulonglong2 b = *(const ulonglong2*)(Krow + d4*4 + 4);
                    FMA2(s0, qp[2*d4+0], a.x, s0);
                    FMA2(s1, qp[2*d4+1], a.y, s1);
                    FMA2(s2, qp[2*d4+2], b.x, s2);
                    FMA2(s3, qp[2*d4+3], b.y, s3);
                }
                float a0,a1,b0,b1,c0,c1,d0,d1;
                UNPACK2(a0,a1,s0); UNPACK2(b0,b1,s1); UNPACK2(c0,c1,s2); UNPACK2(d0,d1,s3);
                float s = ((a0+a1)+(b0+b1)) + ((c0+c1)+(d0+d1));
                s *= 0.125f;

                if (s > m) {
                    float corr = __expf(m - s);
                    l *= corr;
                    ull cp; PACK2(cp, corr, corr);
                    #pragma unroll
                    for (int t = 0; t < 32; t++) MUL2(accp[t], accp[t], cp);
                    m = s;
                }
                float p = __expf(s - m);
                l += p;
                ull pp; PACK2(pp, p, p);
                const float* Vrow = Vs + (k0 + kk) * 64;
                #pragma unroll
                for (int d4 = 0; d4 < 16; d4 += 2) {
                    ulonglong2 a = *(const ulonglong2*)(Vrow + d4*4);
                    ulonglong2 b = *(const ulonglong2*)(Vrow + d4*4 + 4);
                    FMA2(accp[2*d4+0], pp, a.x, accp[2*d4+0]);
                    FMA2(accp[2*d4+1], pp, a.y, accp[2*d4+1]);
                    FMA2(accp[2*d4+2], pp, b.x, accp[2*d4+2]);
                    FMA2(accp[2*d4+3], pp, b.y, accp[2*d4+3]);
                }
            }
            __syncthreads();

            float* accbuf = sm;
            mbuf[tid] = m;
            lbuf[tid] = l;
            #pragma unroll
            for (int t = 0; t < 32; t++) {
                float f0, f1;
                UNPACK2(f0, f1, accp[t]);
                accbuf[tid*65 + 2*t]     = f0;
                accbuf[tid*65 + 2*t + 1] = f1;
            }
            __syncthreads();

            float mv[8], ev[8];
            float mg = -1e30f;
            #pragma unroll
            for (int cc = 0; cc < 8; cc++) { mv[cc] = mbuf[cc*32 + q]; mg = fmaxf(mg, mv[cc]); }
            float lg = 0.f;
            #pragma unroll
            for (int cc = 0; cc < 8; cc++) { ev[cc] = __expf(mv[cc] - mg); lg += lbuf[cc*32 + q] * ev[cc]; }
            float inv = 1.f / lg;

            float* Orow = stb + (size_t)(qt*32 + q) * 1024 + h * DH;
            #pragma unroll
            for (int j = 0; j < 8; j++) {
                int d = ck*8 + j;
                float o = 0.f;
                #pragma unroll
                for (int cc = 0; cc < 8; cc++)
                    o += accbuf[(cc*32 + q)*65 + d] * ev[cc];
                Orow[d] = o * inv;
            }
            __threadfence();
            __syncthreads();
            if (tid == 0) atomicAdd(&g_flagB[qt], 1u);
        }
    }
}

// ---------------- host ----------------
extern "C" void kernel_launch(void* const* d_in, const int* in_sizes, int n_in,
                              void* d_out, int out_size)
{
    const float* path   = (const float*)d_in[0];
    const float* w_in1  = (const float*)d_in[1];
    const float* b_in1  = (const float*)d_in[2];
    const float* w_out1 = (const float*)d_in[3];
    const float* b_out1 = (const float*)d_in[4];
    const float* w_lin  = (const float*)d_in[5];
    const float* b_lin  = (const float*)d_in[6];
    const float* w_in2  = (const float*)d_in[7];
    const float* b_in2  = (const float*)d_in[8];
    const float* w_out2 = (const float*)d_in[9];
    const float* b_out2 = (const float*)d_in[10];

    float *qkv1, *attn1, *x, *q2, *kv, *st, *wt, *wt2, *wcomb, *bcomb, *wkv, *bkv, *zb;
    cudaGetSymbolAddress((void**)&qkv1,  g_qkv1);
    cudaGetSymbolAddress((void**)&attn1, g_attn1);
    cudaGetSymbolAddress((void**)&x,     g_x);
    cudaGetSymbolAddress((void**)&q2,    g_q2);
    cudaGetSymbolAddress((void**)&kv,    g_kv);
    cudaGetSymbolAddress((void**)&st,    g_st);
    cudaGetSymbolAddress((void**)&wt,    g_wt);
    cudaGetSymbolAddress((void**)&wt2,   g_wt2);
    cudaGetSymbolAddress((void**)&wcomb, g_wcomb);
    cudaGetSymbolAddress((void**)&bcomb, g_bcomb);
    cudaGetSymbolAddress((void**)&wkv,   g_wkv);
    cudaGetSymbolAddress((void**)&bkv,   g_bkv);
    cudaGetSymbolAddress((void**)&zb,    g_zb);

    cudaFuncSetAttribute(attn_kernel,        cudaFuncAttributeMaxDynamicSharedMemorySize, ATTN_SMEM);
    cudaFuncSetAttribute(gemm_tf32<false>,   cudaFuncAttributeMaxDynamicSharedMemorySize, TF_SMEM);
    cudaFuncSetAttribute(gemm_tf32<true>,    cudaFuncAttributeMaxDynamicSharedMemorySize, TF_SMEM);
    cudaFuncSetAttribute(recurrence_kernel,  cudaFuncAttributeMaxDynamicSharedMemorySize, REC_SMEM);
    cudaFuncSetAttribute(gemm_tf32<false>,   cudaFuncAttributePreferredSharedMemoryCarveout, 100);
    cudaFuncSetAttribute(gemm_tf32<true>,    cudaFuncAttributePreferredSharedMemoryCarveout, 100);

    auto g64  = gemm_bias<64,64,16,4,4>;
    auto t32  = gemm_tf32<false>;
    auto t32r = gemm_tf32<true>;

    const float* wkv2 = w_in2 + (size_t)ODIM * ODIM;
    const float* bkv2 = b_in2 + ODIM;

    // ---- prologue (tf32 weight folds) ----
    zero_kernel<<<(DM+255)/256, 256>>>(zb, DM);                                   // 0
    transpose1024<<<dim3(32,32), dim3(32,8)>>>(w_out1, wt);                       // 1
    transpose1024<<<dim3(32,32), dim3(32,8)>>>(w_out2, wt2);                      // 2
    t32<<<dim3(DM/128, DM/128), 256, TF_SMEM>>>(w_lin, wt, zb, wcomb, DM, DM, DM);       // 3
    t32<<<dim3(DM/128, 2*ODIM/128), 256, TF_SMEM>>>(wkv2, wt2, zb, wkv, 2*ODIM, DM, DM); // 4

    // ---- stage 1: QKV of every path row ----
    t32<<<dim3(3*DM/128, SEQ/128), 256, TF_SMEM>>>(path, w_in1, b_in1, qkv1, SEQ, 3*DM, DM); // 5

    bias_dot<<<DM/8, 256>>>(w_lin, b_out1, b_lin, bcomb, DM);                     // 6
    bias_dot<<<2*ODIM/8, 256>>>(wkv2, b_out2, bkv2, bkv, DM);                     // 7

    // ---- stage 2: batched window self-attention (exact fp32) ----
    attn_kernel<<<dim3(NH, KW/64, NWIN), 256, ATTN_SMEM>>>(
        qkv1,        (long long)STR * 3*DM, 3*DM,
        qkv1 + DM,   (long long)STR * 3*DM, 3*DM,
        qkv1 + 2*DM, (long long)STR * 3*DM, 3*DM,
        attn1,       (long long)KW * DM,    DM,
        0.125f);

    // ---- stage 3: fused outproj1 + linear + relu (tf32) ----
    t32r<<<dim3(ODIM/128, ROWS/128), 256, TF_SMEM>>>(attn1, wcomb, bcomb, x, ROWS, ODIM, DM);

    // ---- stage 4a: bulk Q2 projections (tf32) ----
    t32<<<dim3(ODIM/128, ROWS/128), 256, TF_SMEM>>>(x, w_in2, b_in2, q2, ROWS, ODIM, ODIM);

    // ---- stage 4b: ONE persistent kernel, flag-synced recurrence ----
    recurrence_kernel<<<REC_NB, 256, REC_SMEM>>>(x, q2, wkv2, bkv2, wkv, bkv, kv, st);

    // ---- final out-projection (exact fp32 -> d_out); last step wrote st[1] ----
    g64<<<dim3(ODIM/64, KW/64), 256>>>(st + (size_t)((NWIN-1)&1) * KW * ODIM,
                                       w_out2, b_out2, (float*)d_out, KW, ODIM, ODIM);
}

// round 10
// speedup vs baseline: 3.6486x; 1.0379x over previous
#include <cuda_runtime.h>
#include <math.h>
#include <stdint.h>

// ---------------- problem constants ----------------
constexpr int SEQ  = 4096;
constexpr int DM   = 1024;
constexpr int ODIM = 1024;
constexpr int KW   = 256;
constexpr int STR  = 16;
constexpr int NH   = 16;
constexpr int DH   = 64;
constexpr int NWIN = (SEQ - KW) / STR;   // 240
constexpr int ROWS = NWIN * KW;          // 61440

typedef unsigned long long ull;

// packed fp32x2 helpers
#define PACK2(o, lo, hi)   asm("mov.b64 %0, {%1,%2};" : "=l"(o) : "f"(lo), "f"(hi))
#define UNPACK2(lo, hi, i) asm("mov.b64 {%0,%1}, %2;" : "=f"(lo), "=f"(hi) : "l"(i))
#define FMA2(d, a, b, c)   asm("fma.rn.f32x2 %0, %1, %2, %3;" : "=l"(d) : "l"(a), "l"(b), "l"(c))
#define MUL2(d, a, b)      asm("mul.rn.f32x2 %0, %1, %2;" : "=l"(d) : "l"(a), "l"(b))

__device__ __forceinline__ uint32_t smaddr(const void* p) {
    return (uint32_t)__cvta_generic_to_shared(p);
}

#define CP_ASYNC16(sm_u32, gptr) \
    asm volatile("cp.async.cg.shared.global [%0], [%1], 16;" :: "r"(sm_u32), "l"(gptr))
#define CP_COMMIT() asm volatile("cp.async.commit_group;")
#define CP_WAIT0()  asm volatile("cp.async.wait_group 0;")
#define CP_WAIT1()  asm volatile("cp.async.wait_group 1;")

#define LDSM4(r0, r1, r2, r3, addr) \
    asm volatile("ldmatrix.sync.aligned.m8n8.x4.shared.b16 {%0,%1,%2,%3}, [%4];" \
        : "=r"(r0), "=r"(r1), "=r"(r2), "=r"(r3) : "r"(addr))

#define MMA_TF32(c, a, b) \
    asm volatile("mma.sync.aligned.m16n8k8.row.col.f32.tf32.tf32.f32 " \
        "{%0,%1,%2,%3},{%4,%5,%6,%7},{%8,%9},{%0,%1,%2,%3};" \
        : "+f"((c)[0]), "+f"((c)[1]), "+f"((c)[2]), "+f"((c)[3]) \
        : "r"((a)[0]), "r"((a)[1]), "r"((a)[2]), "r"((a)[3]), "r"((b)[0]), "r"((b)[1]))

// release/acquire flag ops (L2-scope ordering; NO CCTL.IVALL, unlike __threadfence)
__device__ __forceinline__ void flag_release(unsigned* f) {
    unsigned old;
    asm volatile("atom.release.gpu.global.add.u32 %0, [%1], 1;" : "=r"(old) : "l"(f) : "memory");
}
__device__ __forceinline__ unsigned flag_acquire(unsigned* f) {
    unsigned v;
    asm volatile("ld.acquire.gpu.global.u32 %0, [%1];" : "=r"(v) : "l"(f) : "memory");
    return v;
}

// ---------------- scratch ----------------
__device__ float g_qkv1[SEQ * 3 * DM];
__device__ float g_attn1[ROWS * DM];
__device__ float g_x[ROWS * ODIM];
__device__ float g_q2[ROWS * ODIM];
__device__ float g_kv[2 * KW * 2 * ODIM];   // double-buffered by step parity
__device__ float g_st[2 * KW * ODIM];       // double-buffered by step parity
__device__ float g_wt[DM * DM];
__device__ float g_wt2[DM * DM];
__device__ float g_wcomb[DM * DM];
__device__ float g_bcomb[DM];
__device__ float g_wkv[2 * ODIM * DM];
__device__ float g_bkv[2 * ODIM];
__device__ float g_zb[DM];

// persistent-kernel sync state (monotonic; replay-safe)
__device__ unsigned g_bar_arrive  = 0;
__device__ unsigned g_bar_release = 0;
__device__ unsigned g_flagA[32];            // per kv column-stripe: +4 per step
__device__ unsigned g_flagB[8];             // per st row-block:     +16 per step

// ================= TF32 tensor-core GEMM, 128x128 tiles, 3-stage cp.async =========
constexpr int TF_BK = 32;
constexpr int TF_LD = TF_BK + 4;                       // 36 floats
constexpr int TF_BUF = (128 + 128) * TF_LD;            // floats per stage
constexpr int TF_SMEM = 3 * TF_BUF * (int)sizeof(float);  // 110592 B

template<bool RELU>
__global__ __launch_bounds__(256, 2)
void gemm_tf32(const float* __restrict__ A, const float* __restrict__ W,
               const float* __restrict__ bias, float* __restrict__ C,
               int M, int N, int K)
{
    extern __shared__ float smem[];
    const int tid    = threadIdx.x;
    const int lane   = tid & 31;
    const int warp   = tid >> 5;
    const int warp_m = (warp & 1) * 64;
    const int warp_n = (warp >> 1) * 32;
    const int bm     = blockIdx.y * 128;
    const int bn     = blockIdx.x * 128;

    const int ar = (lane & 7) + ((lane >> 3) & 1) * 8;
    const int ac = (lane >> 4) * 4;
    const int br = (lane & 7) + (lane >> 4) * 8;
    const int bc = ((lane >> 3) & 1) * 4;

    float c[4][4][4];
    #pragma unroll
    for (int i = 0; i < 4; i++)
        #pragma unroll
        for (int j = 0; j < 4; j++)
            #pragma unroll
            for (int r = 0; r < 4; r++) c[i][j][r] = 0.f;

    const int lr = tid >> 3;
    const int lc = tid & 7;

    auto issue = [&](int t) {
        const size_t ko = (size_t)t * TF_BK + lc * 4;
        float* As = smem + (t % 3) * TF_BUF;
        float* Bs = As + 128 * TF_LD;
        #pragma unroll
        for (int i = 0; i < 4; i++) {
            int r = lr + i * 32;
            CP_ASYNC16(smaddr(&As[r * TF_LD + lc * 4]), &A[(size_t)(bm + r) * K + ko]);
            CP_ASYNC16(smaddr(&Bs[r * TF_LD + lc * 4]), &W[(size_t)(bn + r) * K + ko]);
        }
        CP_COMMIT();
    };

    const int nk = K / TF_BK;
    issue(0);
    if (nk > 1) issue(1);

    for (int t = 0; t < nk; t++) {
        if (t == nk - 1) { CP_WAIT0(); } else { CP_WAIT1(); }
        __syncthreads();
        if (t + 2 < nk) issue(t + 2);

        const float* bufp = smem + (t % 3) * TF_BUF;
        const uint32_t a_base = smaddr(bufp + (warp_m + ar) * TF_LD + ac);
        const uint32_t b_base = smaddr(bufp + 128 * TF_LD + (warp_n + br) * TF_LD + bc);

        #pragma unroll
        for (int ks = 0; ks < 4; ks++) {
            uint32_t a[4][4], b[4][2];
            #pragma unroll
            for (int mt = 0; mt < 4; mt++)
                LDSM4(a[mt][0], a[mt][1], a[mt][2], a[mt][3],
                      a_base + (uint32_t)((mt * 16 * TF_LD + ks * 8) * 4));
            #pragma unroll
            for (int np = 0; np < 2; np++)
                LDSM4(b[2*np][0], b[2*np][1], b[2*np+1][0], b[2*np+1][1],
                      b_base + (uint32_t)((np * 16 * TF_LD + ks * 8) * 4));
            #pragma unroll
            for (int mt = 0; mt < 4; mt++)
                #pragma unroll
                for (int nt = 0; nt < 4; nt++)
                    MMA_TF32(c[mt][nt], a[mt], b[nt]);
        }
    }

    const int g  = lane >> 2;
    const int tg = lane & 3;
    #pragma unroll
    for (int mt = 0; mt < 4; mt++) {
        int row0 = bm + warp_m + mt * 16 + g;
        #pragma unroll
        for (int nt = 0; nt < 4; nt++) {
            int col = bn + warp_n + nt * 8 + tg * 2;
            float2 bb = *(const float2*)&bias[col];
            float2 o0, o1;
            o0.x = c[mt][nt][0] + bb.x;  o0.y = c[mt][nt][1] + bb.y;
            o1.x = c[mt][nt][2] + bb.x;  o1.y = c[mt][nt][3] + bb.y;
            if (RELU) {
                o0.x = fmaxf(o0.x, 0.f); o0.y = fmaxf(o0.y, 0.f);
                o1.x = fmaxf(o1.x, 0.f); o1.y = fmaxf(o1.y, 0.f);
            }
            *(float2*)&C[(size_t)row0 * N + col]       = o0;
            *(float2*)&C[(size_t)(row0 + 8) * N + col] = o1;
        }
    }
}

// ================= exact FFMA2 SGEMM (final projection only) =================
template<int BM, int BN, int BK, int TM, int TN>
__global__ __launch_bounds__((BM/TM)*(BN/TN))
void gemm_bias(const float* __restrict__ A, const float* __restrict__ W,
               const float* __restrict__ bias, float* __restrict__ C,
               int M, int N, int K)
{
    constexpr int THREADS = (BM/TM)*(BN/TN);
    __shared__ __align__(16) float As[BK][BM];
    __shared__ __align__(16) float Bs[BK][BN];
    const int tid  = threadIdx.x;
    const int bm   = blockIdx.y * BM;
    const int bn   = blockIdx.x * BN;
    const int tcol = tid % (BN/TN);
    const int trow = tid / (BN/TN);

    ull acc2[TM][TN/2];
    #pragma unroll
    for (int i = 0; i < TM; i++)
        #pragma unroll
        for (int j = 0; j < TN/2; j++) acc2[i][j] = 0ull;

    constexpr int AF4 = BM * (BK/4);
    constexpr int BF4 = BN * (BK/4);

    for (int k0 = 0; k0 < K; k0 += BK) {
        #pragma unroll
        for (int i = tid; i < AF4; i += THREADS) {
            int r  = i / (BK/4);
            int c4 = i % (BK/4);
            float4 v = *(const float4*)&A[(size_t)(bm + r) * K + k0 + c4*4];
            As[c4*4+0][r] = v.x; As[c4*4+1][r] = v.y;
            As[c4*4+2][r] = v.z; As[c4*4+3][r] = v.w;
        }
        #pragma unroll
        for (int i = tid; i < BF4; i += THREADS) {
            int r  = i / (BK/4);
            int c4 = i % (BK/4);
            float4 v = *(const float4*)&W[(size_t)(bn + r) * K + k0 + c4*4];
            Bs[c4*4+0][r] = v.x; Bs[c4*4+1][r] = v.y;
            Bs[c4*4+2][r] = v.z; Bs[c4*4+3][r] = v.w;
        }
        __syncthreads();

        #pragma unroll
        for (int k = 0; k < BK; k++) {
            float ra[TM];
            #pragma unroll
            for (int i = 0; i < TM; i += 4) {
                float4 v = *(const float4*)&As[k][trow*TM + i];
                ra[i] = v.x; ra[i+1] = v.y; ra[i+2] = v.z; ra[i+3] = v.w;
            }
            ull ras[TM];
            #pragma unroll
            for (int i = 0; i < TM; i++) PACK2(ras[i], ra[i], ra[i]);

            ull rb2[TN/2];
            #pragma unroll
            for (int j4 = 0; j4 < TN/4; j4++) {
                ulonglong2 v = *(const ulonglong2*)&Bs[k][tcol*TN + j4*4];
                rb2[2*j4]   = v.x;
                rb2[2*j4+1] = v.y;
            }
            #pragma unroll
            for (int i = 0; i < TM; i++)
                #pragma unroll
                for (int j = 0; j < TN/2; j++)
                    FMA2(acc2[i][j], ras[i], rb2[j], acc2[i][j]);
        }
        __syncthreads();
    }

    #pragma unroll
    for (int i = 0; i < TM; i++) {
        size_t row = (size_t)(bm + trow*TM + i);
        float oc[TN];
        #pragma unroll
        for (int j = 0; j < TN/2; j++) UNPACK2(oc[2*j], oc[2*j+1], acc2[i][j]);
        #pragma unroll
        for (int j = 0; j < TN; j += 4) {
            int col = bn + tcol*TN + j;
            float4 b4 = *(const float4*)&bias[col];
            float4 o;
            o.x = oc[j+0] + b4.x;
            o.y = oc[j+1] + b4.y;
            o.z = oc[j+2] + b4.z;
            o.w = oc[j+3] + b4.w;
            *(float4*)&C[row * N + col] = o;
        }
    }
}

// ---------------- prep: transposes + zero + bias folds in ONE launch ----------------
__global__ __launch_bounds__(256)
void prep_kernel(const float* __restrict__ w_out1, const float* __restrict__ w_out2,
                 const float* __restrict__ w_lin,  const float* __restrict__ b_out1,
                 const float* __restrict__ b_lin,  const float* __restrict__ wkv2,
                 const float* __restrict__ b_out2, const float* __restrict__ bkv2,
                 float* __restrict__ wt, float* __restrict__ wt2, float* __restrict__ zb,
                 float* __restrict__ bcomb, float* __restrict__ bkv)
{
    const int b   = blockIdx.x;
    const int tid = threadIdx.x;

    if (b < 2048) {  // two 1024x1024 transposes
        const float* in = (b < 1024) ? w_out1 : w_out2;
        float* out      = (b < 1024) ? wt : wt2;
        const int bb = b & 1023;
        const int bx = bb & 31, by = bb >> 5;
        __shared__ float tile[32][33];
        const int tx = tid & 31, ty = tid >> 5;   // ty 0..7
        #pragma unroll
        for (int j = 0; j < 32; j += 8)
            tile[ty + j][tx] = in[(size_t)(by*32 + ty + j) * DM + bx*32 + tx];
        __syncthreads();
        #pragma unroll
        for (int j = 0; j < 32; j += 8)
            out[(size_t)(bx*32 + ty + j) * DM + by*32 + tx] = tile[tx][ty + j];
    } else if (b < 2052) {  // zero bias
        zb[(b - 2048) * 256 + tid] = 0.f;
    } else {                // bias folds: out[n] = dot(W[n,:], b1) + b2[n]
        int bb = b - 2052;
        const float *W, *b1, *b2;
        float* out;
        if (bb < 128) { W = w_lin; b1 = b_out1; b2 = b_lin; out = bcomb; }
        else          { bb -= 128; W = wkv2; b1 = b_out2; b2 = bkv2; out = bkv; }
        const int n = bb * 8 + (tid >> 5);
        const int lane = tid & 31;
        float s = 0.f;
        for (int j = lane; j < DM; j += 32) s = fmaf(W[(size_t)n * DM + j], b1[j], s);
        #pragma unroll
        for (int o = 16; o; o >>= 1) s += __shfl_xor_sync(0xffffffffu, s, o);
        if (lane == 0) out[n] = s + b2[n];
    }
}

// ---------------- flash-style attention (stage 2 bulk; packed f32x2) ----------------
constexpr int ATTN_SMEM = (2 * KW * DH + 2 * 256) * (int)sizeof(float); // 133120 B

__global__ __launch_bounds__(256)
void attn_kernel(const float* __restrict__ qbase, long long q_ws, int q_rs,
                 const float* __restrict__ kbase, long long k_ws, int k_rs,
                 const float* __restrict__ vbase, long long v_ws, int v_rs,
                 float* __restrict__ obase,       long long o_ws, int o_rs,
                 float scale)
{
    extern __shared__ float sm[];
    float* Ks   = sm;
    float* Vs   = sm + KW * DH;
    float* mbuf = sm + 2 * KW * DH;
    float* lbuf = mbuf + 256;

    const int h  = blockIdx.x;
    const int qt = blockIdx.y;
    const int w  = blockIdx.z;
    const int tid = threadIdx.x;

    const float* Kp = kbase + (size_t)w * k_ws + h * DH;
    const float* Vp = vbase + (size_t)w * v_ws + h * DH;

    for (int idx = tid; idx < KW * (DH/4); idx += 256) {
        int r  = idx >> 4;
        int c4 = idx & 15;
        CP_ASYNC16(smaddr(Ks + r * DH + c4*4), Kp + (size_t)r * k_rs + c4*4);
        CP_ASYNC16(smaddr(Vs + r * DH + c4*4), Vp + (size_t)r * v_rs + c4*4);
    }
    CP_COMMIT();

    const int q = tid & 63;
    const int c = tid >> 6;
    const int qrow = qt * 64 + q;

    const float* Qr = qbase + (size_t)w * q_ws + (size_t)qrow * q_rs + h * DH;
    ull qp[DH/2];
    #pragma unroll
    for (int d4 = 0; d4 < 16; d4++) {
        ulonglong2 v = *(const ulonglong2*)(Qr + d4*4);
        qp[2*d4]   = v.x;
        qp[2*d4+1] = v.y;
    }

    CP_WAIT0();
    __syncthreads();

    float m = -1e30f, l = 0.f;
    ull accp[DH/2];
    #pragma unroll
    for (int t = 0; t < DH/2; t++) accp[t] = 0ull;

    const int k0 = c * 64;
    for (int kk = 0; kk < 64; kk++) {
        const float* Krow = Ks + (k0 + kk) * DH;
        ull s0 = 0ull, s1 = 0ull, s2 = 0ull, s3 = 0ull;
        #pragma unroll
        for (int d4 = 0; d4 < 16; d4 += 2) {
            ulonglong2 a = *(const ulonglong2*)(Krow + d4*4);
            ulonglong2 b = *(const ulonglong2*)(Krow + d4*4 + 4);
            FMA2(s0, qp[2*d4+0], a.x, s0);
            FMA2(s1, qp[2*d4+1], a.y, s1);
            FMA2(s2, qp[2*d4+2], b.x, s2);
            FMA2(s3, qp[2*d4+3], b.y, s3);
        }
        float a0,a1,b0,b1,c0,c1,d0,d1;
        UNPACK2(a0,a1,s0); UNPACK2(b0,b1,s1); UNPACK2(c0,c1,s2); UNPACK2(d0,d1,s3);
        float s = ((a0+a1)+(b0+b1)) + ((c0+c1)+(d0+d1));
        s *= scale;

        if (s > m) {
            float corr = __expf(m - s);
            l *= corr;
            ull cp; PACK2(cp, corr, corr);
            #pragma unroll
            for (int t = 0; t < DH/2; t++) MUL2(accp[t], accp[t], cp);
            m = s;
        }
        float p = __expf(s - m);
        l += p;
        ull pp; PACK2(pp, p, p);
        const float* Vrow = Vs + (k0 + kk) * DH;
        #pragma unroll
        for (int d4 = 0; d4 < 16; d4 += 2) {
            ulonglong2 a = *(const ulonglong2*)(Vrow + d4*4);
            ulonglong2 b = *(const ulonglong2*)(Vrow + d4*4 + 4);
            FMA2(accp[2*d4+0], pp, a.x, accp[2*d4+0]);
            FMA2(accp[2*d4+1], pp, a.y, accp[2*d4+1]);
            FMA2(accp[2*d4+2], pp, b.x, accp[2*d4+2]);
            FMA2(accp[2*d4+3], pp, b.y, accp[2*d4+3]);
        }
    }
    __syncthreads();

    float* accbuf = Ks;
    mbuf[tid] = m;
    lbuf[tid] = l;
    #pragma unroll
    for (int d4 = 0; d4 < 16; d4++)
        *(ulonglong2*)(accbuf + (size_t)tid * DH + d4*4) =
            make_ulonglong2(accp[2*d4], accp[2*d4+1]);
    __syncthreads();

    float m0 = mbuf[q], m1 = mbuf[64+q], m2 = mbuf[128+q], m3 = mbuf[192+q];
    float mg = fmaxf(fmaxf(m0, m1), fmaxf(m2, m3));
    float e0 = __expf(m0 - mg), e1 = __expf(m1 - mg);
    float e2 = __expf(m2 - mg), e3 = __expf(m3 - mg);
    float lg = lbuf[q]*e0 + lbuf[64+q]*e1 + lbuf[128+q]*e2 + lbuf[192+q]*e3;
    float inv = 1.f / lg;

    float* Or = obase + (size_t)w * o_ws + (size_t)qrow * o_rs + h * DH;
    #pragma unroll
    for (int d = c*16; d < c*16 + 16; d++) {
        float o = accbuf[(size_t)(0*64+q)*DH + d] * e0
                + accbuf[(size_t)(1*64+q)*DH + d] * e1
                + accbuf[(size_t)(2*64+q)*DH + d] * e2
                + accbuf[(size_t)(3*64+q)*DH + d] * e3;
        Or[d] = o * inv;
    }
}

// ================= persistent recurrence kernel (flag-synced, BK=64 phase A) ======
constexpr int REC_NB   = 128;
constexpr int REC_SMEM = (32768 + 512) * (int)sizeof(float);   // 133120 B
constexpr int RA_BK  = 64;
constexpr int RA_LD  = RA_BK + 4;                              // 68 floats
constexpr int RA_BUF = (64 + 64) * RA_LD;                      // 8704 floats per stage

__device__ __forceinline__ void grid_bar(unsigned base, unsigned bar_id)
{
    __syncthreads();
    if (threadIdx.x == 0) {
        __threadfence();
        unsigned a = atomicAdd(&g_bar_arrive, 1u);
        if ((a & (REC_NB - 1u)) == (REC_NB - 1u)) {
            atomicAdd(&g_bar_release, 1u);
        } else {
            while (*(volatile unsigned*)&g_bar_release - base < bar_id) { }
        }
        __threadfence();
    }
    __syncthreads();
}

__global__ __launch_bounds__(256)
void recurrence_kernel(const float* __restrict__ x,
                       const float* __restrict__ q2,
                       const float* __restrict__ wkv2, const float* __restrict__ bkv2,
                       const float* __restrict__ wkvF, const float* __restrict__ bkvF,
                       float* __restrict__ kv, float* __restrict__ st)
{
    extern __shared__ float sm[];
    const int tid = threadIdx.x;
    const int bid = blockIdx.x;

    __shared__ unsigned s_base;
    if (tid == 0) s_base = *(volatile unsigned*)&g_bar_release;
    __syncthreads();
    const unsigned base = s_base;

    // zero flags behind the (replay-safe) global barrier
    if (bid == 0) {
        if (tid < 32)              g_flagA[tid]      = 0;
        else if (tid < 40)         g_flagB[tid - 32] = 0;
    }
    grid_bar(base, 1);

    const int lane = tid & 31, warp = tid >> 5;
    const int g = lane >> 2, tg = lane & 3;
    const int warp_m = (warp & 1) * 32;
    const int warp_n = (warp >> 1) * 16;
    const int tm = bid >> 5;            // 0..3   A: M-tile
    const int tn = bid & 31;            // 0..31  A: N-stripe of kv
    const int lr2 = tid >> 4;           // 0..15  (cp.async row)
    const int lc2 = tid & 15;           // 0..15  (cp.async float4 col)

    const int ar = (lane & 7) + ((lane >> 3) & 1) * 8;
    const int ac = (lane >> 4) * 4;
    const int br = (lane & 7) + (lane >> 4) * 8;
    const int bc = ((lane >> 3) & 1) * 4;

    const int h  = bid >> 3;            // 0..15  B: head
    const int qt = bid & 7;             // 0..7   B: q row-block (32 rows)
    const int q  = tid & 31;
    const int ck = tid >> 5;

    for (int i = 1; i < NWIN; i++) {
        float* kvb          = kv + (size_t)(i & 1) * KW * 2 * ODIM;
        float* stb          = st + (size_t)(i & 1) * KW * ODIM;
        const float* stprev = st + (size_t)((i - 1) & 1) * KW * ODIM;

        // ================= Phase A: KV projection (BK=64, 3-stage) =================
        {
            if (i > 1 && tid == 0) {
                unsigned tgt = 16u * (unsigned)(i - 1);
                while (flag_acquire(&g_flagB[2*tm])     < tgt) { }
                while (flag_acquire(&g_flagB[2*tm + 1]) < tgt) { }
            }
            __syncthreads();

            const float* A  = (i == 1) ? x    : stprev;
            const float* W  = (i == 1) ? wkv2 : wkvF;
            const float* bb = (i == 1) ? bkv2 : bkvF;

            float cacc[2][2][4];
            #pragma unroll
            for (int mt = 0; mt < 2; mt++)
                #pragma unroll
                for (int nt = 0; nt < 2; nt++)
                    #pragma unroll
                    for (int r = 0; r < 4; r++) cacc[mt][nt][r] = 0.f;

            auto issue = [&](int t) {
                size_t ko = (size_t)t * RA_BK + lc2 * 4;
                float* As = sm + (t % 3) * RA_BUF;
                float* Bs = As + 64 * RA_LD;
                #pragma unroll
                for (int p = 0; p < 4; p++) {
                    int r = lr2 + p * 16;
                    CP_ASYNC16(smaddr(&As[r * RA_LD + lc2*4]), &A[(size_t)(tm*64 + r) * 1024 + ko]);
                    CP_ASYNC16(smaddr(&Bs[r * RA_LD + lc2*4]), &W[(size_t)(tn*64 + r) * 1024 + ko]);
                }
                CP_COMMIT();
            };

            issue(0);
            issue(1);
            for (int t = 0; t < 16; t++) {
                if (t == 15) { CP_WAIT0(); } else { CP_WAIT1(); }
                __syncthreads();
                if (t + 2 < 16) issue(t + 2);

                const float* bufp = sm + (t % 3) * RA_BUF;
                const uint32_t a_base = smaddr(bufp + (warp_m + ar) * RA_LD + ac);
                const uint32_t b_base = smaddr(bufp + 64 * RA_LD + (warp_n + br) * RA_LD + bc);

                #pragma unroll
                for (int ks = 0; ks < 8; ks++) {
                    uint32_t a[2][4], b[2][2];
                    #pragma unroll
                    for (int mt = 0; mt < 2; mt++)
                        LDSM4(a[mt][0], a[mt][1], a[mt][2], a[mt][3],
                              a_base + (uint32_t)((mt * 16 * RA_LD + ks * 8) * 4));
                    LDSM4(b[0][0], b[0][1], b[1][0], b[1][1],
                          b_base + (uint32_t)((ks * 8) * 4));
                    #pragma unroll
                    for (int mt = 0; mt < 2; mt++)
                        #pragma unroll
                        for (int nt = 0; nt < 2; nt++)
                            MMA_TF32(cacc[mt][nt], a[mt], b[nt]);
                }
            }

            #pragma unroll
            for (int mt = 0; mt < 2; mt++) {
                int row0 = tm*64 + warp_m + mt*16 + g;
                #pragma unroll
                for (int nt = 0; nt < 2; nt++) {
                    int col = tn*64 + warp_n + nt*8 + tg*2;
                    float2 bb2 = *(const float2*)&bb[col];
                    float2 o0, o1;
                    o0.x = cacc[mt][nt][0] + bb2.x;  o0.y = cacc[mt][nt][1] + bb2.y;
                    o1.x = cacc[mt][nt][2] + bb2.x;  o1.y = cacc[mt][nt][3] + bb2.y;
                    *(float2*)&kvb[(size_t)row0 * 2048 + col]       = o0;
                    *(float2*)&kvb[(size_t)(row0 + 8) * 2048 + col] = o1;
                }
            }
            __syncthreads();
            if (tid == 0) flag_release(&g_flagA[tn]);
        }

        // ================= Phase B: attention =================
        {
            if (tid == 0) {
                unsigned tgt = 4u * (unsigned)i;
                while (flag_acquire(&g_flagA[h])      < tgt) { }
                while (flag_acquire(&g_flagA[16 + h]) < tgt) { }
            }
            __syncthreads();

            float* Ks   = sm;
            float* Vs   = sm + 16384;
            float* mbuf = sm + 32768;
            float* lbuf = mbuf + 256;

            const float* Kp = kvb + h * DH;
            const float* Vp = kvb + 1024 + h * DH;
            for (int idx = tid; idx < 256 * 16; idx += 256) {
                int r  = idx >> 4;
                int c4 = idx & 15;
                CP_ASYNC16(smaddr(Ks + r*64 + c4*4), Kp + (size_t)r*2048 + c4*4);
                CP_ASYNC16(smaddr(Vs + r*64 + c4*4), Vp + (size_t)r*2048 + c4*4);
            }
            CP_COMMIT();

            const float* Qr = q2 + (size_t)i * KW * ODIM + (size_t)(qt*32 + q) * 1024 + h * DH;
            ull qp[32];
            #pragma unroll
            for (int d4 = 0; d4 < 16; d4++) {
                ulonglong2 v = *(const ulonglong2*)(Qr + d4*4);
                qp[2*d4]   = v.x;
                qp[2*d4+1] = v.y;
            }

            CP_WAIT0();
            __syncthreads();

            float m = -1e30f, l = 0.f;
            ull accp[32];
            #pragma unroll
            for (int t = 0; t < 32; t++) accp[t] = 0ull;

            const int k0 = ck * 32;
            for (int kk = 0; kk < 32; kk++) {
                const float* Krow = Ks + (k0 + kk) * 64;
                ull s0 = 0ull, s1 = 0ull, s2 = 0ull, s3 = 0ull;
                #pragma unroll
                for (int d4 = 0; d4 < 16; d4 += 2) {
                    ulonglong2 a = *(const ulonglong2*)(Krow + d4*4);
                    ulonglong2 b = *(const ulonglong2*)(Krow + d4*4 + 4);
                    FMA2(s0, qp[2*d4+0], a.x, s0);
                    FMA2(s1, qp[2*d4+1], a.y, s1);
                    FMA2(s2, qp[2*d4+2], b.x, s2);
                    FMA2(s3, qp[2*d4+3], b.y, s3);
                }
                float a0,a1,b0,b1,c0,c1,d0,d1;
                UNPACK2(a0,a1,s0); UNPACK2(b0,b1,s1); UNPACK2(c0,c1,s2); UNPACK2(d0,d1,s3);
                float s = ((a0+a1)+(b0+b1)) + ((c0+c1)+(d0+d1));
                s *= 0.125f;

                if (s > m) {
                    float corr = __expf(m - s);
                    l *= corr;
                    ull cp; PACK2(cp, corr, corr);
                    #pragma unroll
                    for (int t = 0; t < 32; t++) MUL2(accp[t], accp[t], cp);
                    m = s;
                }
                float p = __expf(s - m);
                l += p;
                ull pp; PACK2(pp, p, p);
                const float* Vrow = Vs + (k0 + kk) * 64;
                #pragma unroll
                for (int d4 = 0; d4 < 16; d4 += 2) {
                    ulonglong2 a = *(const ulonglong2*)(Vrow + d4*4);
                    ulonglong2 b = *(const ulonglong2*)(Vrow + d4*4 + 4);
                    FMA2(accp[2*d4+0], pp, a.x, accp[2*d4+0]);
                    FMA2(accp[2*d4+1], pp, a.y, accp[2*d4+1]);
                    FMA2(accp[2*d4+2], pp, b.x, accp[2*d4+2]);
                    FMA2(accp[2*d4+3], pp, b.y, accp[2*d4+3]);
                }
            }
            __syncthreads();

            float* accbuf = sm;
            mbuf[tid] = m;
            lbuf[tid] = l;
            #pragma unroll
            for (int t = 0; t < 32; t++) {
                float f0, f1;
                UNPACK2(f0, f1, accp[t]);
                accbuf[tid*65 + 2*t]     = f0;
                accbuf[tid*65 + 2*t + 1] = f1;
            }
            __syncthreads();

            float mv[8], ev[8];
            float mg = -1e30f;
            #pragma unroll
            for (int cc = 0; cc < 8; cc++) { mv[cc] = mbuf[cc*32 + q]; mg = fmaxf(mg, mv[cc]); }
            float lg = 0.f;
            #pragma unroll
            for (int cc = 0; cc < 8; cc++) { ev[cc] = __expf(mv[cc] - mg); lg += lbuf[cc*32 + q] * ev[cc]; }
            float inv = 1.f / lg;

            float* Orow = stb + (size_t)(qt*32 + q) * 1024 + h * DH;
            #pragma unroll
            for (int j = 0; j < 8; j++) {
                int d = ck*8 + j;
                float o = 0.f;
                #pragma unroll
                for (int cc = 0; cc < 8; cc++)
                    o += accbuf[(cc*32 + q)*65 + d] * ev[cc];
                Orow[d] = o * inv;
            }
            __syncthreads();
            if (tid == 0) flag_release(&g_flagB[qt]);
        }
    }
}

// ---------------- host ----------------
extern "C" void kernel_launch(void* const* d_in, const int* in_sizes, int n_in,
                              void* d_out, int out_size)
{
    const float* path   = (const float*)d_in[0];
    const float* w_in1  = (const float*)d_in[1];
    const float* b_in1  = (const float*)d_in[2];
    const float* w_out1 = (const float*)d_in[3];
    const float* b_out1 = (const float*)d_in[4];
    const float* w_lin  = (const float*)d_in[5];
    const float* b_lin  = (const float*)d_in[6];
    const float* w_in2  = (const float*)d_in[7];
    const float* b_in2  = (const float*)d_in[8];
    const float* w_out2 = (const float*)d_in[9];
    const float* b_out2 = (const float*)d_in[10];

    float *qkv1, *attn1, *x, *q2, *kv, *st, *wt, *wt2, *wcomb, *bcomb, *wkv, *bkv, *zb;
    cudaGetSymbolAddress((void**)&qkv1,  g_qkv1);
    cudaGetSymbolAddress((void**)&attn1, g_attn1);
    cudaGetSymbolAddress((void**)&x,     g_x);
    cudaGetSymbolAddress((void**)&q2,    g_q2);
    cudaGetSymbolAddress((void**)&kv,    g_kv);
    cudaGetSymbolAddress((void**)&st,    g_st);
    cudaGetSymbolAddress((void**)&wt,    g_wt);
    cudaGetSymbolAddress((void**)&wt2,   g_wt2);
    cudaGetSymbolAddress((void**)&wcomb, g_wcomb);
    cudaGetSymbolAddress((void**)&bcomb, g_bcomb);
    cudaGetSymbolAddress((void**)&wkv,   g_wkv);
    cudaGetSymbolAddress((void**)&bkv,   g_bkv);
    cudaGetSymbolAddress((void**)&zb,    g_zb);

    cudaFuncSetAttribute(attn_kernel,        cudaFuncAttributeMaxDynamicSharedMemorySize, ATTN_SMEM);
    cudaFuncSetAttribute(gemm_tf32<false>,   cudaFuncAttributeMaxDynamicSharedMemorySize, TF_SMEM);
    cudaFuncSetAttribute(gemm_tf32<true>,    cudaFuncAttributeMaxDynamicSharedMemorySize, TF_SMEM);
    cudaFuncSetAttribute(recurrence_kernel,  cudaFuncAttributeMaxDynamicSharedMemorySize, REC_SMEM);
    cudaFuncSetAttribute(gemm_tf32<false>,   cudaFuncAttributePreferredSharedMemoryCarveout, 100);
    cudaFuncSetAttribute(gemm_tf32<true>,    cudaFuncAttributePreferredSharedMemoryCarveout, 100);

    auto g64  = gemm_bias<64,64,16,4,4>;
    auto t32  = gemm_tf32<false>;
    auto t32r = gemm_tf32<true>;

    const float* wkv2 = w_in2 + (size_t)ODIM * ODIM;
    const float* bkv2 = b_in2 + ODIM;

    // launch 0: all prologue prep in one kernel
    prep_kernel<<<2052 + 128 + 256, 256>>>(w_out1, w_out2, w_lin, b_out1, b_lin,
                                           wkv2, b_out2, bkv2, wt, wt2, zb, bcomb, bkv);
    // launches 1-2: weight folds (tf32)
    t32<<<dim3(DM/128, DM/128), 256, TF_SMEM>>>(w_lin, wt, zb, wcomb, DM, DM, DM);
    t32<<<dim3(DM/128, 2*ODIM/128), 256, TF_SMEM>>>(wkv2, wt2, zb, wkv, 2*ODIM, DM, DM);

    // launch 3: stage 1 QKV of every path row
    t32<<<dim3(3*DM/128, SEQ/128), 256, TF_SMEM>>>(path, w_in1, b_in1, qkv1, SEQ, 3*DM, DM);

    // launch 4: stage 2 batched window self-attention (exact fp32)
    attn_kernel<<<dim3(NH, KW/64, NWIN), 256, ATTN_SMEM>>>(
        qkv1,        (long long)STR * 3*DM, 3*DM,
        qkv1 + DM,   (long long)STR * 3*DM, 3*DM,
        qkv1 + 2*DM, (long long)STR * 3*DM, 3*DM,
        attn1,       (long long)KW * DM,    DM,
        0.125f);

    // launch 5: stage 3 fused outproj1 + linear + relu (tf32)  <-- ncu -s 5 target
    t32r<<<dim3(ODIM/128, ROWS/128), 256, TF_SMEM>>>(attn1, wcomb, bcomb, x, ROWS, ODIM, DM);

    // launch 6: stage 4a bulk Q2 projections (tf32)
    t32<<<dim3(ODIM/128, ROWS/128), 256, TF_SMEM>>>(x, w_in2, b_in2, q2, ROWS, ODIM, ODIM);

    // launch 7: persistent flag-synced recurrence
    recurrence_kernel<<<REC_NB, 256, REC_SMEM>>>(x, q2, wkv2, bkv2, wkv, bkv, kv, st);

    // launch 8: final out-projection (exact fp32 -> d_out); last step wrote st[(NWIN-1)&1]
    g64<<<dim3(ODIM/64, KW/64), 256>>>(st + (size_t)((NWIN-1)&1) * KW * ODIM,
                                       w_out2, b_out2, (float*)d_out, KW, ODIM, ODIM);
}